// round 1
// baseline (speedup 1.0000x reference)
#include <cuda_runtime.h>
#include <math.h>
#include <stdint.h>

// Problem constants
#define TOK   4096          // b*l tokens
#define CDIM  1024
#define CHID  4096          // mlp hidden
#define NHEAD 16
#define HDIM  64
#define NB    4
#define SEQ   1024

// ---------------- scratch (device globals; no allocation allowed) ----------
__device__ float g_x   [TOK * CDIM];
__device__ float g_op0 [TOK * CDIM];
__device__ float g_h1  [TOK * 64];
__device__ float g_gate[TOK * CDIM];
__device__ float g_mh  [TOK * CHID];
__device__ float g_op3 [TOK * CDIM];
__device__ float g_xc  [TOK * CDIM];
__device__ float g_qkv [TOK * 3 * CDIM];
__device__ float g_q   [TOK * CDIM];   // [b,h,n,d]
__device__ float g_k   [TOK * CDIM];   // [b,h,n,d]
__device__ float g_v   [TOK * CDIM];   // [b,h,n,d]
__device__ float g_ao  [TOK * CDIM];   // attention out, token-major [tok, h*d]

// ---------------- epilogues -------------------------------------------------
#define EPI_NONE 0
#define EPI_GELU 1
#define EPI_RELU 2
#define EPI_SIGM 3
#define EPI_RES  4

__device__ __forceinline__ float gelu_exact(float v) {
    return 0.5f * v * (1.0f + erff(v * 0.70710678118654752f));
}

// ---------------- generic NT GEMM: Out[m,n] = sum_k A[m,k] * W[n,k] + bias --
template<int BM, int BN, int BK, int TM, int TN, int EPI>
__global__ __launch_bounds__((BM/TM)*(BN/TN))
void gemm_nt(const float* __restrict__ A, const float* __restrict__ W,
             const float* __restrict__ bias, const float* __restrict__ res,
             float* __restrict__ Out, int M, int N, int K)
{
    constexpr int NT = (BM/TM)*(BN/TN);
    __shared__ float As[BK][BM + 4];
    __shared__ float Ws[BK][BN + 4];

    const int tid = threadIdx.x;
    const int m0 = blockIdx.y * BM;
    const int n0 = blockIdx.x * BN;
    const int tx = tid % (BN / TN);
    const int ty = tid / (BN / TN);

    float acc[TM][TN];
#pragma unroll
    for (int i = 0; i < TM; i++)
#pragma unroll
        for (int j = 0; j < TN; j++) acc[i][j] = 0.f;

    for (int k0 = 0; k0 < K; k0 += BK) {
        // load A tile (transposed into smem)
#pragma unroll
        for (int i = tid; i < BM*BK/4; i += NT) {
            int r = i / (BK/4), cg = i % (BK/4);
            float4 v = *(const float4*)&A[(size_t)(m0 + r) * K + k0 + cg*4];
            As[cg*4+0][r] = v.x; As[cg*4+1][r] = v.y;
            As[cg*4+2][r] = v.z; As[cg*4+3][r] = v.w;
        }
#pragma unroll
        for (int i = tid; i < BN*BK/4; i += NT) {
            int r = i / (BK/4), cg = i % (BK/4);
            float4 v = *(const float4*)&W[(size_t)(n0 + r) * K + k0 + cg*4];
            Ws[cg*4+0][r] = v.x; Ws[cg*4+1][r] = v.y;
            Ws[cg*4+2][r] = v.z; Ws[cg*4+3][r] = v.w;
        }
        __syncthreads();
#pragma unroll
        for (int k = 0; k < BK; k++) {
            float a[TM], b[TN];
#pragma unroll
            for (int i = 0; i < TM; i++) a[i] = As[k][ty*TM + i];
#pragma unroll
            for (int j = 0; j < TN; j++) b[j] = Ws[k][tx*TN + j];
#pragma unroll
            for (int i = 0; i < TM; i++)
#pragma unroll
                for (int j = 0; j < TN; j++) acc[i][j] += a[i] * b[j];
        }
        __syncthreads();
    }

#pragma unroll
    for (int i = 0; i < TM; i++) {
        int m = m0 + ty*TM + i;
#pragma unroll
        for (int j = 0; j < TN; j++) {
            int n = n0 + tx*TN + j;
            float v = acc[i][j] + bias[n];
            if (EPI == EPI_GELU) v = gelu_exact(v);
            else if (EPI == EPI_RELU) v = fmaxf(v, 0.f);
            else if (EPI == EPI_SIGM) v = 1.0f / (1.0f + __expf(-v));
            else if (EPI == EPI_RES)  v += res[(size_t)m * N + n];
            Out[(size_t)m * N + n] = v;
        }
    }
}

// ---------------- extract x = x_list[...,-1] --------------------------------
__global__ void extract_x(const float* __restrict__ x_list, float* __restrict__ x)
{
    int i = blockIdx.x * blockDim.x + threadIdx.x;
    if (i < TOK * CDIM) x[i] = x_list[2*i + 1];
}

// ---------------- combine: softmax(w_/T) weighted mix -----------------------
__global__ void combine(const float* __restrict__ x_list,
                        const float* __restrict__ w_,
                        const float* __restrict__ op0,
                        const float* __restrict__ gate,
                        const float* __restrict__ op3,
                        float* __restrict__ xc)
{
    // compute 6-way softmax (w_/0.01) — every thread redundantly (cheap)
    float w[6], mx = -1e30f;
#pragma unroll
    for (int i = 0; i < 6; i++) { w[i] = w_[i] * 100.0f; mx = fmaxf(mx, w[i]); }
    float s = 0.f;
#pragma unroll
    for (int i = 0; i < 6; i++) { w[i] = __expf(w[i] - mx); s += w[i]; }
    float inv = 1.0f / s;
#pragma unroll
    for (int i = 0; i < 6; i++) w[i] *= inv;

    int i = blockIdx.x * blockDim.x + threadIdx.x;
    if (i >= TOK * CDIM) return;
    float xl0 = x_list[2*i];
    float xv  = x_list[2*i + 1];
    // order: [xl0, xl1(=x), op0, op1(=gate*x), op2(=x), op3]
    float v = w[0]*xl0 + (w[1] + w[4])*xv + w[2]*op0[i] + w[3]*(gate[i]*xv) + w[5]*op3[i];
    xc[i] = v;
}

// ---------------- qkv split + per-head LN + head-major transpose ------------
__global__ void ln_split(const float* __restrict__ qkv,
                         const float* __restrict__ nqg, const float* __restrict__ nqb,
                         const float* __restrict__ nkg, const float* __restrict__ nkb,
                         float* __restrict__ Qo, float* __restrict__ Ko, float* __restrict__ Vo)
{
    int gw = (blockIdx.x * blockDim.x + threadIdx.x) >> 5;
    int lane = threadIdx.x & 31;
    if (gw >= TOK * NHEAD) return;
    int t = gw / NHEAD, h = gw % NHEAD;
    int b = t / SEQ, n = t % SEQ;
    size_t src = (size_t)t * (3*CDIM) + h * HDIM;
    size_t dst = ((size_t)(b*NHEAD + h) * SEQ + n) * HDIM;

#pragma unroll
    for (int which = 0; which < 2; which++) {
        size_t so = src + (which ? CDIM : 0);
        float2 xv = *(const float2*)&qkv[so + lane*2];
        float sum = xv.x + xv.y;
        float ssq = xv.x*xv.x + xv.y*xv.y;
#pragma unroll
        for (int o = 16; o > 0; o >>= 1) {
            sum += __shfl_xor_sync(0xffffffff, sum, o);
            ssq += __shfl_xor_sync(0xffffffff, ssq, o);
        }
        float mean = sum * (1.0f/64.0f);
        float var  = ssq * (1.0f/64.0f) - mean*mean;
        float inv  = rsqrtf(var + 1e-5f);
        const float* g = which ? nkg : nqg;
        const float* bb = which ? nkb : nqb;
        float* O = which ? Ko : Qo;
        O[dst + lane*2 + 0] = (xv.x - mean)*inv*g[lane*2+0] + bb[lane*2+0];
        O[dst + lane*2 + 1] = (xv.y - mean)*inv*g[lane*2+1] + bb[lane*2+1];
    }
    *(float2*)&Vo[dst + lane*2] = *(const float2*)&qkv[src + 2*CDIM + lane*2];
}

// ---------------- flash attention (64x64 tiles, online softmax) -------------
#define APAD 68
__global__ __launch_bounds__(256)
void attn_kernel(const float* __restrict__ Q, const float* __restrict__ K,
                 const float* __restrict__ V, float* __restrict__ AO)
{
    extern __shared__ float sm[];
    float* Qs = sm;                 // [64][APAD] transposed (d-major)
    float* Ks = Qs + 64*APAD;       // [64][APAD] transposed (d-major)
    float* Vs = Ks + 64*APAD;       // [64][APAD] natural   (k-major)
    float* Ss = Vs + 64*APAD;       // [64][APAD] scores [q][k]
    float* Pt = Ss + 64*APAD;       // [64][APAD] probs transposed [k][q]
    float* m_s  = Pt + 64*APAD;     // [64]
    float* l_s  = m_s + 64;         // [64]
    float* sc_s = l_s + 64;         // [64]

    const int tid = threadIdx.x;
    const int q0 = blockIdx.x * 64;
    const int bh = blockIdx.y;
    const float* Qb = Q + (size_t)bh * SEQ * HDIM;
    const float* Kb = K + (size_t)bh * SEQ * HDIM;
    const float* Vb = V + (size_t)bh * SEQ * HDIM;

    // load Q tile transposed
    for (int i = tid; i < 64*16; i += 256) {
        int r = i / 16, cg = i % 16;
        float4 v = *(const float4*)&Qb[(size_t)(q0 + r) * HDIM + cg*4];
        Qs[(cg*4+0)*APAD + r] = v.x; Qs[(cg*4+1)*APAD + r] = v.y;
        Qs[(cg*4+2)*APAD + r] = v.z; Qs[(cg*4+3)*APAD + r] = v.w;
    }
    if (tid < 64) { m_s[tid] = -1e30f; l_s[tid] = 0.f; }

    const int ty = tid / 16, tx = tid % 16;   // gemm mapping: q=ty*4.., n=tx*4..
    const int rg = tid / 4,  sub = tid % 4;   // softmax mapping: 4 threads per row

    float o[4][4];
#pragma unroll
    for (int i = 0; i < 4; i++)
#pragma unroll
        for (int j = 0; j < 4; j++) o[i][j] = 0.f;

    for (int kt = 0; kt < 16; kt++) {
        __syncthreads();
        int k0 = kt * 64;
        for (int i = tid; i < 64*16; i += 256) {
            int r = i / 16, cg = i % 16;
            float4 v = *(const float4*)&Kb[(size_t)(k0 + r) * HDIM + cg*4];
            Ks[(cg*4+0)*APAD + r] = v.x; Ks[(cg*4+1)*APAD + r] = v.y;
            Ks[(cg*4+2)*APAD + r] = v.z; Ks[(cg*4+3)*APAD + r] = v.w;
            float4 w = *(const float4*)&Vb[(size_t)(k0 + r) * HDIM + cg*4];
            *(float4*)&Vs[r*APAD + cg*4] = w;
        }
        __syncthreads();

        // S = Q K^T * 0.125
        float s[4][4];
#pragma unroll
        for (int i = 0; i < 4; i++)
#pragma unroll
            for (int j = 0; j < 4; j++) s[i][j] = 0.f;
#pragma unroll 16
        for (int d = 0; d < 64; d++) {
            float a[4], b[4];
#pragma unroll
            for (int i = 0; i < 4; i++) a[i] = Qs[d*APAD + ty*4 + i];
#pragma unroll
            for (int j = 0; j < 4; j++) b[j] = Ks[d*APAD + tx*4 + j];
#pragma unroll
            for (int i = 0; i < 4; i++)
#pragma unroll
                for (int j = 0; j < 4; j++) s[i][j] += a[i] * b[j];
        }
#pragma unroll
        for (int i = 0; i < 4; i++)
#pragma unroll
            for (int j = 0; j < 4; j++)
                Ss[(ty*4+i)*APAD + tx*4 + j] = s[i][j] * 0.125f;
        __syncthreads();

        // online softmax per row (4 threads/row, 16 cols each)
        float p[16], mx = -1e30f;
#pragma unroll
        for (int i = 0; i < 16; i++) { p[i] = Ss[rg*APAD + sub*16 + i]; mx = fmaxf(mx, p[i]); }
        mx = fmaxf(mx, __shfl_xor_sync(0xffffffff, mx, 1));
        mx = fmaxf(mx, __shfl_xor_sync(0xffffffff, mx, 2));
        float newm = fmaxf(m_s[rg], mx);
        float sum = 0.f;
#pragma unroll
        for (int i = 0; i < 16; i++) {
            p[i] = __expf(p[i] - newm);
            sum += p[i];
            Pt[(sub*16 + i)*APAD + rg] = p[i];
        }
        sum += __shfl_xor_sync(0xffffffff, sum, 1);
        sum += __shfl_xor_sync(0xffffffff, sum, 2);
        if (sub == 0) {
            float sc = __expf(m_s[rg] - newm);
            sc_s[rg] = sc;
            l_s[rg] = l_s[rg] * sc + sum;
            m_s[rg] = newm;
        }
        __syncthreads();

        // O = O*scale + P V   (gemm mapping)
        float scq[4];
#pragma unroll
        for (int i = 0; i < 4; i++) scq[i] = sc_s[ty*4 + i];
#pragma unroll
        for (int i = 0; i < 4; i++)
#pragma unroll
            for (int j = 0; j < 4; j++) o[i][j] *= scq[i];
#pragma unroll 16
        for (int kk = 0; kk < 64; kk++) {
            float a[4], b[4];
#pragma unroll
            for (int i = 0; i < 4; i++) a[i] = Pt[kk*APAD + ty*4 + i];
#pragma unroll
            for (int j = 0; j < 4; j++) b[j] = Vs[kk*APAD + tx*4 + j];
#pragma unroll
            for (int i = 0; i < 4; i++)
#pragma unroll
                for (int j = 0; j < 4; j++) o[i][j] += a[i] * b[j];
        }
    }
    __syncthreads();

    int b = bh / NHEAD, h = bh % NHEAD;
#pragma unroll
    for (int i = 0; i < 4; i++) {
        int q = ty*4 + i;
        float inv = 1.0f / l_s[q];
#pragma unroll
        for (int j = 0; j < 4; j++) {
            AO[(size_t)(b*SEQ + q0 + q) * CDIM + h*HDIM + tx*4 + j] = o[i][j] * inv;
        }
    }
}

// ---------------- attention map for query 0 (mean over heads) ---------------
__global__ void attn_map_kernel(const float* __restrict__ Q, const float* __restrict__ K,
                                float* __restrict__ omap)
{
    __shared__ float sc[SEQ];
    __shared__ float acc[SEQ];
    __shared__ float red[256];
    __shared__ float q0[HDIM];
    int b = blockIdx.x, tid = threadIdx.x;
    for (int i = tid; i < SEQ; i += 256) acc[i] = 0.f;
    for (int h = 0; h < NHEAD; h++) {
        const float* Qb = Q + ((size_t)(b*NHEAD + h) * SEQ) * HDIM;
        const float* Kb = K + ((size_t)(b*NHEAD + h) * SEQ) * HDIM;
        __syncthreads();
        if (tid < HDIM) q0[tid] = Qb[tid];
        __syncthreads();
        for (int m = tid; m < SEQ; m += 256) {
            float s = 0.f;
#pragma unroll 16
            for (int j = 0; j < HDIM; j++) s += q0[j] * Kb[(size_t)m*HDIM + j];
            sc[m] = s * 0.125f;
        }
        __syncthreads();
        float mx = -1e30f;
        for (int m = tid; m < SEQ; m += 256) mx = fmaxf(mx, sc[m]);
        red[tid] = mx; __syncthreads();
        for (int s = 128; s > 0; s >>= 1) { if (tid < s) red[tid] = fmaxf(red[tid], red[tid+s]); __syncthreads(); }
        mx = red[0]; __syncthreads();
        float sum = 0.f;
        for (int m = tid; m < SEQ; m += 256) { float p = __expf(sc[m] - mx); sc[m] = p; sum += p; }
        red[tid] = sum; __syncthreads();
        for (int s = 128; s > 0; s >>= 1) { if (tid < s) red[tid] += red[tid+s]; __syncthreads(); }
        float inv = 1.0f / red[0]; __syncthreads();
        for (int m = tid; m < SEQ; m += 256) acc[m] += sc[m] * inv;
    }
    __syncthreads();
    for (int m = tid; m < SEQ; m += 256)
        if (m >= 1) omap[(size_t)b*(SEQ-1) + m - 1] = acc[m] * (1.0f/NHEAD);
}

// ---------------- launch ----------------------------------------------------
extern "C" void kernel_launch(void* const* d_in, const int* in_sizes, int n_in,
                              void* d_out, int out_size)
{
    const float* x_list = (const float*)d_in[0];
    const float* w_     = (const float*)d_in[1];
    const float* qkv_w  = (const float*)d_in[2];
    const float* qkv_b  = (const float*)d_in[3];
    const float* proj_w = (const float*)d_in[4];
    const float* proj_b = (const float*)d_in[5];
    const float* nq_g   = (const float*)d_in[6];
    const float* nq_b   = (const float*)d_in[7];
    const float* nk_g   = (const float*)d_in[8];
    const float* nk_b   = (const float*)d_in[9];
    const float* conv_w = (const float*)d_in[10];
    const float* conv_b = (const float*)d_in[11];
    const float* ca1_w  = (const float*)d_in[12];
    const float* ca1_b  = (const float*)d_in[13];
    const float* ca2_w  = (const float*)d_in[14];
    const float* ca2_b  = (const float*)d_in[15];
    const float* mlp1_w = (const float*)d_in[16];
    const float* mlp1_b = (const float*)d_in[17];
    const float* mlp2_w = (const float*)d_in[18];
    const float* mlp2_b = (const float*)d_in[19];
    float* out = (float*)d_out;

    float *px, *pop0, *ph1, *pgate, *pmh, *pop3, *pxc, *pqkv, *pq, *pk, *pv, *pao;
    cudaGetSymbolAddress((void**)&px,   g_x);
    cudaGetSymbolAddress((void**)&pop0, g_op0);
    cudaGetSymbolAddress((void**)&ph1,  g_h1);
    cudaGetSymbolAddress((void**)&pgate,g_gate);
    cudaGetSymbolAddress((void**)&pmh,  g_mh);
    cudaGetSymbolAddress((void**)&pop3, g_op3);
    cudaGetSymbolAddress((void**)&pxc,  g_xc);
    cudaGetSymbolAddress((void**)&pqkv, g_qkv);
    cudaGetSymbolAddress((void**)&pq,   g_q);
    cudaGetSymbolAddress((void**)&pk,   g_k);
    cudaGetSymbolAddress((void**)&pv,   g_v);
    cudaGetSymbolAddress((void**)&pao,  g_ao);

    const int NE = TOK * CDIM;

    extract_x<<<(NE + 255)/256, 256>>>(x_list, px);

    // op0 = gelu(x @ conv_w^T + conv_b)
    gemm_nt<128,128,16,8,8,EPI_GELU><<<dim3(CDIM/128, TOK/128), 256>>>(
        px, conv_w, conv_b, nullptr, pop0, TOK, CDIM, CDIM);
    // h1 = relu(x @ ca1_w^T + ca1_b)   [4096,64]
    gemm_nt<128,64,16,8,4,EPI_RELU><<<dim3(1, TOK/128), 256>>>(
        px, ca1_w, ca1_b, nullptr, ph1, TOK, 64, CDIM);
    // gate = sigmoid(h1 @ ca2_w^T + ca2_b)
    gemm_nt<128,128,16,8,8,EPI_SIGM><<<dim3(CDIM/128, TOK/128), 256>>>(
        ph1, ca2_w, ca2_b, nullptr, pgate, TOK, CDIM, 64);
    // mh = gelu(x @ mlp1_w^T + mlp1_b)  [4096,4096]
    gemm_nt<128,128,16,8,8,EPI_GELU><<<dim3(CHID/128, TOK/128), 256>>>(
        px, mlp1_w, mlp1_b, nullptr, pmh, TOK, CHID, CDIM);
    // op3 = mh @ mlp2_w^T + mlp2_b
    gemm_nt<128,128,16,8,8,EPI_NONE><<<dim3(CDIM/128, TOK/128), 256>>>(
        pmh, mlp2_w, mlp2_b, nullptr, pop3, TOK, CDIM, CHID);

    combine<<<(NE + 255)/256, 256>>>(x_list, w_, pop0, pgate, pop3, pxc);

    // qkv = xc @ qkv_w^T + qkv_b   [4096,3072]
    gemm_nt<128,128,16,8,8,EPI_NONE><<<dim3(3*CDIM/128, TOK/128), 256>>>(
        pxc, qkv_w, qkv_b, nullptr, pqkv, TOK, 3*CDIM, CDIM);

    ln_split<<<(TOK*NHEAD*32 + 255)/256, 256>>>(pqkv, nq_g, nq_b, nk_g, nk_b, pq, pk, pv);

    int smem = (5 * 64 * APAD + 3 * 64) * (int)sizeof(float);
    cudaFuncSetAttribute(attn_kernel, cudaFuncAttributeMaxDynamicSharedMemorySize, smem);
    attn_kernel<<<dim3(SEQ/64, NB*NHEAD), 256, smem>>>(pq, pk, pv, pao);

    attn_map_kernel<<<NB, 256>>>(pq, pk, out + (size_t)TOK * CDIM);

    // out = ao @ proj_w^T + proj_b + xc
    gemm_nt<128,128,16,8,8,EPI_RES><<<dim3(CDIM/128, TOK/128), 256>>>(
        pao, proj_w, proj_b, pxc, out, TOK, CDIM, CDIM);
}

// round 2
// speedup vs baseline: 1.6290x; 1.6290x over previous
#include <cuda_runtime.h>
#include <math.h>
#include <stdint.h>

// Problem constants
#define TOK   4096          // b*l tokens
#define CDIM  1024
#define CHID  4096          // mlp hidden
#define NHEAD 16
#define HDIM  64
#define NB    4
#define SEQ   1024

// ---------------- scratch (device globals; no allocation allowed) ----------
__device__ float g_x   [TOK * CDIM];
__device__ float g_op0 [TOK * CDIM];
__device__ float g_h1  [TOK * 64];
__device__ float g_gate[TOK * CDIM];
__device__ float g_mh  [TOK * CHID];
__device__ float g_op3 [TOK * CDIM];
__device__ float g_xc  [TOK * CDIM];
__device__ float g_qkv [TOK * 3 * CDIM];
__device__ float g_q   [TOK * CDIM];   // [b,h,n,d]
__device__ float g_k   [TOK * CDIM];   // [b,h,n,d]
__device__ float g_v   [TOK * CDIM];   // [b,h,n,d]
__device__ float g_ao  [TOK * CDIM];   // attention out, token-major [tok, h*d]

// ---------------- epilogues -------------------------------------------------
#define EPI_NONE 0
#define EPI_GELU 1
#define EPI_RELU 2
#define EPI_SIGM 3
#define EPI_RES  4

__device__ __forceinline__ float gelu_exact(float v) {
    return 0.5f * v * (1.0f + erff(v * 0.70710678118654752f));
}

// ---------------- generic NT GEMM: Out[m,n] = sum_k A[m,k] * W[n,k] + bias --
template<int BM, int BN, int BK, int TM, int TN, int EPI>
__global__ __launch_bounds__((BM/TM)*(BN/TN))
void gemm_nt(const float* __restrict__ A, const float* __restrict__ W,
             const float* __restrict__ bias, const float* __restrict__ res,
             float* __restrict__ Out, int M, int N, int K)
{
    constexpr int NT = (BM/TM)*(BN/TN);
    __shared__ float As[BK][BM + 4];
    __shared__ float Ws[BK][BN + 4];

    const int tid = threadIdx.x;
    const int m0 = blockIdx.y * BM;
    const int n0 = blockIdx.x * BN;
    const int tx = tid % (BN / TN);
    const int ty = tid / (BN / TN);

    float acc[TM][TN];
#pragma unroll
    for (int i = 0; i < TM; i++)
#pragma unroll
        for (int j = 0; j < TN; j++) acc[i][j] = 0.f;

    for (int k0 = 0; k0 < K; k0 += BK) {
        // load A tile (transposed into smem)
#pragma unroll
        for (int i = tid; i < BM*BK/4; i += NT) {
            int r = i / (BK/4), cg = i % (BK/4);
            float4 v = *(const float4*)&A[(size_t)(m0 + r) * K + k0 + cg*4];
            As[cg*4+0][r] = v.x; As[cg*4+1][r] = v.y;
            As[cg*4+2][r] = v.z; As[cg*4+3][r] = v.w;
        }
#pragma unroll
        for (int i = tid; i < BN*BK/4; i += NT) {
            int r = i / (BK/4), cg = i % (BK/4);
            float4 v = *(const float4*)&W[(size_t)(n0 + r) * K + k0 + cg*4];
            Ws[cg*4+0][r] = v.x; Ws[cg*4+1][r] = v.y;
            Ws[cg*4+2][r] = v.z; Ws[cg*4+3][r] = v.w;
        }
        __syncthreads();
#pragma unroll
        for (int k = 0; k < BK; k++) {
            float a[TM], b[TN];
#pragma unroll
            for (int i = 0; i < TM; i++) a[i] = As[k][ty*TM + i];
#pragma unroll
            for (int j = 0; j < TN; j++) b[j] = Ws[k][tx*TN + j];
#pragma unroll
            for (int i = 0; i < TM; i++)
#pragma unroll
                for (int j = 0; j < TN; j++) acc[i][j] += a[i] * b[j];
        }
        __syncthreads();
    }

#pragma unroll
    for (int i = 0; i < TM; i++) {
        int m = m0 + ty*TM + i;
#pragma unroll
        for (int j = 0; j < TN; j++) {
            int n = n0 + tx*TN + j;
            float v = acc[i][j] + bias[n];
            if (EPI == EPI_GELU) v = gelu_exact(v);
            else if (EPI == EPI_RELU) v = fmaxf(v, 0.f);
            else if (EPI == EPI_SIGM) v = 1.0f / (1.0f + __expf(-v));
            else if (EPI == EPI_RES)  v += res[(size_t)m * N + n];
            Out[(size_t)m * N + n] = v;
        }
    }
}

// ---------------- extract x = x_list[...,-1] --------------------------------
__global__ void extract_x(const float* __restrict__ x_list, float* __restrict__ x)
{
    int i = blockIdx.x * blockDim.x + threadIdx.x;
    if (i < TOK * CDIM) x[i] = x_list[2*i + 1];
}

// ---------------- combine: softmax(w_/T) weighted mix -----------------------
__global__ void combine(const float* __restrict__ x_list,
                        const float* __restrict__ w_,
                        const float* __restrict__ op0,
                        const float* __restrict__ gate,
                        const float* __restrict__ op3,
                        float* __restrict__ xc)
{
    // compute 6-way softmax (w_/0.01) — every thread redundantly (cheap)
    float w[6], mx = -1e30f;
#pragma unroll
    for (int i = 0; i < 6; i++) { w[i] = w_[i] * 100.0f; mx = fmaxf(mx, w[i]); }
    float s = 0.f;
#pragma unroll
    for (int i = 0; i < 6; i++) { w[i] = __expf(w[i] - mx); s += w[i]; }
    float inv = 1.0f / s;
#pragma unroll
    for (int i = 0; i < 6; i++) w[i] *= inv;

    int i = blockIdx.x * blockDim.x + threadIdx.x;
    if (i >= TOK * CDIM) return;
    float xl0 = x_list[2*i];
    float xv  = x_list[2*i + 1];
    // order: [xl0, xl1(=x), op0, op1(=gate*x), op2(=x), op3]
    float v = w[0]*xl0 + (w[1] + w[4])*xv + w[2]*op0[i] + w[3]*(gate[i]*xv) + w[5]*op3[i];
    xc[i] = v;
}

// ---------------- qkv split + per-head LN + head-major transpose ------------
__global__ void ln_split(const float* __restrict__ qkv,
                         const float* __restrict__ nqg, const float* __restrict__ nqb,
                         const float* __restrict__ nkg, const float* __restrict__ nkb,
                         float* __restrict__ Qo, float* __restrict__ Ko, float* __restrict__ Vo)
{
    int gw = (blockIdx.x * blockDim.x + threadIdx.x) >> 5;
    int lane = threadIdx.x & 31;
    if (gw >= TOK * NHEAD) return;
    int t = gw / NHEAD, h = gw % NHEAD;
    int b = t / SEQ, n = t % SEQ;
    size_t src = (size_t)t * (3*CDIM) + h * HDIM;
    size_t dst = ((size_t)(b*NHEAD + h) * SEQ + n) * HDIM;

#pragma unroll
    for (int which = 0; which < 2; which++) {
        size_t so = src + (which ? CDIM : 0);
        float2 xv = *(const float2*)&qkv[so + lane*2];
        float sum = xv.x + xv.y;
        float ssq = xv.x*xv.x + xv.y*xv.y;
#pragma unroll
        for (int o = 16; o > 0; o >>= 1) {
            sum += __shfl_xor_sync(0xffffffff, sum, o);
            ssq += __shfl_xor_sync(0xffffffff, ssq, o);
        }
        float mean = sum * (1.0f/64.0f);
        float var  = ssq * (1.0f/64.0f) - mean*mean;
        float inv  = rsqrtf(var + 1e-5f);
        const float* g = which ? nkg : nqg;
        const float* bb = which ? nkb : nqb;
        float* O = which ? Ko : Qo;
        O[dst + lane*2 + 0] = (xv.x - mean)*inv*g[lane*2+0] + bb[lane*2+0];
        O[dst + lane*2 + 1] = (xv.y - mean)*inv*g[lane*2+1] + bb[lane*2+1];
    }
    *(float2*)&Vo[dst + lane*2] = *(const float2*)&qkv[src + 2*CDIM + lane*2];
}

// ---------------- flash attention (64x64 tiles, online softmax) -------------
#define APAD 68
__global__ __launch_bounds__(256)
void attn_kernel(const float* __restrict__ Q, const float* __restrict__ K,
                 const float* __restrict__ V, float* __restrict__ AO)
{
    extern __shared__ float sm[];
    float* Qs = sm;                 // [64][APAD] transposed (d-major)
    float* Ks = Qs + 64*APAD;       // [64][APAD] transposed (d-major)
    float* Vs = Ks + 64*APAD;       // [64][APAD] natural   (k-major)
    float* Ss = Vs + 64*APAD;       // [64][APAD] scores [q][k]
    float* Pt = Ss + 64*APAD;       // [64][APAD] probs transposed [k][q]
    float* m_s  = Pt + 64*APAD;     // [64]
    float* l_s  = m_s + 64;         // [64]
    float* sc_s = l_s + 64;         // [64]

    const int tid = threadIdx.x;
    const int q0 = blockIdx.x * 64;
    const int bh = blockIdx.y;
    const float* Qb = Q + (size_t)bh * SEQ * HDIM;
    const float* Kb = K + (size_t)bh * SEQ * HDIM;
    const float* Vb = V + (size_t)bh * SEQ * HDIM;

    // load Q tile transposed
    for (int i = tid; i < 64*16; i += 256) {
        int r = i / 16, cg = i % 16;
        float4 v = *(const float4*)&Qb[(size_t)(q0 + r) * HDIM + cg*4];
        Qs[(cg*4+0)*APAD + r] = v.x; Qs[(cg*4+1)*APAD + r] = v.y;
        Qs[(cg*4+2)*APAD + r] = v.z; Qs[(cg*4+3)*APAD + r] = v.w;
    }
    if (tid < 64) { m_s[tid] = -1e30f; l_s[tid] = 0.f; }

    const int ty = tid / 16, tx = tid % 16;   // gemm mapping: q=ty*4.., n=tx*4..
    const int rg = tid / 4,  sub = tid % 4;   // softmax mapping: 4 threads per row

    float o[4][4];
#pragma unroll
    for (int i = 0; i < 4; i++)
#pragma unroll
        for (int j = 0; j < 4; j++) o[i][j] = 0.f;

    for (int kt = 0; kt < 16; kt++) {
        __syncthreads();
        int k0 = kt * 64;
        for (int i = tid; i < 64*16; i += 256) {
            int r = i / 16, cg = i % 16;
            float4 v = *(const float4*)&Kb[(size_t)(k0 + r) * HDIM + cg*4];
            Ks[(cg*4+0)*APAD + r] = v.x; Ks[(cg*4+1)*APAD + r] = v.y;
            Ks[(cg*4+2)*APAD + r] = v.z; Ks[(cg*4+3)*APAD + r] = v.w;
            float4 w = *(const float4*)&Vb[(size_t)(k0 + r) * HDIM + cg*4];
            *(float4*)&Vs[r*APAD + cg*4] = w;
        }
        __syncthreads();

        // S = Q K^T * 0.125
        float s[4][4];
#pragma unroll
        for (int i = 0; i < 4; i++)
#pragma unroll
            for (int j = 0; j < 4; j++) s[i][j] = 0.f;
#pragma unroll 16
        for (int d = 0; d < 64; d++) {
            float a[4], b[4];
#pragma unroll
            for (int i = 0; i < 4; i++) a[i] = Qs[d*APAD + ty*4 + i];
#pragma unroll
            for (int j = 0; j < 4; j++) b[j] = Ks[d*APAD + tx*4 + j];
#pragma unroll
            for (int i = 0; i < 4; i++)
#pragma unroll
                for (int j = 0; j < 4; j++) s[i][j] += a[i] * b[j];
        }
#pragma unroll
        for (int i = 0; i < 4; i++)
#pragma unroll
            for (int j = 0; j < 4; j++)
                Ss[(ty*4+i)*APAD + tx*4 + j] = s[i][j] * 0.125f;
        __syncthreads();

        // online softmax per row (4 threads/row, 16 cols each)
        float p[16], mx = -1e30f;
#pragma unroll
        for (int i = 0; i < 16; i++) { p[i] = Ss[rg*APAD + sub*16 + i]; mx = fmaxf(mx, p[i]); }
        mx = fmaxf(mx, __shfl_xor_sync(0xffffffff, mx, 1));
        mx = fmaxf(mx, __shfl_xor_sync(0xffffffff, mx, 2));
        float newm = fmaxf(m_s[rg], mx);
        float sum = 0.f;
#pragma unroll
        for (int i = 0; i < 16; i++) {
            p[i] = __expf(p[i] - newm);
            sum += p[i];
            Pt[(sub*16 + i)*APAD + rg] = p[i];
        }
        sum += __shfl_xor_sync(0xffffffff, sum, 1);
        sum += __shfl_xor_sync(0xffffffff, sum, 2);
        if (sub == 0) {
            float sc = __expf(m_s[rg] - newm);
            sc_s[rg] = sc;
            l_s[rg] = l_s[rg] * sc + sum;
            m_s[rg] = newm;
        }
        __syncthreads();

        // O = O*scale + P V   (gemm mapping)
        float scq[4];
#pragma unroll
        for (int i = 0; i < 4; i++) scq[i] = sc_s[ty*4 + i];
#pragma unroll
        for (int i = 0; i < 4; i++)
#pragma unroll
            for (int j = 0; j < 4; j++) o[i][j] *= scq[i];
#pragma unroll 16
        for (int kk = 0; kk < 64; kk++) {
            float a[4], b[4];
#pragma unroll
            for (int i = 0; i < 4; i++) a[i] = Pt[kk*APAD + ty*4 + i];
#pragma unroll
            for (int j = 0; j < 4; j++) b[j] = Vs[kk*APAD + tx*4 + j];
#pragma unroll
            for (int i = 0; i < 4; i++)
#pragma unroll
                for (int j = 0; j < 4; j++) o[i][j] += a[i] * b[j];
        }
    }
    __syncthreads();

    int b = bh / NHEAD, h = bh % NHEAD;
#pragma unroll
    for (int i = 0; i < 4; i++) {
        int q = ty*4 + i;
        float inv = 1.0f / l_s[q];
#pragma unroll
        for (int j = 0; j < 4; j++) {
            AO[(size_t)(b*SEQ + q0 + q) * CDIM + h*HDIM + tx*4 + j] = o[i][j] * inv;
        }
    }
}

// ---------------- attention map for query 0 (mean over heads) ---------------
__global__ void attn_map_kernel(const float* __restrict__ Q, const float* __restrict__ K,
                                float* __restrict__ omap)
{
    __shared__ float sc[SEQ];
    __shared__ float acc[SEQ];
    __shared__ float red[256];
    __shared__ float q0[HDIM];
    int b = blockIdx.x, tid = threadIdx.x;
    for (int i = tid; i < SEQ; i += 256) acc[i] = 0.f;
    for (int h = 0; h < NHEAD; h++) {
        const float* Qb = Q + ((size_t)(b*NHEAD + h) * SEQ) * HDIM;
        const float* Kb = K + ((size_t)(b*NHEAD + h) * SEQ) * HDIM;
        __syncthreads();
        if (tid < HDIM) q0[tid] = Qb[tid];
        __syncthreads();
        for (int m = tid; m < SEQ; m += 256) {
            float s = 0.f;
#pragma unroll 16
            for (int j = 0; j < HDIM; j++) s += q0[j] * Kb[(size_t)m*HDIM + j];
            sc[m] = s * 0.125f;
        }
        __syncthreads();
        float mx = -1e30f;
        for (int m = tid; m < SEQ; m += 256) mx = fmaxf(mx, sc[m]);
        red[tid] = mx; __syncthreads();
        for (int s = 128; s > 0; s >>= 1) { if (tid < s) red[tid] = fmaxf(red[tid], red[tid+s]); __syncthreads(); }
        mx = red[0]; __syncthreads();
        float sum = 0.f;
        for (int m = tid; m < SEQ; m += 256) { float p = __expf(sc[m] - mx); sc[m] = p; sum += p; }
        red[tid] = sum; __syncthreads();
        for (int s = 128; s > 0; s >>= 1) { if (tid < s) red[tid] += red[tid+s]; __syncthreads(); }
        float inv = 1.0f / red[0]; __syncthreads();
        for (int m = tid; m < SEQ; m += 256) acc[m] += sc[m] * inv;
    }
    __syncthreads();
    for (int m = tid; m < SEQ; m += 256)
        if (m >= 1) omap[(size_t)b*(SEQ-1) + m - 1] = acc[m] * (1.0f/NHEAD);
}

// ---------------- launch ----------------------------------------------------
extern "C" void kernel_launch(void* const* d_in, const int* in_sizes, int n_in,
                              void* d_out, int out_size)
{
    const float* x_list = (const float*)d_in[0];
    const float* w_     = (const float*)d_in[1];
    const float* qkv_w  = (const float*)d_in[2];
    const float* qkv_b  = (const float*)d_in[3];
    const float* proj_w = (const float*)d_in[4];
    const float* proj_b = (const float*)d_in[5];
    const float* nq_g   = (const float*)d_in[6];
    const float* nq_b   = (const float*)d_in[7];
    const float* nk_g   = (const float*)d_in[8];
    const float* nk_b   = (const float*)d_in[9];
    const float* conv_w = (const float*)d_in[10];
    const float* conv_b = (const float*)d_in[11];
    const float* ca1_w  = (const float*)d_in[12];
    const float* ca1_b  = (const float*)d_in[13];
    const float* ca2_w  = (const float*)d_in[14];
    const float* ca2_b  = (const float*)d_in[15];
    const float* mlp1_w = (const float*)d_in[16];
    const float* mlp1_b = (const float*)d_in[17];
    const float* mlp2_w = (const float*)d_in[18];
    const float* mlp2_b = (const float*)d_in[19];
    float* out = (float*)d_out;

    float *px, *pop0, *ph1, *pgate, *pmh, *pop3, *pxc, *pqkv, *pq, *pk, *pv, *pao;
    cudaGetSymbolAddress((void**)&px,   g_x);
    cudaGetSymbolAddress((void**)&pop0, g_op0);
    cudaGetSymbolAddress((void**)&ph1,  g_h1);
    cudaGetSymbolAddress((void**)&pgate,g_gate);
    cudaGetSymbolAddress((void**)&pmh,  g_mh);
    cudaGetSymbolAddress((void**)&pop3, g_op3);
    cudaGetSymbolAddress((void**)&pxc,  g_xc);
    cudaGetSymbolAddress((void**)&pqkv, g_qkv);
    cudaGetSymbolAddress((void**)&pq,   g_q);
    cudaGetSymbolAddress((void**)&pk,   g_k);
    cudaGetSymbolAddress((void**)&pv,   g_v);
    cudaGetSymbolAddress((void**)&pao,  g_ao);

    const int NE = TOK * CDIM;

    extract_x<<<(NE + 255)/256, 256>>>(x_list, px);

    // op0 = gelu(x @ conv_w^T + conv_b)
    gemm_nt<128,128,16,8,8,EPI_GELU><<<dim3(CDIM/128, TOK/128), 256>>>(
        px, conv_w, conv_b, nullptr, pop0, TOK, CDIM, CDIM);
    // h1 = relu(x @ ca1_w^T + ca1_b)   [4096,64]
    gemm_nt<128,64,16,8,4,EPI_RELU><<<dim3(1, TOK/128), 256>>>(
        px, ca1_w, ca1_b, nullptr, ph1, TOK, 64, CDIM);
    // gate = sigmoid(h1 @ ca2_w^T + ca2_b)
    gemm_nt<128,128,16,8,8,EPI_SIGM><<<dim3(CDIM/128, TOK/128), 256>>>(
        ph1, ca2_w, ca2_b, nullptr, pgate, TOK, CDIM, 64);
    // mh = gelu(x @ mlp1_w^T + mlp1_b)  [4096,4096]
    gemm_nt<128,128,16,8,8,EPI_GELU><<<dim3(CHID/128, TOK/128), 256>>>(
        px, mlp1_w, mlp1_b, nullptr, pmh, TOK, CHID, CDIM);
    // op3 = mh @ mlp2_w^T + mlp2_b
    gemm_nt<128,128,16,8,8,EPI_NONE><<<dim3(CDIM/128, TOK/128), 256>>>(
        pmh, mlp2_w, mlp2_b, nullptr, pop3, TOK, CDIM, CHID);

    combine<<<(NE + 255)/256, 256>>>(x_list, w_, pop0, pgate, pop3, pxc);

    // qkv = xc @ qkv_w^T + qkv_b   [4096,3072]
    gemm_nt<128,128,16,8,8,EPI_NONE><<<dim3(3*CDIM/128, TOK/128), 256>>>(
        pxc, qkv_w, qkv_b, nullptr, pqkv, TOK, 3*CDIM, CDIM);

    ln_split<<<(TOK*NHEAD*32 + 255)/256, 256>>>(pqkv, nq_g, nq_b, nk_g, nk_b, pq, pk, pv);

    int smem = (5 * 64 * APAD + 3 * 64) * (int)sizeof(float);
    cudaFuncSetAttribute(attn_kernel, cudaFuncAttributeMaxDynamicSharedMemorySize, smem);
    attn_kernel<<<dim3(SEQ/64, NB*NHEAD), 256, smem>>>(pq, pk, pv, pao);

    attn_map_kernel<<<NB, 256>>>(pq, pk, out + (size_t)TOK * CDIM);

    // out = ao @ proj_w^T + proj_b + xc
    gemm_nt<128,128,16,8,8,EPI_RES><<<dim3(CDIM/128, TOK/128), 256>>>(
        pao, proj_w, proj_b, pxc, out, TOK, CDIM, CDIM);
}

// round 4
// speedup vs baseline: 2.7465x; 1.6860x over previous
#include <cuda_runtime.h>
#include <math.h>
#include <stdint.h>

// Problem constants
#define TOK   4096          // b*l tokens
#define CDIM  1024
#define CHID  4096          // mlp hidden
#define NHEAD 16
#define HDIM  64
#define NB    4
#define SEQ   1024

// ---------------- scratch (device globals; no allocation allowed) ----------
__device__ float g_x   [TOK * CDIM];
__device__ float g_op0 [TOK * CDIM];
__device__ float g_h1  [TOK * 64];
__device__ float g_gate[TOK * CDIM];
__device__ float g_mh  [TOK * CHID];
__device__ float g_op3 [TOK * CDIM];
__device__ float g_xc  [TOK * CDIM];
__device__ float g_qkv [TOK * 3 * CDIM];
__device__ float g_q   [TOK * CDIM];   // [b,h,n,d]
__device__ float g_k   [TOK * CDIM];   // [b,h,n,d]
__device__ float g_v   [TOK * CDIM];   // [b,h,n,d]
__device__ float g_ao  [TOK * CDIM];   // attention out, token-major

// ---------------- epilogues -------------------------------------------------
#define EPI_NONE 0
#define EPI_GELU 1
#define EPI_RELU 2
#define EPI_SIGM 3
#define EPI_RES  4

__device__ __forceinline__ float gelu_exact(float v) {
    return 0.5f * v * (1.0f + erff(v * 0.70710678118654752f));
}
__device__ __forceinline__ float epi_apply_sc(float v, int EPI) { return v; }

__device__ __forceinline__ uint32_t f2tf32(float x) {
    uint32_t u;
    asm("cvt.rn.tf32.f32 %0, %1;" : "=r"(u) : "f"(x));
    return u;
}
__device__ __forceinline__ float tf32bits(float x) {
    return __uint_as_float(f2tf32(x));
}

__device__ __forceinline__ void mma16n8k8(float acc[4],
                                          uint32_t a0, uint32_t a1, uint32_t a2, uint32_t a3,
                                          uint32_t b0, uint32_t b1) {
    asm volatile(
        "mma.sync.aligned.m16n8k8.row.col.f32.tf32.tf32.f32 "
        "{%0,%1,%2,%3}, {%4,%5,%6,%7}, {%8,%9}, {%0,%1,%2,%3};\n"
        : "+f"(acc[0]), "+f"(acc[1]), "+f"(acc[2]), "+f"(acc[3])
        : "r"(a0), "r"(a1), "r"(a2), "r"(a3), "r"(b0), "r"(b1));
}

// ================= tf32 mma.sync GEMM: Out[m,n] = A[m,:].W[n,:] + bias ======
// CTA tile 128x128, BK=16, 8 warps (2x4), warp tile 64x32 (4x4 m16n8k8 frags).
// SMEM layout pairs (k, k+4) as float2 so each A/B fragment is one LDS.64.
template<int EPI>
__global__ __launch_bounds__(256, 2)
void gemm_mma(const float* __restrict__ A, const float* __restrict__ W,
              const float* __restrict__ bias, const float* __restrict__ res,
              float* __restrict__ Out, int M, int N, int K)
{
    __shared__ float2 As2[2][8][130];   // [buf][pair-idx][m]
    __shared__ float2 Ws2[2][8][130];   // [buf][pair-idx][n]

    const int tid  = threadIdx.x;
    const int lane = tid & 31, wid = tid >> 5;
    const int gid  = lane >> 2, tig = lane & 3;
    const int m0 = blockIdx.y * 128, n0 = blockIdx.x * 128;
    const int mb = (wid >> 2) * 64,  nb = (wid & 3) * 32;

    // staging indices: each thread owns rows r_, r_+64 at k-group f_
    const int r_ = tid >> 2, f_ = tid & 3;

    float acc[4][4][4];
#pragma unroll
    for (int mf = 0; mf < 4; mf++)
#pragma unroll
        for (int nf = 0; nf < 4; nf++)
#pragma unroll
            for (int i = 0; i < 4; i++) acc[mf][nf][i] = 0.f;

    const int nchunk = K >> 4;
    float4 sa[2], sb[2];

    // ---- LDG chunk 0
#pragma unroll
    for (int i = 0; i < 2; i++) {
        int rr = r_ + i * 64;
        sa[i] = *(const float4*)&A[(size_t)(m0 + rr) * K + f_ * 4];
        sb[i] = *(const float4*)&W[(size_t)(n0 + rr) * K + f_ * 4];
    }
    // ---- STS chunk 0 -> buf 0 (tf32-rounded)
    {
        const int p0 = (f_ >> 1) * 4, h = f_ & 1;
#pragma unroll
        for (int i = 0; i < 2; i++) {
            int rr = r_ + i * 64;
            ((float*)&As2[0][p0 + 0][rr])[h] = tf32bits(sa[i].x);
            ((float*)&As2[0][p0 + 1][rr])[h] = tf32bits(sa[i].y);
            ((float*)&As2[0][p0 + 2][rr])[h] = tf32bits(sa[i].z);
            ((float*)&As2[0][p0 + 3][rr])[h] = tf32bits(sa[i].w);
            ((float*)&Ws2[0][p0 + 0][rr])[h] = tf32bits(sb[i].x);
            ((float*)&Ws2[0][p0 + 1][rr])[h] = tf32bits(sb[i].y);
            ((float*)&Ws2[0][p0 + 2][rr])[h] = tf32bits(sb[i].z);
            ((float*)&Ws2[0][p0 + 3][rr])[h] = tf32bits(sb[i].w);
        }
    }
    __syncthreads();

    for (int c = 0; c < nchunk; c++) {
        const int buf = c & 1;
        const bool more = (c + 1 < nchunk);
        if (more) {
            int kc = (c + 1) << 4;
#pragma unroll
            for (int i = 0; i < 2; i++) {
                int rr = r_ + i * 64;
                sa[i] = *(const float4*)&A[(size_t)(m0 + rr) * K + kc + f_ * 4];
                sb[i] = *(const float4*)&W[(size_t)(n0 + rr) * K + kc + f_ * 4];
            }
        }
        // ---- compute current buffer
#pragma unroll
        for (int ks = 0; ks < 2; ks++) {
            const int p = ks * 4 + tig;
            uint2 bfr[4];
#pragma unroll
            for (int nf = 0; nf < 4; nf++)
                bfr[nf] = *(const uint2*)&Ws2[buf][p][nb + nf * 8 + gid];
#pragma unroll
            for (int mf = 0; mf < 4; mf++) {
                uint2 aL = *(const uint2*)&As2[buf][p][mb + mf * 16 + gid];
                uint2 aH = *(const uint2*)&As2[buf][p][mb + mf * 16 + 8 + gid];
#pragma unroll
                for (int nf = 0; nf < 4; nf++)
                    mma16n8k8(acc[mf][nf], aL.x, aH.x, aL.y, aH.y, bfr[nf].x, bfr[nf].y);
            }
        }
        if (more) {
            const int p0 = (f_ >> 1) * 4, h = f_ & 1, nbuf = buf ^ 1;
#pragma unroll
            for (int i = 0; i < 2; i++) {
                int rr = r_ + i * 64;
                ((float*)&As2[nbuf][p0 + 0][rr])[h] = tf32bits(sa[i].x);
                ((float*)&As2[nbuf][p0 + 1][rr])[h] = tf32bits(sa[i].y);
                ((float*)&As2[nbuf][p0 + 2][rr])[h] = tf32bits(sa[i].z);
                ((float*)&As2[nbuf][p0 + 3][rr])[h] = tf32bits(sa[i].w);
                ((float*)&Ws2[nbuf][p0 + 0][rr])[h] = tf32bits(sb[i].x);
                ((float*)&Ws2[nbuf][p0 + 1][rr])[h] = tf32bits(sb[i].y);
                ((float*)&Ws2[nbuf][p0 + 2][rr])[h] = tf32bits(sb[i].z);
                ((float*)&Ws2[nbuf][p0 + 3][rr])[h] = tf32bits(sb[i].w);
            }
            __syncthreads();
        }
    }

    // ---- epilogue
#pragma unroll
    for (int mf = 0; mf < 4; mf++) {
        const int row0 = m0 + mb + mf * 16 + gid;
        const int row1 = row0 + 8;
#pragma unroll
        for (int nf = 0; nf < 4; nf++) {
            const int col = n0 + nb + nf * 8 + 2 * tig;
            float2 b2 = *(const float2*)&bias[col];
            float v0 = acc[mf][nf][0] + b2.x;
            float v1 = acc[mf][nf][1] + b2.y;
            float v2 = acc[mf][nf][2] + b2.x;
            float v3 = acc[mf][nf][3] + b2.y;
            if (EPI == EPI_GELU) {
                v0 = gelu_exact(v0); v1 = gelu_exact(v1);
                v2 = gelu_exact(v2); v3 = gelu_exact(v3);
            } else if (EPI == EPI_RELU) {
                v0 = fmaxf(v0, 0.f); v1 = fmaxf(v1, 0.f);
                v2 = fmaxf(v2, 0.f); v3 = fmaxf(v3, 0.f);
            } else if (EPI == EPI_SIGM) {
                v0 = 1.f/(1.f+__expf(-v0)); v1 = 1.f/(1.f+__expf(-v1));
                v2 = 1.f/(1.f+__expf(-v2)); v3 = 1.f/(1.f+__expf(-v3));
            } else if (EPI == EPI_RES) {
                float2 r0 = *(const float2*)&res[(size_t)row0 * N + col];
                float2 r1 = *(const float2*)&res[(size_t)row1 * N + col];
                v0 += r0.x; v1 += r0.y; v2 += r1.x; v3 += r1.y;
            }
            float2 o0 = {v0, v1}, o1 = {v2, v3};
            *(float2*)&Out[(size_t)row0 * N + col] = o0;
            *(float2*)&Out[(size_t)row1 * N + col] = o1;
        }
    }
}

// ---------------- fp32 fallback GEMM (small ca1 only) -----------------------
template<int BM, int BN, int BK, int TM, int TN, int EPI>
__global__ __launch_bounds__((BM/TM)*(BN/TN))
void gemm_nt(const float* __restrict__ A, const float* __restrict__ W,
             const float* __restrict__ bias, const float* __restrict__ res,
             float* __restrict__ Out, int M, int N, int K)
{
    constexpr int NT = (BM/TM)*(BN/TN);
    __shared__ float As[BK][BM + 4];
    __shared__ float Ws[BK][BN + 4];

    const int tid = threadIdx.x;
    const int m0 = blockIdx.y * BM;
    const int n0 = blockIdx.x * BN;
    const int tx = tid % (BN / TN);
    const int ty = tid / (BN / TN);

    float acc[TM][TN];
#pragma unroll
    for (int i = 0; i < TM; i++)
#pragma unroll
        for (int j = 0; j < TN; j++) acc[i][j] = 0.f;

    for (int k0 = 0; k0 < K; k0 += BK) {
#pragma unroll
        for (int i = tid; i < BM*BK/4; i += NT) {
            int r = i / (BK/4), cg = i % (BK/4);
            float4 v = *(const float4*)&A[(size_t)(m0 + r) * K + k0 + cg*4];
            As[cg*4+0][r] = v.x; As[cg*4+1][r] = v.y;
            As[cg*4+2][r] = v.z; As[cg*4+3][r] = v.w;
        }
#pragma unroll
        for (int i = tid; i < BN*BK/4; i += NT) {
            int r = i / (BK/4), cg = i % (BK/4);
            float4 v = *(const float4*)&W[(size_t)(n0 + r) * K + k0 + cg*4];
            Ws[cg*4+0][r] = v.x; Ws[cg*4+1][r] = v.y;
            Ws[cg*4+2][r] = v.z; Ws[cg*4+3][r] = v.w;
        }
        __syncthreads();
#pragma unroll
        for (int k = 0; k < BK; k++) {
            float a[TM], b[TN];
#pragma unroll
            for (int i = 0; i < TM; i++) a[i] = As[k][ty*TM + i];
#pragma unroll
            for (int j = 0; j < TN; j++) b[j] = Ws[k][tx*TN + j];
#pragma unroll
            for (int i = 0; i < TM; i++)
#pragma unroll
                for (int j = 0; j < TN; j++) acc[i][j] += a[i] * b[j];
        }
        __syncthreads();
    }

#pragma unroll
    for (int i = 0; i < TM; i++) {
        int m = m0 + ty*TM + i;
#pragma unroll
        for (int j = 0; j < TN; j++) {
            int n = n0 + tx*TN + j;
            float v = acc[i][j] + bias[n];
            if (EPI == EPI_GELU) v = gelu_exact(v);
            else if (EPI == EPI_RELU) v = fmaxf(v, 0.f);
            else if (EPI == EPI_SIGM) v = 1.0f / (1.0f + __expf(-v));
            else if (EPI == EPI_RES)  v += res[(size_t)m * N + n];
            Out[(size_t)m * N + n] = v;
        }
    }
}

// ---------------- extract x = x_list[...,-1] --------------------------------
__global__ void extract_x(const float* __restrict__ x_list, float* __restrict__ x)
{
    int i = blockIdx.x * blockDim.x + threadIdx.x;
    if (i < TOK * CDIM) x[i] = x_list[2*i + 1];
}

// ---------------- combine: softmax(w_/T) weighted mix -----------------------
__global__ void combine(const float* __restrict__ x_list,
                        const float* __restrict__ w_,
                        const float* __restrict__ op0,
                        const float* __restrict__ gate,
                        const float* __restrict__ op3,
                        float* __restrict__ xc)
{
    float w[6], mx = -1e30f;
#pragma unroll
    for (int i = 0; i < 6; i++) { w[i] = w_[i] * 100.0f; mx = fmaxf(mx, w[i]); }
    float s = 0.f;
#pragma unroll
    for (int i = 0; i < 6; i++) { w[i] = __expf(w[i] - mx); s += w[i]; }
    float inv = 1.0f / s;
#pragma unroll
    for (int i = 0; i < 6; i++) w[i] *= inv;

    int i = blockIdx.x * blockDim.x + threadIdx.x;
    if (i >= TOK * CDIM) return;
    float xl0 = x_list[2*i];
    float xv  = x_list[2*i + 1];
    float v = w[0]*xl0 + (w[1] + w[4])*xv + w[2]*op0[i] + w[3]*(gate[i]*xv) + w[5]*op3[i];
    xc[i] = v;
}

// ---------------- qkv split + per-head LN + head-major transpose ------------
__global__ void ln_split(const float* __restrict__ qkv,
                         const float* __restrict__ nqg, const float* __restrict__ nqb,
                         const float* __restrict__ nkg, const float* __restrict__ nkb,
                         float* __restrict__ Qo, float* __restrict__ Ko, float* __restrict__ Vo)
{
    int gw = (blockIdx.x * blockDim.x + threadIdx.x) >> 5;
    int lane = threadIdx.x & 31;
    if (gw >= TOK * NHEAD) return;
    int t = gw / NHEAD, h = gw % NHEAD;
    int b = t / SEQ, n = t % SEQ;
    size_t src = (size_t)t * (3*CDIM) + h * HDIM;
    size_t dst = ((size_t)(b*NHEAD + h) * SEQ + n) * HDIM;

#pragma unroll
    for (int which = 0; which < 2; which++) {
        size_t so = src + (which ? CDIM : 0);
        float2 xv = *(const float2*)&qkv[so + lane*2];
        float sum = xv.x + xv.y;
        float ssq = xv.x*xv.x + xv.y*xv.y;
#pragma unroll
        for (int o = 16; o > 0; o >>= 1) {
            sum += __shfl_xor_sync(0xffffffff, sum, o);
            ssq += __shfl_xor_sync(0xffffffff, ssq, o);
        }
        float mean = sum * (1.0f/64.0f);
        float var  = ssq * (1.0f/64.0f) - mean*mean;
        float inv  = rsqrtf(var + 1e-5f);
        const float* g = which ? nkg : nqg;
        const float* bb = which ? nkb : nqb;
        float* O = which ? Ko : Qo;
        O[dst + lane*2 + 0] = (xv.x - mean)*inv*g[lane*2+0] + bb[lane*2+0];
        O[dst + lane*2 + 1] = (xv.y - mean)*inv*g[lane*2+1] + bb[lane*2+1];
    }
    *(float2*)&Vo[dst + lane*2] = *(const float2*)&qkv[src + 2*CDIM + lane*2];
}

// ---------------- flash attention (64x64 tiles, online softmax) -------------
#define APAD 68
__global__ __launch_bounds__(256)
void attn_kernel(const float* __restrict__ Q, const float* __restrict__ K,
                 const float* __restrict__ V, float* __restrict__ AO)
{
    extern __shared__ float sm[];
    float* Qs = sm;
    float* Ks = Qs + 64*APAD;
    float* Vs = Ks + 64*APAD;
    float* Ss = Vs + 64*APAD;
    float* Pt = Ss + 64*APAD;
    float* m_s  = Pt + 64*APAD;
    float* l_s  = m_s + 64;
    float* sc_s = l_s + 64;

    const int tid = threadIdx.x;
    const int q0 = blockIdx.x * 64;
    const int bh = blockIdx.y;
    const float* Qb = Q + (size_t)bh * SEQ * HDIM;
    const float* Kb = K + (size_t)bh * SEQ * HDIM;
    const float* Vb = V + (size_t)bh * SEQ * HDIM;

    for (int i = tid; i < 64*16; i += 256) {
        int r = i / 16, cg = i % 16;
        float4 v = *(const float4*)&Qb[(size_t)(q0 + r) * HDIM + cg*4];
        Qs[(cg*4+0)*APAD + r] = v.x; Qs[(cg*4+1)*APAD + r] = v.y;
        Qs[(cg*4+2)*APAD + r] = v.z; Qs[(cg*4+3)*APAD + r] = v.w;
    }
    if (tid < 64) { m_s[tid] = -1e30f; l_s[tid] = 0.f; }

    const int ty = tid / 16, tx = tid % 16;
    const int rg = tid / 4,  sub = tid % 4;

    float o[4][4];
#pragma unroll
    for (int i = 0; i < 4; i++)
#pragma unroll
        for (int j = 0; j < 4; j++) o[i][j] = 0.f;

    for (int kt = 0; kt < 16; kt++) {
        __syncthreads();
        int k0 = kt * 64;
        for (int i = tid; i < 64*16; i += 256) {
            int r = i / 16, cg = i % 16;
            float4 v = *(const float4*)&Kb[(size_t)(k0 + r) * HDIM + cg*4];
            Ks[(cg*4+0)*APAD + r] = v.x; Ks[(cg*4+1)*APAD + r] = v.y;
            Ks[(cg*4+2)*APAD + r] = v.z; Ks[(cg*4+3)*APAD + r] = v.w;
            float4 w = *(const float4*)&Vb[(size_t)(k0 + r) * HDIM + cg*4];
            *(float4*)&Vs[r*APAD + cg*4] = w;
        }
        __syncthreads();

        float s[4][4];
#pragma unroll
        for (int i = 0; i < 4; i++)
#pragma unroll
            for (int j = 0; j < 4; j++) s[i][j] = 0.f;
#pragma unroll 16
        for (int d = 0; d < 64; d++) {
            float a[4], b[4];
#pragma unroll
            for (int i = 0; i < 4; i++) a[i] = Qs[d*APAD + ty*4 + i];
#pragma unroll
            for (int j = 0; j < 4; j++) b[j] = Ks[d*APAD + tx*4 + j];
#pragma unroll
            for (int i = 0; i < 4; i++)
#pragma unroll
                for (int j = 0; j < 4; j++) s[i][j] += a[i] * b[j];
        }
#pragma unroll
        for (int i = 0; i < 4; i++)
#pragma unroll
            for (int j = 0; j < 4; j++)
                Ss[(ty*4+i)*APAD + tx*4 + j] = s[i][j] * 0.125f;
        __syncthreads();

        float p[16], mx = -1e30f;
#pragma unroll
        for (int i = 0; i < 16; i++) { p[i] = Ss[rg*APAD + sub*16 + i]; mx = fmaxf(mx, p[i]); }
        mx = fmaxf(mx, __shfl_xor_sync(0xffffffff, mx, 1));
        mx = fmaxf(mx, __shfl_xor_sync(0xffffffff, mx, 2));
        float newm = fmaxf(m_s[rg], mx);
        float sum = 0.f;
#pragma unroll
        for (int i = 0; i < 16; i++) {
            p[i] = __expf(p[i] - newm);
            sum += p[i];
            Pt[(sub*16 + i)*APAD + rg] = p[i];
        }
        sum += __shfl_xor_sync(0xffffffff, sum, 1);
        sum += __shfl_xor_sync(0xffffffff, sum, 2);
        if (sub == 0) {
            float sc = __expf(m_s[rg] - newm);
            sc_s[rg] = sc;
            l_s[rg] = l_s[rg] * sc + sum;
            m_s[rg] = newm;
        }
        __syncthreads();

        float scq[4];
#pragma unroll
        for (int i = 0; i < 4; i++) scq[i] = sc_s[ty*4 + i];
#pragma unroll
        for (int i = 0; i < 4; i++)
#pragma unroll
            for (int j = 0; j < 4; j++) o[i][j] *= scq[i];
#pragma unroll 16
        for (int kk = 0; kk < 64; kk++) {
            float a[4], b[4];
#pragma unroll
            for (int i = 0; i < 4; i++) a[i] = Pt[kk*APAD + ty*4 + i];
#pragma unroll
            for (int j = 0; j < 4; j++) b[j] = Vs[kk*APAD + tx*4 + j];
#pragma unroll
            for (int i = 0; i < 4; i++)
#pragma unroll
                for (int j = 0; j < 4; j++) o[i][j] += a[i] * b[j];
        }
    }
    __syncthreads();

    int b = bh / NHEAD, h = bh % NHEAD;
#pragma unroll
    for (int i = 0; i < 4; i++) {
        int q = ty*4 + i;
        float inv = 1.0f / l_s[q];
#pragma unroll
        for (int j = 0; j < 4; j++) {
            AO[(size_t)(b*SEQ + q0 + q) * CDIM + h*HDIM + tx*4 + j] = o[i][j] * inv;
        }
    }
}

// ---------------- attention map for query 0 (mean over heads) ---------------
__global__ void attn_map_kernel(const float* __restrict__ Q, const float* __restrict__ K,
                                float* __restrict__ omap)
{
    __shared__ float sc[SEQ];
    __shared__ float acc[SEQ];
    __shared__ float red[256];
    __shared__ float q0[HDIM];
    int b = blockIdx.x, tid = threadIdx.x;
    for (int i = tid; i < SEQ; i += 256) acc[i] = 0.f;
    for (int h = 0; h < NHEAD; h++) {
        const float* Qb = Q + ((size_t)(b*NHEAD + h) * SEQ) * HDIM;
        const float* Kb = K + ((size_t)(b*NHEAD + h) * SEQ) * HDIM;
        __syncthreads();
        if (tid < HDIM) q0[tid] = Qb[tid];
        __syncthreads();
        for (int m = tid; m < SEQ; m += 256) {
            float s = 0.f;
#pragma unroll 16
            for (int j = 0; j < HDIM; j++) s += q0[j] * Kb[(size_t)m*HDIM + j];
            sc[m] = s * 0.125f;
        }
        __syncthreads();
        float mx = -1e30f;
        for (int m = tid; m < SEQ; m += 256) mx = fmaxf(mx, sc[m]);
        red[tid] = mx; __syncthreads();
        for (int s = 128; s > 0; s >>= 1) { if (tid < s) red[tid] = fmaxf(red[tid], red[tid+s]); __syncthreads(); }
        mx = red[0]; __syncthreads();
        float sum = 0.f;
        for (int m = tid; m < SEQ; m += 256) { float p = __expf(sc[m] - mx); sc[m] = p; sum += p; }
        red[tid] = sum; __syncthreads();
        for (int s = 128; s > 0; s >>= 1) { if (tid < s) red[tid] += red[tid+s]; __syncthreads(); }
        float inv = 1.0f / red[0]; __syncthreads();
        for (int m = tid; m < SEQ; m += 256) acc[m] += sc[m] * inv;
    }
    __syncthreads();
    for (int m = tid; m < SEQ; m += 256)
        if (m >= 1) omap[(size_t)b*(SEQ-1) + m - 1] = acc[m] * (1.0f/NHEAD);
}

// ---------------- launch ----------------------------------------------------
extern "C" void kernel_launch(void* const* d_in, const int* in_sizes, int n_in,
                              void* d_out, int out_size)
{
    const float* x_list = (const float*)d_in[0];
    const float* w_     = (const float*)d_in[1];
    const float* qkv_w  = (const float*)d_in[2];
    const float* qkv_b  = (const float*)d_in[3];
    const float* proj_w = (const float*)d_in[4];
    const float* proj_b = (const float*)d_in[5];
    const float* nq_g   = (const float*)d_in[6];
    const float* nq_b   = (const float*)d_in[7];
    const float* nk_g   = (const float*)d_in[8];
    const float* nk_b   = (const float*)d_in[9];
    const float* conv_w = (const float*)d_in[10];
    const float* conv_b = (const float*)d_in[11];
    const float* ca1_w  = (const float*)d_in[12];
    const float* ca1_b  = (const float*)d_in[13];
    const float* ca2_w  = (const float*)d_in[14];
    const float* ca2_b  = (const float*)d_in[15];
    const float* mlp1_w = (const float*)d_in[16];
    const float* mlp1_b = (const float*)d_in[17];
    const float* mlp2_w = (const float*)d_in[18];
    const float* mlp2_b = (const float*)d_in[19];
    float* out = (float*)d_out;

    float *px, *pop0, *ph1, *pgate, *pmh, *pop3, *pxc, *pqkv, *pq, *pk, *pv, *pao;
    cudaGetSymbolAddress((void**)&px,   g_x);
    cudaGetSymbolAddress((void**)&pop0, g_op0);
    cudaGetSymbolAddress((void**)&ph1,  g_h1);
    cudaGetSymbolAddress((void**)&pgate,g_gate);
    cudaGetSymbolAddress((void**)&pmh,  g_mh);
    cudaGetSymbolAddress((void**)&pop3, g_op3);
    cudaGetSymbolAddress((void**)&pxc,  g_xc);
    cudaGetSymbolAddress((void**)&pqkv, g_qkv);
    cudaGetSymbolAddress((void**)&pq,   g_q);
    cudaGetSymbolAddress((void**)&pk,   g_k);
    cudaGetSymbolAddress((void**)&pv,   g_v);
    cudaGetSymbolAddress((void**)&pao,  g_ao);

    const int NE = TOK * CDIM;

    extract_x<<<(NE + 255)/256, 256>>>(x_list, px);

    // op0 = gelu(x @ conv_w^T + conv_b)
    gemm_mma<EPI_GELU><<<dim3(CDIM/128, TOK/128), 256>>>(
        px, conv_w, conv_b, nullptr, pop0, TOK, CDIM, CDIM);
    // h1 = relu(x @ ca1_w^T + ca1_b)   [4096,64]  (small, fp32)
    gemm_nt<128,64,16,8,4,EPI_RELU><<<dim3(1, TOK/128), 256>>>(
        px, ca1_w, ca1_b, nullptr, ph1, TOK, 64, CDIM);
    // gate = sigmoid(h1 @ ca2_w^T + ca2_b)  (K=64)
    gemm_mma<EPI_SIGM><<<dim3(CDIM/128, TOK/128), 256>>>(
        ph1, ca2_w, ca2_b, nullptr, pgate, TOK, CDIM, 64);
    // mh = gelu(x @ mlp1_w^T + mlp1_b)  [4096,4096]
    gemm_mma<EPI_GELU><<<dim3(CHID/128, TOK/128), 256>>>(
        px, mlp1_w, mlp1_b, nullptr, pmh, TOK, CHID, CDIM);
    // op3 = mh @ mlp2_w^T + mlp2_b   (K=4096)
    gemm_mma<EPI_NONE><<<dim3(CDIM/128, TOK/128), 256>>>(
        pmh, mlp2_w, mlp2_b, nullptr, pop3, TOK, CDIM, CHID);

    combine<<<(NE + 255)/256, 256>>>(x_list, w_, pop0, pgate, pop3, pxc);

    // qkv = xc @ qkv_w^T + qkv_b   [4096,3072]
    gemm_mma<EPI_NONE><<<dim3(3*CDIM/128, TOK/128), 256>>>(
        pxc, qkv_w, qkv_b, nullptr, pqkv, TOK, 3*CDIM, CDIM);

    ln_split<<<(TOK*NHEAD*32 + 255)/256, 256>>>(pqkv, nq_g, nq_b, nk_g, nk_b, pq, pk, pv);

    int smem = (5 * 64 * APAD + 3 * 64) * (int)sizeof(float);
    cudaFuncSetAttribute(attn_kernel, cudaFuncAttributeMaxDynamicSharedMemorySize, smem);
    attn_kernel<<<dim3(SEQ/64, NB*NHEAD), 256, smem>>>(pq, pk, pv, pao);

    attn_map_kernel<<<NB, 256>>>(pq, pk, out + (size_t)TOK * CDIM);

    // out = ao @ proj_w^T + proj_b + xc
    gemm_mma<EPI_RES><<<dim3(CDIM/128, TOK/128), 256>>>(
        pao, proj_w, proj_b, pxc, out, TOK, CDIM, CDIM);
}

// round 6
// speedup vs baseline: 3.2916x; 1.1985x over previous
#include <cuda_runtime.h>
#include <math.h>
#include <stdint.h>

// Problem constants
#define TOK   4096          // b*l tokens
#define CDIM  1024
#define CHID  4096          // mlp hidden
#define NHEAD 16
#define HDIM  64
#define NB    4
#define SEQ   1024

// ---------------- scratch (device globals; no allocation allowed) ----------
__device__ float g_x   [TOK * CDIM];
__device__ float g_op0 [TOK * CDIM];
__device__ float g_h1  [TOK * 64];
__device__ float g_gate[TOK * CDIM];
__device__ float g_mh  [TOK * CHID];
__device__ float g_op3 [TOK * CDIM];
__device__ float g_xc  [TOK * CDIM];
__device__ float g_qkv [TOK * 3 * CDIM];
__device__ float g_q   [TOK * CDIM];   // [b,h,n,d]
__device__ float g_k   [TOK * CDIM];   // [b,h,n,d]
__device__ float g_v   [TOK * CDIM];   // [b,h,n,d]
__device__ float g_ao  [TOK * CDIM];   // attention out, token-major

// ---------------- epilogues -------------------------------------------------
#define EPI_NONE 0
#define EPI_GELU 1
#define EPI_RELU 2
#define EPI_SIGM 3
#define EPI_RES  4

__device__ __forceinline__ float gelu_exact(float v) {
    return 0.5f * v * (1.0f + erff(v * 0.70710678118654752f));
}

__device__ __forceinline__ uint32_t f2tf32(float x) {
    uint32_t u;
    asm("cvt.rn.tf32.f32 %0, %1;" : "=r"(u) : "f"(x));
    return u;
}
__device__ __forceinline__ float tf32bits(float x) {
    return __uint_as_float(f2tf32(x));
}

__device__ __forceinline__ void mma16n8k8(float acc[4],
                                          uint32_t a0, uint32_t a1, uint32_t a2, uint32_t a3,
                                          uint32_t b0, uint32_t b1) {
    asm volatile(
        "mma.sync.aligned.m16n8k8.row.col.f32.tf32.tf32.f32 "
        "{%0,%1,%2,%3}, {%4,%5,%6,%7}, {%8,%9}, {%0,%1,%2,%3};\n"
        : "+f"(acc[0]), "+f"(acc[1]), "+f"(acc[2]), "+f"(acc[3])
        : "r"(a0), "r"(a1), "r"(a2), "r"(a3), "r"(b0), "r"(b1));
}

// ================= tf32 mma.sync GEMM: Out[m,n] = A[m,:].W[n,:] + bias ======
// CTA tile 128x128, BK=16, 8 warps (2x4), warp tile 64x32 (4x4 m16n8k8 frags).
template<int EPI>
__global__ __launch_bounds__(256, 2)
void gemm_mma(const float* __restrict__ A, const float* __restrict__ W,
              const float* __restrict__ bias, const float* __restrict__ res,
              float* __restrict__ Out, int M, int N, int K)
{
    __shared__ float2 As2[2][8][130];   // [buf][pair-idx][m]
    __shared__ float2 Ws2[2][8][130];   // [buf][pair-idx][n]

    const int tid  = threadIdx.x;
    const int lane = tid & 31, wid = tid >> 5;
    const int gid  = lane >> 2, tig = lane & 3;
    const int m0 = blockIdx.y * 128, n0 = blockIdx.x * 128;
    const int mb = (wid >> 2) * 64,  nb = (wid & 3) * 32;

    const int r_ = tid >> 2, f_ = tid & 3;

    float acc[4][4][4];
#pragma unroll
    for (int mf = 0; mf < 4; mf++)
#pragma unroll
        for (int nf = 0; nf < 4; nf++)
#pragma unroll
            for (int i = 0; i < 4; i++) acc[mf][nf][i] = 0.f;

    const int nchunk = K >> 4;
    float4 sa[2], sb[2];

#pragma unroll
    for (int i = 0; i < 2; i++) {
        int rr = r_ + i * 64;
        sa[i] = *(const float4*)&A[(size_t)(m0 + rr) * K + f_ * 4];
        sb[i] = *(const float4*)&W[(size_t)(n0 + rr) * K + f_ * 4];
    }
    {
        const int p0 = (f_ >> 1) * 4, h = f_ & 1;
#pragma unroll
        for (int i = 0; i < 2; i++) {
            int rr = r_ + i * 64;
            ((float*)&As2[0][p0 + 0][rr])[h] = tf32bits(sa[i].x);
            ((float*)&As2[0][p0 + 1][rr])[h] = tf32bits(sa[i].y);
            ((float*)&As2[0][p0 + 2][rr])[h] = tf32bits(sa[i].z);
            ((float*)&As2[0][p0 + 3][rr])[h] = tf32bits(sa[i].w);
            ((float*)&Ws2[0][p0 + 0][rr])[h] = tf32bits(sb[i].x);
            ((float*)&Ws2[0][p0 + 1][rr])[h] = tf32bits(sb[i].y);
            ((float*)&Ws2[0][p0 + 2][rr])[h] = tf32bits(sb[i].z);
            ((float*)&Ws2[0][p0 + 3][rr])[h] = tf32bits(sb[i].w);
        }
    }
    __syncthreads();

    for (int c = 0; c < nchunk; c++) {
        const int buf = c & 1;
        const bool more = (c + 1 < nchunk);
        if (more) {
            int kc = (c + 1) << 4;
#pragma unroll
            for (int i = 0; i < 2; i++) {
                int rr = r_ + i * 64;
                sa[i] = *(const float4*)&A[(size_t)(m0 + rr) * K + kc + f_ * 4];
                sb[i] = *(const float4*)&W[(size_t)(n0 + rr) * K + kc + f_ * 4];
            }
        }
#pragma unroll
        for (int ks = 0; ks < 2; ks++) {
            const int p = ks * 4 + tig;
            uint2 bfr[4];
#pragma unroll
            for (int nf = 0; nf < 4; nf++)
                bfr[nf] = *(const uint2*)&Ws2[buf][p][nb + nf * 8 + gid];
#pragma unroll
            for (int mf = 0; mf < 4; mf++) {
                uint2 aL = *(const uint2*)&As2[buf][p][mb + mf * 16 + gid];
                uint2 aH = *(const uint2*)&As2[buf][p][mb + mf * 16 + 8 + gid];
#pragma unroll
                for (int nf = 0; nf < 4; nf++)
                    mma16n8k8(acc[mf][nf], aL.x, aH.x, aL.y, aH.y, bfr[nf].x, bfr[nf].y);
            }
        }
        if (more) {
            const int p0 = (f_ >> 1) * 4, h = f_ & 1, nbuf = buf ^ 1;
#pragma unroll
            for (int i = 0; i < 2; i++) {
                int rr = r_ + i * 64;
                ((float*)&As2[nbuf][p0 + 0][rr])[h] = tf32bits(sa[i].x);
                ((float*)&As2[nbuf][p0 + 1][rr])[h] = tf32bits(sa[i].y);
                ((float*)&As2[nbuf][p0 + 2][rr])[h] = tf32bits(sa[i].z);
                ((float*)&As2[nbuf][p0 + 3][rr])[h] = tf32bits(sa[i].w);
                ((float*)&Ws2[nbuf][p0 + 0][rr])[h] = tf32bits(sb[i].x);
                ((float*)&Ws2[nbuf][p0 + 1][rr])[h] = tf32bits(sb[i].y);
                ((float*)&Ws2[nbuf][p0 + 2][rr])[h] = tf32bits(sb[i].z);
                ((float*)&Ws2[nbuf][p0 + 3][rr])[h] = tf32bits(sb[i].w);
            }
            __syncthreads();
        }
    }

#pragma unroll
    for (int mf = 0; mf < 4; mf++) {
        const int row0 = m0 + mb + mf * 16 + gid;
        const int row1 = row0 + 8;
#pragma unroll
        for (int nf = 0; nf < 4; nf++) {
            const int col = n0 + nb + nf * 8 + 2 * tig;
            float2 b2 = *(const float2*)&bias[col];
            float v0 = acc[mf][nf][0] + b2.x;
            float v1 = acc[mf][nf][1] + b2.y;
            float v2 = acc[mf][nf][2] + b2.x;
            float v3 = acc[mf][nf][3] + b2.y;
            if (EPI == EPI_GELU) {
                v0 = gelu_exact(v0); v1 = gelu_exact(v1);
                v2 = gelu_exact(v2); v3 = gelu_exact(v3);
            } else if (EPI == EPI_RELU) {
                v0 = fmaxf(v0, 0.f); v1 = fmaxf(v1, 0.f);
                v2 = fmaxf(v2, 0.f); v3 = fmaxf(v3, 0.f);
            } else if (EPI == EPI_SIGM) {
                v0 = 1.f/(1.f+__expf(-v0)); v1 = 1.f/(1.f+__expf(-v1));
                v2 = 1.f/(1.f+__expf(-v2)); v3 = 1.f/(1.f+__expf(-v3));
            } else if (EPI == EPI_RES) {
                float2 r0 = *(const float2*)&res[(size_t)row0 * N + col];
                float2 r1 = *(const float2*)&res[(size_t)row1 * N + col];
                v0 += r0.x; v1 += r0.y; v2 += r1.x; v3 += r1.y;
            }
            float2 o0 = {v0, v1}, o1 = {v2, v3};
            *(float2*)&Out[(size_t)row0 * N + col] = o0;
            *(float2*)&Out[(size_t)row1 * N + col] = o1;
        }
    }
}

// ---------------- fp32 fallback GEMM (small ca1 only) -----------------------
template<int BM, int BN, int BK, int TM, int TN, int EPI>
__global__ __launch_bounds__((BM/TM)*(BN/TN))
void gemm_nt(const float* __restrict__ A, const float* __restrict__ W,
             const float* __restrict__ bias, const float* __restrict__ res,
             float* __restrict__ Out, int M, int N, int K)
{
    constexpr int NT = (BM/TM)*(BN/TN);
    __shared__ float As[BK][BM + 4];
    __shared__ float Ws[BK][BN + 4];

    const int tid = threadIdx.x;
    const int m0 = blockIdx.y * BM;
    const int n0 = blockIdx.x * BN;
    const int tx = tid % (BN / TN);
    const int ty = tid / (BN / TN);

    float acc[TM][TN];
#pragma unroll
    for (int i = 0; i < TM; i++)
#pragma unroll
        for (int j = 0; j < TN; j++) acc[i][j] = 0.f;

    for (int k0 = 0; k0 < K; k0 += BK) {
#pragma unroll
        for (int i = tid; i < BM*BK/4; i += NT) {
            int r = i / (BK/4), cg = i % (BK/4);
            float4 v = *(const float4*)&A[(size_t)(m0 + r) * K + k0 + cg*4];
            As[cg*4+0][r] = v.x; As[cg*4+1][r] = v.y;
            As[cg*4+2][r] = v.z; As[cg*4+3][r] = v.w;
        }
#pragma unroll
        for (int i = tid; i < BN*BK/4; i += NT) {
            int r = i / (BK/4), cg = i % (BK/4);
            float4 v = *(const float4*)&W[(size_t)(n0 + r) * K + k0 + cg*4];
            Ws[cg*4+0][r] = v.x; Ws[cg*4+1][r] = v.y;
            Ws[cg*4+2][r] = v.z; Ws[cg*4+3][r] = v.w;
        }
        __syncthreads();
#pragma unroll
        for (int k = 0; k < BK; k++) {
            float a[TM], b[TN];
#pragma unroll
            for (int i = 0; i < TM; i++) a[i] = As[k][ty*TM + i];
#pragma unroll
            for (int j = 0; j < TN; j++) b[j] = Ws[k][tx*TN + j];
#pragma unroll
            for (int i = 0; i < TM; i++)
#pragma unroll
                for (int j = 0; j < TN; j++) acc[i][j] += a[i] * b[j];
        }
        __syncthreads();
    }

#pragma unroll
    for (int i = 0; i < TM; i++) {
        int m = m0 + ty*TM + i;
#pragma unroll
        for (int j = 0; j < TN; j++) {
            int n = n0 + tx*TN + j;
            float v = acc[i][j] + bias[n];
            if (EPI == EPI_GELU) v = gelu_exact(v);
            else if (EPI == EPI_RELU) v = fmaxf(v, 0.f);
            else if (EPI == EPI_SIGM) v = 1.0f / (1.0f + __expf(-v));
            else if (EPI == EPI_RES)  v += res[(size_t)m * N + n];
            Out[(size_t)m * N + n] = v;
        }
    }
}

// ---------------- extract x = x_list[...,-1] --------------------------------
__global__ void extract_x(const float* __restrict__ x_list, float* __restrict__ x)
{
    int i = blockIdx.x * blockDim.x + threadIdx.x;
    if (i < TOK * CDIM) x[i] = x_list[2*i + 1];
}

// ---------------- combine: softmax(w_/T) weighted mix -----------------------
__global__ void combine(const float* __restrict__ x_list,
                        const float* __restrict__ w_,
                        const float* __restrict__ op0,
                        const float* __restrict__ gate,
                        const float* __restrict__ op3,
                        float* __restrict__ xc)
{
    float w[6], mx = -1e30f;
#pragma unroll
    for (int i = 0; i < 6; i++) { w[i] = w_[i] * 100.0f; mx = fmaxf(mx, w[i]); }
    float s = 0.f;
#pragma unroll
    for (int i = 0; i < 6; i++) { w[i] = __expf(w[i] - mx); s += w[i]; }
    float inv = 1.0f / s;
#pragma unroll
    for (int i = 0; i < 6; i++) w[i] *= inv;

    int i = blockIdx.x * blockDim.x + threadIdx.x;
    if (i >= TOK * CDIM) return;
    float xl0 = x_list[2*i];
    float xv  = x_list[2*i + 1];
    float v = w[0]*xl0 + (w[1] + w[4])*xv + w[2]*op0[i] + w[3]*(gate[i]*xv) + w[5]*op3[i];
    xc[i] = v;
}

// ---------------- qkv split + per-head LN + head-major transpose ------------
__global__ void ln_split(const float* __restrict__ qkv,
                         const float* __restrict__ nqg, const float* __restrict__ nqb,
                         const float* __restrict__ nkg, const float* __restrict__ nkb,
                         float* __restrict__ Qo, float* __restrict__ Ko, float* __restrict__ Vo)
{
    int gw = (blockIdx.x * blockDim.x + threadIdx.x) >> 5;
    int lane = threadIdx.x & 31;
    if (gw >= TOK * NHEAD) return;
    int t = gw / NHEAD, h = gw % NHEAD;
    int b = t / SEQ, n = t % SEQ;
    size_t src = (size_t)t * (3*CDIM) + h * HDIM;
    size_t dst = ((size_t)(b*NHEAD + h) * SEQ + n) * HDIM;

#pragma unroll
    for (int which = 0; which < 2; which++) {
        size_t so = src + (which ? CDIM : 0);
        float2 xv = *(const float2*)&qkv[so + lane*2];
        float sum = xv.x + xv.y;
        float ssq = xv.x*xv.x + xv.y*xv.y;
#pragma unroll
        for (int o = 16; o > 0; o >>= 1) {
            sum += __shfl_xor_sync(0xffffffff, sum, o);
            ssq += __shfl_xor_sync(0xffffffff, ssq, o);
        }
        float mean = sum * (1.0f/64.0f);
        float var  = ssq * (1.0f/64.0f) - mean*mean;
        float inv  = rsqrtf(var + 1e-5f);
        const float* g = which ? nkg : nqg;
        const float* bb = which ? nkb : nqb;
        float* O = which ? Ko : Qo;
        O[dst + lane*2 + 0] = (xv.x - mean)*inv*g[lane*2+0] + bb[lane*2+0];
        O[dst + lane*2 + 1] = (xv.y - mean)*inv*g[lane*2+1] + bb[lane*2+1];
    }
    *(float2*)&Vo[dst + lane*2] = *(const float2*)&qkv[src + 2*CDIM + lane*2];
}

// ---------------- tf32 MMA flash attention ----------------------------------
// CTA: 128 q-rows, 8 warps (16 q-rows each, full 64-col softmax in-warp),
// kv tiles of 64. Q and P in smem in paired-(k,k+4) float2 A-fragment format
// (32 pair-rows for K=64). K raw [64][KPAD], V raw [64][VPAD].
#define KPAD 68
#define VPAD 72
#define QS_F2   (32*130)                 // float2 count (32 pair-rows!)
#define KS_F    (64*KPAD)
#define VS_F    (64*VPAD)
#define ATT_SMEM ((QS_F2*2 + KS_F + VS_F + QS_F2*2) * 4)

__global__ __launch_bounds__(256, 2)
void attn_mma(const float* __restrict__ Q, const float* __restrict__ K,
              const float* __restrict__ V, float* __restrict__ AO)
{
    extern __shared__ float sma[];
    float2* Qs2 = (float2*)sma;                       // [32][130]
    float*  Ks  = sma + QS_F2*2;                      // [64][KPAD]
    float*  Vs  = Ks + KS_F;                          // [64][VPAD]
    float2* Ps2 = (float2*)(Vs + VS_F);               // [32][130]

    const int tid = threadIdx.x;
    const int lane = tid & 31, wid = tid >> 5;
    const int gid = lane >> 2, tig = lane & 3;
    const int q0 = blockIdx.x * 128;
    const int bh = blockIdx.y;
    const int qb = wid * 16;
    const float* Qb = Q + (size_t)bh * SEQ * HDIM;
    const float* Kb = K + (size_t)bh * SEQ * HDIM;
    const float* Vb = V + (size_t)bh * SEQ * HDIM;

    // ---- load Q tile into paired format (rn->tf32)
    {
        int r = tid >> 1, hf = tid & 1;
#pragma unroll
        for (int i = 0; i < 8; i++) {
            int k0 = hf * 32 + i * 4;
            float4 v = *(const float4*)&Qb[(size_t)(q0 + r) * HDIM + k0];
            int p0 = (k0 >> 3) * 4;
            int h  = (k0 & 4) >> 2;
            ((float*)&Qs2[(p0 + 0) * 130 + r])[h] = tf32bits(v.x);
            ((float*)&Qs2[(p0 + 1) * 130 + r])[h] = tf32bits(v.y);
            ((float*)&Qs2[(p0 + 2) * 130 + r])[h] = tf32bits(v.z);
            ((float*)&Qs2[(p0 + 3) * 130 + r])[h] = tf32bits(v.w);
        }
    }

    float oacc[8][4];
#pragma unroll
    for (int nf = 0; nf < 8; nf++)
#pragma unroll
        for (int i = 0; i < 4; i++) oacc[nf][i] = 0.f;
    float m0s = -1e30f, m1s = -1e30f, l0s = 0.f, l1s = 0.f;

    for (int kt = 0; kt < 16; kt++) {
        __syncthreads();                    // Ks/Vs free (prev tile consumed)
        {
            int j = tid >> 2, f = tid & 3;
            int rowg = kt * 64 + j;
#pragma unroll
            for (int i = 0; i < 4; i++) {
                int d0 = f * 16 + i * 4;
                float4 kv = *(const float4*)&Kb[(size_t)rowg * HDIM + d0];
                float4 vv = *(const float4*)&Vb[(size_t)rowg * HDIM + d0];
                float4 kc = { tf32bits(kv.x), tf32bits(kv.y), tf32bits(kv.z), tf32bits(kv.w) };
                float4 vc = { tf32bits(vv.x), tf32bits(vv.y), tf32bits(vv.z), tf32bits(vv.w) };
                *(float4*)&Ks[j * KPAD + d0] = kc;
                *(float4*)&Vs[j * VPAD + d0] = vc;
            }
        }
        __syncthreads();

        // ---- S = Q K^T (per-warp 16x64)
        float sacc[8][4];
#pragma unroll
        for (int nf = 0; nf < 8; nf++)
#pragma unroll
            for (int i = 0; i < 4; i++) sacc[nf][i] = 0.f;
#pragma unroll
        for (int ks = 0; ks < 8; ks++) {
            int p = ks * 4 + tig;
            uint2 aL = *(const uint2*)&Qs2[p * 130 + qb + gid];
            uint2 aH = *(const uint2*)&Qs2[p * 130 + qb + gid + 8];
#pragma unroll
            for (int nf = 0; nf < 8; nf++) {
                uint32_t b0 = __float_as_uint(Ks[(nf * 8 + gid) * KPAD + ks * 8 + tig]);
                uint32_t b1 = __float_as_uint(Ks[(nf * 8 + gid) * KPAD + ks * 8 + tig + 4]);
                mma16n8k8(sacc[nf], aL.x, aH.x, aL.y, aH.y, b0, b1);
            }
        }

        // ---- online softmax (rows qb+gid, qb+gid+8)
        float mx0 = -1e30f, mx1 = -1e30f;
#pragma unroll
        for (int nf = 0; nf < 8; nf++) {
            sacc[nf][0] *= 0.125f; sacc[nf][1] *= 0.125f;
            sacc[nf][2] *= 0.125f; sacc[nf][3] *= 0.125f;
            mx0 = fmaxf(mx0, fmaxf(sacc[nf][0], sacc[nf][1]));
            mx1 = fmaxf(mx1, fmaxf(sacc[nf][2], sacc[nf][3]));
        }
        mx0 = fmaxf(mx0, __shfl_xor_sync(0xffffffff, mx0, 1));
        mx0 = fmaxf(mx0, __shfl_xor_sync(0xffffffff, mx0, 2));
        mx1 = fmaxf(mx1, __shfl_xor_sync(0xffffffff, mx1, 1));
        mx1 = fmaxf(mx1, __shfl_xor_sync(0xffffffff, mx1, 2));
        float mn0 = fmaxf(m0s, mx0), mn1 = fmaxf(m1s, mx1);
        float sc0 = __expf(m0s - mn0), sc1 = __expf(m1s - mn1);
        float sum0 = 0.f, sum1 = 0.f;
#pragma unroll
        for (int nf = 0; nf < 8; nf++) {
#pragma unroll
            for (int j = 0; j < 2; j++) {
                int cc = 2 * tig + j;
                int pc = nf * 4 + (cc & 3);
                int h  = cc >> 2;
                float p0 = __expf(sacc[nf][j]     - mn0);
                float p1 = __expf(sacc[nf][2 + j] - mn1);
                sum0 += p0; sum1 += p1;
                ((float*)&Ps2[pc * 130 + qb + gid])[h]     = tf32bits(p0);
                ((float*)&Ps2[pc * 130 + qb + gid + 8])[h] = tf32bits(p1);
            }
        }
        sum0 += __shfl_xor_sync(0xffffffff, sum0, 1);
        sum0 += __shfl_xor_sync(0xffffffff, sum0, 2);
        sum1 += __shfl_xor_sync(0xffffffff, sum1, 1);
        sum1 += __shfl_xor_sync(0xffffffff, sum1, 2);
        l0s = l0s * sc0 + sum0;  m0s = mn0;
        l1s = l1s * sc1 + sum1;  m1s = mn1;
#pragma unroll
        for (int nf = 0; nf < 8; nf++) {
            oacc[nf][0] *= sc0; oacc[nf][1] *= sc0;
            oacc[nf][2] *= sc1; oacc[nf][3] *= sc1;
        }
        __syncwarp();           // P visible across lanes of this warp

        // ---- O += P V (per-warp 16x64, k=64)
#pragma unroll
        for (int ks = 0; ks < 8; ks++) {
            int p = ks * 4 + tig;
            uint2 aL = *(const uint2*)&Ps2[p * 130 + qb + gid];
            uint2 aH = *(const uint2*)&Ps2[p * 130 + qb + gid + 8];
#pragma unroll
            for (int nf = 0; nf < 8; nf++) {
                uint32_t b0 = __float_as_uint(Vs[(ks * 8 + tig) * VPAD + nf * 8 + gid]);
                uint32_t b1 = __float_as_uint(Vs[(ks * 8 + tig + 4) * VPAD + nf * 8 + gid]);
                mma16n8k8(oacc[nf], aL.x, aH.x, aL.y, aH.y, b0, b1);
            }
        }
    }

    // ---- epilogue: normalize and store token-major
    {
        int b = bh >> 4, h = bh & 15;
        int r0 = q0 + qb + gid, r1 = r0 + 8;
        float inv0 = 1.0f / l0s, inv1 = 1.0f / l1s;
#pragma unroll
        for (int nf = 0; nf < 8; nf++) {
            int col = h * 64 + nf * 8 + 2 * tig;
            float2 o0 = { oacc[nf][0] * inv0, oacc[nf][1] * inv0 };
            float2 o1 = { oacc[nf][2] * inv1, oacc[nf][3] * inv1 };
            *(float2*)&AO[(size_t)(b * SEQ + r0) * CDIM + col] = o0;
            *(float2*)&AO[(size_t)(b * SEQ + r1) * CDIM + col] = o1;
        }
    }
}

// ---------------- attention map for query 0 (mean over heads) ---------------
__global__ void attn_map_kernel(const float* __restrict__ Q, const float* __restrict__ K,
                                float* __restrict__ omap)
{
    __shared__ float sc[SEQ];
    __shared__ float acc[SEQ];
    __shared__ float red[256];
    __shared__ float q0[HDIM];
    int b = blockIdx.x, tid = threadIdx.x;
    for (int i = tid; i < SEQ; i += 256) acc[i] = 0.f;
    for (int h = 0; h < NHEAD; h++) {
        const float* Qb = Q + ((size_t)(b*NHEAD + h) * SEQ) * HDIM;
        const float* Kb = K + ((size_t)(b*NHEAD + h) * SEQ) * HDIM;
        __syncthreads();
        if (tid < HDIM) q0[tid] = Qb[tid];
        __syncthreads();
        for (int m = tid; m < SEQ; m += 256) {
            float s = 0.f;
#pragma unroll 16
            for (int j = 0; j < HDIM; j++) s += q0[j] * Kb[(size_t)m*HDIM + j];
            sc[m] = s * 0.125f;
        }
        __syncthreads();
        float mx = -1e30f;
        for (int m = tid; m < SEQ; m += 256) mx = fmaxf(mx, sc[m]);
        red[tid] = mx; __syncthreads();
        for (int s = 128; s > 0; s >>= 1) { if (tid < s) red[tid] = fmaxf(red[tid], red[tid+s]); __syncthreads(); }
        mx = red[0]; __syncthreads();
        float sum = 0.f;
        for (int m = tid; m < SEQ; m += 256) { float p = __expf(sc[m] - mx); sc[m] = p; sum += p; }
        red[tid] = sum; __syncthreads();
        for (int s = 128; s > 0; s >>= 1) { if (tid < s) red[tid] += red[tid+s]; __syncthreads(); }
        float inv = 1.0f / red[0]; __syncthreads();
        for (int m = tid; m < SEQ; m += 256) acc[m] += sc[m] * inv;
    }
    __syncthreads();
    for (int m = tid; m < SEQ; m += 256)
        if (m >= 1) omap[(size_t)b*(SEQ-1) + m - 1] = acc[m] * (1.0f/NHEAD);
}

// ---------------- launch ----------------------------------------------------
extern "C" void kernel_launch(void* const* d_in, const int* in_sizes, int n_in,
                              void* d_out, int out_size)
{
    const float* x_list = (const float*)d_in[0];
    const float* w_     = (const float*)d_in[1];
    const float* qkv_w  = (const float*)d_in[2];
    const float* qkv_b  = (const float*)d_in[3];
    const float* proj_w = (const float*)d_in[4];
    const float* proj_b = (const float*)d_in[5];
    const float* nq_g   = (const float*)d_in[6];
    const float* nq_b   = (const float*)d_in[7];
    const float* nk_g   = (const float*)d_in[8];
    const float* nk_b   = (const float*)d_in[9];
    const float* conv_w = (const float*)d_in[10];
    const float* conv_b = (const float*)d_in[11];
    const float* ca1_w  = (const float*)d_in[12];
    const float* ca1_b  = (const float*)d_in[13];
    const float* ca2_w  = (const float*)d_in[14];
    const float* ca2_b  = (const float*)d_in[15];
    const float* mlp1_w = (const float*)d_in[16];
    const float* mlp1_b = (const float*)d_in[17];
    const float* mlp2_w = (const float*)d_in[18];
    const float* mlp2_b = (const float*)d_in[19];
    float* out = (float*)d_out;

    float *px, *pop0, *ph1, *pgate, *pmh, *pop3, *pxc, *pqkv, *pq, *pk, *pv, *pao;
    cudaGetSymbolAddress((void**)&px,   g_x);
    cudaGetSymbolAddress((void**)&pop0, g_op0);
    cudaGetSymbolAddress((void**)&ph1,  g_h1);
    cudaGetSymbolAddress((void**)&pgate,g_gate);
    cudaGetSymbolAddress((void**)&pmh,  g_mh);
    cudaGetSymbolAddress((void**)&pop3, g_op3);
    cudaGetSymbolAddress((void**)&pxc,  g_xc);
    cudaGetSymbolAddress((void**)&pqkv, g_qkv);
    cudaGetSymbolAddress((void**)&pq,   g_q);
    cudaGetSymbolAddress((void**)&pk,   g_k);
    cudaGetSymbolAddress((void**)&pv,   g_v);
    cudaGetSymbolAddress((void**)&pao,  g_ao);

    const int NE = TOK * CDIM;

    extract_x<<<(NE + 255)/256, 256>>>(x_list, px);

    // op0 = gelu(x @ conv_w^T + conv_b)
    gemm_mma<EPI_GELU><<<dim3(CDIM/128, TOK/128), 256>>>(
        px, conv_w, conv_b, nullptr, pop0, TOK, CDIM, CDIM);
    // h1 = relu(x @ ca1_w^T + ca1_b)   [4096,64]
    gemm_nt<32,64,16,2,4,EPI_RELU><<<dim3(1, TOK/32), 256>>>(
        px, ca1_w, ca1_b, nullptr, ph1, TOK, 64, CDIM);
    // gate = sigmoid(h1 @ ca2_w^T + ca2_b)  (K=64)
    gemm_mma<EPI_SIGM><<<dim3(CDIM/128, TOK/128), 256>>>(
        ph1, ca2_w, ca2_b, nullptr, pgate, TOK, CDIM, 64);
    // mh = gelu(x @ mlp1_w^T + mlp1_b)  [4096,4096]
    gemm_mma<EPI_GELU><<<dim3(CHID/128, TOK/128), 256>>>(
        px, mlp1_w, mlp1_b, nullptr, pmh, TOK, CHID, CDIM);
    // op3 = mh @ mlp2_w^T + mlp2_b   (K=4096)
    gemm_mma<EPI_NONE><<<dim3(CDIM/128, TOK/128), 256>>>(
        pmh, mlp2_w, mlp2_b, nullptr, pop3, TOK, CDIM, CHID);

    combine<<<(NE + 255)/256, 256>>>(x_list, w_, pop0, pgate, pop3, pxc);

    // qkv = xc @ qkv_w^T + qkv_b   [4096,3072]
    gemm_mma<EPI_NONE><<<dim3(3*CDIM/128, TOK/128), 256>>>(
        pxc, qkv_w, qkv_b, nullptr, pqkv, TOK, 3*CDIM, CDIM);

    ln_split<<<(TOK*NHEAD*32 + 255)/256, 256>>>(pqkv, nq_g, nq_b, nk_g, nk_b, pq, pk, pv);

    cudaFuncSetAttribute(attn_mma, cudaFuncAttributeMaxDynamicSharedMemorySize, ATT_SMEM);
    attn_mma<<<dim3(SEQ/128, NB*NHEAD), 256, ATT_SMEM>>>(pq, pk, pv, pao);

    attn_map_kernel<<<NB, 256>>>(pq, pk, out + (size_t)TOK * CDIM);

    // out = ao @ proj_w^T + proj_b + xc
    gemm_mma<EPI_RES><<<dim3(CDIM/128, TOK/128), 256>>>(
        pao, proj_w, proj_b, pxc, out, TOK, CDIM, CDIM);
}

// round 7
// speedup vs baseline: 3.3892x; 1.0296x over previous
#include <cuda_runtime.h>
#include <math.h>
#include <stdint.h>

// Problem constants
#define TOK   4096          // b*l tokens
#define CDIM  1024
#define CHID  4096          // mlp hidden
#define NHEAD 16
#define HDIM  64
#define NB    4
#define SEQ   1024

// ---------------- scratch (device globals; no allocation allowed) ----------
__device__ float g_x   [TOK * CDIM];        // paired+rounded x
__device__ float g_op0 [TOK * CDIM];        // normal (combine input)
__device__ float g_h1p [TOK * 64];          // paired+rounded
__device__ float g_gate[TOK * CDIM];        // normal
__device__ float g_mhp [TOK * CHID];        // paired+rounded
__device__ float g_op3 [TOK * CDIM];        // normal
__device__ float g_xc  [TOK * CDIM];        // normal rounded (residual)
__device__ float g_xcp [TOK * CDIM];        // paired rounded (qkv A)
__device__ float g_qkv [TOK * 3 * CDIM];
__device__ float g_q   [TOK * CDIM];
__device__ float g_k   [TOK * CDIM];
__device__ float g_v   [TOK * CDIM];
__device__ float g_aop [TOK * CDIM];        // paired+rounded attention out
// pre-rounded + paired weights
__device__ float g_wpk  [(CDIM + CHID) * CDIM];   // [conv_w; mlp1_w]
__device__ float g_bpk  [CDIM + CHID];
__device__ float g_qkvw [3 * CDIM * CDIM];
__device__ float g_projw[CDIM * CDIM];
__device__ float g_mlp2w[CDIM * CHID];
__device__ float g_ca2w [CDIM * 64];
__device__ float g_ca1w [64 * CDIM];

// ---------------- epilogues -------------------------------------------------
#define EPI_NONE 0
#define EPI_GELU 1
#define EPI_RELU 2
#define EPI_SIGM 3
#define EPI_RES  4

__device__ __forceinline__ float gelu_exact(float v) {
    return 0.5f * v * (1.0f + erff(v * 0.70710678118654752f));
}
__device__ __forceinline__ uint32_t f2tf32(float x) {
    uint32_t u; asm("cvt.rn.tf32.f32 %0, %1;" : "=r"(u) : "f"(x)); return u;
}
__device__ __forceinline__ float tf32bits(float x) { return __uint_as_float(f2tf32(x)); }

// octet-local pair permutation of the K index: k -> 2*(k%4) + (k/4)%2
__device__ __forceinline__ size_t ppf(size_t i) {
    return (i & ~(size_t)7) | (((i & 3) << 1) | ((i >> 2) & 1));
}
__device__ __forceinline__ uint32_t smem_to_u32(const void* p) {
    uint32_t a;
    asm("{ .reg .u64 t; cvta.to.shared.u64 t, %1; cvt.u32.u64 %0, t; }" : "=r"(a) : "l"(p));
    return a;
}
__device__ __forceinline__ void mma16n8k8(float acc[4],
                                          uint32_t a0, uint32_t a1, uint32_t a2, uint32_t a3,
                                          uint32_t b0, uint32_t b1) {
    asm volatile(
        "mma.sync.aligned.m16n8k8.row.col.f32.tf32.tf32.f32 "
        "{%0,%1,%2,%3}, {%4,%5,%6,%7}, {%8,%9}, {%0,%1,%2,%3};\n"
        : "+f"(acc[0]), "+f"(acc[1]), "+f"(acc[2]), "+f"(acc[3])
        : "r"(a0), "r"(a1), "r"(a2), "r"(a3), "r"(b0), "r"(b1));
}

// =========== cp.async tf32 GEMM. A/W pre-rounded tf32 + K-paired. ===========
// CTA 128x128, BK=16, 5-stage cp.async ring, 8 warps (2x4), warp tile 64x32.
#define GST 5
#define BKC 16
#define APITCH 20
#define TILEF (128 * APITCH)
#define CASMEM (GST * 2 * TILEF * 4)

template<int EPI, int PACK>
__global__ __launch_bounds__(256, 2)
void gemm_ca(const float* __restrict__ A, const float* __restrict__ W,
             const float* __restrict__ bias, const float* __restrict__ res,
             float* __restrict__ Out, float* __restrict__ Out2,
             int M, int N, int K, int lda)
{
    extern __shared__ float smem[];
    const uint32_t abase = smem_to_u32(smem);
    const uint32_t wbase = abase + GST * TILEF * 4;

    const int tid = threadIdx.x;
    const int lane = tid & 31, wid = tid >> 5;
    const int gid = lane >> 2, tig = lane & 3;
    const int m0 = blockIdx.y * 128, n0 = blockIdx.x * 128;
    const int mb = (wid >> 2) * 64, nb = (wid & 3) * 32;

    const int nchunk = K >> 4;

    auto issue = [&](int c) {
        const int st = c % GST;
        const int k0 = c * BKC;
        const uint32_t sA = abase + st * TILEF * 4;
        const uint32_t sW = wbase + st * TILEF * 4;
#pragma unroll
        for (int i = 0; i < 2; i++) {
            int u = tid + i * 256;
            int row = u >> 2, q = u & 3;
            const float* ga = A + (size_t)(m0 + row) * lda + k0 + q * 4;
            asm volatile("cp.async.cg.shared.global [%0], [%1], 16;"
                         :: "r"(sA + (uint32_t)(row * APITCH + q * 4) * 4), "l"(ga));
            const float* gw = W + (size_t)(n0 + row) * K + k0 + q * 4;
            asm volatile("cp.async.cg.shared.global [%0], [%1], 16;"
                         :: "r"(sW + (uint32_t)(row * APITCH + q * 4) * 4), "l"(gw));
        }
        asm volatile("cp.async.commit_group;" ::: "memory");
    };

    float acc[4][4][4];
#pragma unroll
    for (int mf = 0; mf < 4; mf++)
#pragma unroll
        for (int nf = 0; nf < 4; nf++)
#pragma unroll
            for (int i = 0; i < 4; i++) acc[mf][nf][i] = 0.f;

    for (int c = 0; c < 4 && c < nchunk; c++) issue(c);
    for (int c = nchunk; c < 4; c++)
        asm volatile("cp.async.commit_group;" ::: "memory");

    for (int c = 0; c < nchunk; c++) {
        asm volatile("cp.async.wait_group 3;" ::: "memory");
        __syncthreads();
        if (c + 4 < nchunk) issue(c + 4);
        else asm volatile("cp.async.commit_group;" ::: "memory");

        const float* Ac = smem + (c % GST) * TILEF;
        const float* Wc = smem + (GST + (c % GST)) * TILEF;
#pragma unroll
        for (int ks = 0; ks < 2; ks++) {
            const int kb = ks * 8 + tig * 2;
            float2 bf[4];
#pragma unroll
            for (int nf = 0; nf < 4; nf++)
                bf[nf] = *(const float2*)&Wc[(nb + nf * 8 + gid) * APITCH + kb];
#pragma unroll
            for (int mf = 0; mf < 4; mf++) {
                float2 alo = *(const float2*)&Ac[(mb + mf * 16 + gid) * APITCH + kb];
                float2 ahi = *(const float2*)&Ac[(mb + mf * 16 + 8 + gid) * APITCH + kb];
#pragma unroll
                for (int nf = 0; nf < 4; nf++)
                    mma16n8k8(acc[mf][nf],
                              __float_as_uint(alo.x), __float_as_uint(ahi.x),
                              __float_as_uint(alo.y), __float_as_uint(ahi.y),
                              __float_as_uint(bf[nf].x), __float_as_uint(bf[nf].y));
            }
        }
    }

    // ---- epilogue
#pragma unroll
    for (int mf = 0; mf < 4; mf++) {
        const int row0 = m0 + mb + mf * 16 + gid;
        const int row1 = row0 + 8;
#pragma unroll
        for (int nf = 0; nf < 4; nf++) {
            const int col = n0 + nb + nf * 8 + 2 * tig;
            float2 b2 = *(const float2*)&bias[col];
            float v0 = acc[mf][nf][0] + b2.x;
            float v1 = acc[mf][nf][1] + b2.y;
            float v2 = acc[mf][nf][2] + b2.x;
            float v3 = acc[mf][nf][3] + b2.y;
            if (PACK || EPI == EPI_GELU) {
                v0 = gelu_exact(v0); v1 = gelu_exact(v1);
                v2 = gelu_exact(v2); v3 = gelu_exact(v3);
            } else if (EPI == EPI_SIGM) {
                v0 = 1.f/(1.f+__expf(-v0)); v1 = 1.f/(1.f+__expf(-v1));
                v2 = 1.f/(1.f+__expf(-v2)); v3 = 1.f/(1.f+__expf(-v3));
            } else if (EPI == EPI_RES) {
                float2 r0 = *(const float2*)&res[(size_t)row0 * N + col];
                float2 r1 = *(const float2*)&res[(size_t)row1 * N + col];
                v0 += r0.x; v1 += r0.y; v2 += r1.x; v3 += r1.y;
            }
            if (PACK) {
                if (n0 < CDIM) {          // op0 region: normal layout, rounded
                    float2 o0 = { tf32bits(v0), tf32bits(v1) };
                    float2 o1 = { tf32bits(v2), tf32bits(v3) };
                    *(float2*)&Out[(size_t)row0 * CDIM + col] = o0;
                    *(float2*)&Out[(size_t)row1 * CDIM + col] = o1;
                } else {                  // mh region: paired + rounded
                    int cm = col - CDIM;
                    Out2[ppf((size_t)row0 * CHID + cm)]     = tf32bits(v0);
                    Out2[ppf((size_t)row0 * CHID + cm + 1)] = tf32bits(v1);
                    Out2[ppf((size_t)row1 * CHID + cm)]     = tf32bits(v2);
                    Out2[ppf((size_t)row1 * CHID + cm + 1)] = tf32bits(v3);
                }
            } else {
                float2 o0 = {v0, v1}, o1 = {v2, v3};
                *(float2*)&Out[(size_t)row0 * N + col] = o0;
                *(float2*)&Out[(size_t)row1 * N + col] = o1;
            }
        }
    }
}

// ---------------- fp32 GEMM for tiny ca1 (output paired+rounded) ------------
template<int BM, int BN, int BK, int TM, int TN>
__global__ __launch_bounds__((BM/TM)*(BN/TN))
void gemm_nt_relu(const float* __restrict__ A, const float* __restrict__ W,
                  const float* __restrict__ bias, float* __restrict__ Out,
                  int M, int N, int K)
{
    constexpr int NT = (BM/TM)*(BN/TN);
    __shared__ float As[BK][BM + 4];
    __shared__ float Ws[BK][BN + 4];

    const int tid = threadIdx.x;
    const int m0 = blockIdx.y * BM;
    const int n0 = blockIdx.x * BN;
    const int tx = tid % (BN / TN);
    const int ty = tid / (BN / TN);

    float acc[TM][TN];
#pragma unroll
    for (int i = 0; i < TM; i++)
#pragma unroll
        for (int j = 0; j < TN; j++) acc[i][j] = 0.f;

    for (int k0 = 0; k0 < K; k0 += BK) {
#pragma unroll
        for (int i = tid; i < BM*BK/4; i += NT) {
            int r = i / (BK/4), cg = i % (BK/4);
            float4 v = *(const float4*)&A[(size_t)(m0 + r) * K + k0 + cg*4];
            As[cg*4+0][r] = v.x; As[cg*4+1][r] = v.y;
            As[cg*4+2][r] = v.z; As[cg*4+3][r] = v.w;
        }
#pragma unroll
        for (int i = tid; i < BN*BK/4; i += NT) {
            int r = i / (BK/4), cg = i % (BK/4);
            float4 v = *(const float4*)&W[(size_t)(n0 + r) * K + k0 + cg*4];
            Ws[cg*4+0][r] = v.x; Ws[cg*4+1][r] = v.y;
            Ws[cg*4+2][r] = v.z; Ws[cg*4+3][r] = v.w;
        }
        __syncthreads();
#pragma unroll
        for (int k = 0; k < BK; k++) {
            float a[TM], b[TN];
#pragma unroll
            for (int i = 0; i < TM; i++) a[i] = As[k][ty*TM + i];
#pragma unroll
            for (int j = 0; j < TN; j++) b[j] = Ws[k][tx*TN + j];
#pragma unroll
            for (int i = 0; i < TM; i++)
#pragma unroll
                for (int j = 0; j < TN; j++) acc[i][j] += a[i] * b[j];
        }
        __syncthreads();
    }

#pragma unroll
    for (int i = 0; i < TM; i++) {
        int m = m0 + ty*TM + i;
#pragma unroll
        for (int j = 0; j < TN; j++) {
            int n = n0 + tx*TN + j;
            float v = fmaxf(acc[i][j] + bias[n], 0.f);
            Out[ppf((size_t)m * N + n)] = tf32bits(v);
        }
    }
}

// ---------------- pack kernels ----------------------------------------------
__global__ void pack_pair_round(float* __restrict__ dst, const float* __restrict__ src, int n)
{
    int i = blockIdx.x * blockDim.x + threadIdx.x;
    if (i < n) dst[ppf((size_t)i)] = tf32bits(src[i]);
}
__global__ void pack_bias(float* __restrict__ dst, const float* __restrict__ b0,
                          const float* __restrict__ b1)
{
    int i = blockIdx.x * blockDim.x + threadIdx.x;
    if (i < CDIM + CHID) dst[i] = (i < CDIM) ? b0[i] : b1[i - CDIM];
}

// ---------------- extract x = x_list[...,-1] (paired + rounded) -------------
__global__ void extract_x(const float* __restrict__ x_list, float* __restrict__ x)
{
    int i = blockIdx.x * blockDim.x + threadIdx.x;
    if (i < TOK * CDIM) x[ppf((size_t)i)] = tf32bits(x_list[2*i + 1]);
}

// ---------------- combine: softmax(w_/T) weighted mix -----------------------
__global__ void combine(const float* __restrict__ x_list,
                        const float* __restrict__ w_,
                        const float* __restrict__ op0,
                        const float* __restrict__ gate,
                        const float* __restrict__ op3,
                        float* __restrict__ xc, float* __restrict__ xcp)
{
    float w[6], mx = -1e30f;
#pragma unroll
    for (int i = 0; i < 6; i++) { w[i] = w_[i] * 100.0f; mx = fmaxf(mx, w[i]); }
    float s = 0.f;
#pragma unroll
    for (int i = 0; i < 6; i++) { w[i] = __expf(w[i] - mx); s += w[i]; }
    float inv = 1.0f / s;
#pragma unroll
    for (int i = 0; i < 6; i++) w[i] *= inv;

    int i = blockIdx.x * blockDim.x + threadIdx.x;
    if (i >= TOK * CDIM) return;
    float xl0 = x_list[2*i];
    float xv  = x_list[2*i + 1];
    float v = w[0]*xl0 + (w[1] + w[4])*xv + w[2]*op0[i] + w[3]*(gate[i]*xv) + w[5]*op3[i];
    v = tf32bits(v);
    xc[i] = v;
    xcp[ppf((size_t)i)] = v;
}

// ---------------- qkv split + per-head LN + head-major transpose ------------
__global__ void ln_split(const float* __restrict__ qkv,
                         const float* __restrict__ nqg, const float* __restrict__ nqb,
                         const float* __restrict__ nkg, const float* __restrict__ nkb,
                         float* __restrict__ Qo, float* __restrict__ Ko, float* __restrict__ Vo)
{
    int gw = (blockIdx.x * blockDim.x + threadIdx.x) >> 5;
    int lane = threadIdx.x & 31;
    if (gw >= TOK * NHEAD) return;
    int t = gw / NHEAD, h = gw % NHEAD;
    int b = t / SEQ, n = t % SEQ;
    size_t src = (size_t)t * (3*CDIM) + h * HDIM;
    size_t dst = ((size_t)(b*NHEAD + h) * SEQ + n) * HDIM;

#pragma unroll
    for (int which = 0; which < 2; which++) {
        size_t so = src + (which ? CDIM : 0);
        float2 xv = *(const float2*)&qkv[so + lane*2];
        float sum = xv.x + xv.y;
        float ssq = xv.x*xv.x + xv.y*xv.y;
#pragma unroll
        for (int o = 16; o > 0; o >>= 1) {
            sum += __shfl_xor_sync(0xffffffff, sum, o);
            ssq += __shfl_xor_sync(0xffffffff, ssq, o);
        }
        float mean = sum * (1.0f/64.0f);
        float var  = ssq * (1.0f/64.0f) - mean*mean;
        float inv  = rsqrtf(var + 1e-5f);
        const float* g = which ? nkg : nqg;
        const float* bb = which ? nkb : nqb;
        float* O = which ? Ko : Qo;
        O[dst + lane*2 + 0] = (xv.x - mean)*inv*g[lane*2+0] + bb[lane*2+0];
        O[dst + lane*2 + 1] = (xv.y - mean)*inv*g[lane*2+1] + bb[lane*2+1];
    }
    *(float2*)&Vo[dst + lane*2] = *(const float2*)&qkv[src + 2*CDIM + lane*2];
}

// ---------------- tf32 MMA flash attention (epilogue: paired+rounded) -------
#define KPAD 68
#define VPAD 72
#define QS_F2   (32*130)
#define KS_F    (64*KPAD)
#define VS_F    (64*VPAD)
#define ATT_SMEM ((QS_F2*2 + KS_F + VS_F + QS_F2*2) * 4)

__global__ __launch_bounds__(256, 2)
void attn_mma(const float* __restrict__ Q, const float* __restrict__ K,
              const float* __restrict__ V, float* __restrict__ AO)
{
    extern __shared__ float sma[];
    float2* Qs2 = (float2*)sma;
    float*  Ks  = sma + QS_F2*2;
    float*  Vs  = Ks + KS_F;
    float2* Ps2 = (float2*)(Vs + VS_F);

    const int tid = threadIdx.x;
    const int lane = tid & 31, wid = tid >> 5;
    const int gid = lane >> 2, tig = lane & 3;
    const int q0 = blockIdx.x * 128;
    const int bh = blockIdx.y;
    const int qb = wid * 16;
    const float* Qb = Q + (size_t)bh * SEQ * HDIM;
    const float* Kb = K + (size_t)bh * SEQ * HDIM;
    const float* Vb = V + (size_t)bh * SEQ * HDIM;

    {
        int r = tid >> 1, hf = tid & 1;
#pragma unroll
        for (int i = 0; i < 8; i++) {
            int k0 = hf * 32 + i * 4;
            float4 v = *(const float4*)&Qb[(size_t)(q0 + r) * HDIM + k0];
            int p0 = (k0 >> 3) * 4;
            int h  = (k0 & 4) >> 2;
            ((float*)&Qs2[(p0 + 0) * 130 + r])[h] = tf32bits(v.x);
            ((float*)&Qs2[(p0 + 1) * 130 + r])[h] = tf32bits(v.y);
            ((float*)&Qs2[(p0 + 2) * 130 + r])[h] = tf32bits(v.z);
            ((float*)&Qs2[(p0 + 3) * 130 + r])[h] = tf32bits(v.w);
        }
    }

    float oacc[8][4];
#pragma unroll
    for (int nf = 0; nf < 8; nf++)
#pragma unroll
        for (int i = 0; i < 4; i++) oacc[nf][i] = 0.f;
    float m0s = -1e30f, m1s = -1e30f, l0s = 0.f, l1s = 0.f;

    for (int kt = 0; kt < 16; kt++) {
        __syncthreads();
        {
            int j = tid >> 2, f = tid & 3;
            int rowg = kt * 64 + j;
#pragma unroll
            for (int i = 0; i < 4; i++) {
                int d0 = f * 16 + i * 4;
                float4 kv = *(const float4*)&Kb[(size_t)rowg * HDIM + d0];
                float4 vv = *(const float4*)&Vb[(size_t)rowg * HDIM + d0];
                float4 kc = { tf32bits(kv.x), tf32bits(kv.y), tf32bits(kv.z), tf32bits(kv.w) };
                float4 vc = { tf32bits(vv.x), tf32bits(vv.y), tf32bits(vv.z), tf32bits(vv.w) };
                *(float4*)&Ks[j * KPAD + d0] = kc;
                *(float4*)&Vs[j * VPAD + d0] = vc;
            }
        }
        __syncthreads();

        float sacc[8][4];
#pragma unroll
        for (int nf = 0; nf < 8; nf++)
#pragma unroll
            for (int i = 0; i < 4; i++) sacc[nf][i] = 0.f;
#pragma unroll
        for (int ks = 0; ks < 8; ks++) {
            int p = ks * 4 + tig;
            uint2 aL = *(const uint2*)&Qs2[p * 130 + qb + gid];
            uint2 aH = *(const uint2*)&Qs2[p * 130 + qb + gid + 8];
#pragma unroll
            for (int nf = 0; nf < 8; nf++) {
                uint32_t b0 = __float_as_uint(Ks[(nf * 8 + gid) * KPAD + ks * 8 + tig]);
                uint32_t b1 = __float_as_uint(Ks[(nf * 8 + gid) * KPAD + ks * 8 + tig + 4]);
                mma16n8k8(sacc[nf], aL.x, aH.x, aL.y, aH.y, b0, b1);
            }
        }

        float mx0 = -1e30f, mx1 = -1e30f;
#pragma unroll
        for (int nf = 0; nf < 8; nf++) {
            sacc[nf][0] *= 0.125f; sacc[nf][1] *= 0.125f;
            sacc[nf][2] *= 0.125f; sacc[nf][3] *= 0.125f;
            mx0 = fmaxf(mx0, fmaxf(sacc[nf][0], sacc[nf][1]));
            mx1 = fmaxf(mx1, fmaxf(sacc[nf][2], sacc[nf][3]));
        }
        mx0 = fmaxf(mx0, __shfl_xor_sync(0xffffffff, mx0, 1));
        mx0 = fmaxf(mx0, __shfl_xor_sync(0xffffffff, mx0, 2));
        mx1 = fmaxf(mx1, __shfl_xor_sync(0xffffffff, mx1, 1));
        mx1 = fmaxf(mx1, __shfl_xor_sync(0xffffffff, mx1, 2));
        float mn0 = fmaxf(m0s, mx0), mn1 = fmaxf(m1s, mx1);
        float sc0 = __expf(m0s - mn0), sc1 = __expf(m1s - mn1);
        float sum0 = 0.f, sum1 = 0.f;
#pragma unroll
        for (int nf = 0; nf < 8; nf++) {
#pragma unroll
            for (int j = 0; j < 2; j++) {
                int cc = 2 * tig + j;
                int pc = nf * 4 + (cc & 3);
                int h  = cc >> 2;
                float p0 = __expf(sacc[nf][j]     - mn0);
                float p1 = __expf(sacc[nf][2 + j] - mn1);
                sum0 += p0; sum1 += p1;
                ((float*)&Ps2[pc * 130 + qb + gid])[h]     = tf32bits(p0);
                ((float*)&Ps2[pc * 130 + qb + gid + 8])[h] = tf32bits(p1);
            }
        }
        sum0 += __shfl_xor_sync(0xffffffff, sum0, 1);
        sum0 += __shfl_xor_sync(0xffffffff, sum0, 2);
        sum1 += __shfl_xor_sync(0xffffffff, sum1, 1);
        sum1 += __shfl_xor_sync(0xffffffff, sum1, 2);
        l0s = l0s * sc0 + sum0;  m0s = mn0;
        l1s = l1s * sc1 + sum1;  m1s = mn1;
#pragma unroll
        for (int nf = 0; nf < 8; nf++) {
            oacc[nf][0] *= sc0; oacc[nf][1] *= sc0;
            oacc[nf][2] *= sc1; oacc[nf][3] *= sc1;
        }
        __syncwarp();

#pragma unroll
        for (int ks = 0; ks < 8; ks++) {
            int p = ks * 4 + tig;
            uint2 aL = *(const uint2*)&Ps2[p * 130 + qb + gid];
            uint2 aH = *(const uint2*)&Ps2[p * 130 + qb + gid + 8];
#pragma unroll
            for (int nf = 0; nf < 8; nf++) {
                uint32_t b0 = __float_as_uint(Vs[(ks * 8 + tig) * VPAD + nf * 8 + gid]);
                uint32_t b1 = __float_as_uint(Vs[(ks * 8 + tig + 4) * VPAD + nf * 8 + gid]);
                mma16n8k8(oacc[nf], aL.x, aH.x, aL.y, aH.y, b0, b1);
            }
        }
    }

    // epilogue: normalize, round, store paired token-major (proj A input)
    {
        int b = bh >> 4, h = bh & 15;
        int r0 = q0 + qb + gid, r1 = r0 + 8;
        float inv0 = 1.0f / l0s, inv1 = 1.0f / l1s;
        size_t base0 = (size_t)(b * SEQ + r0) * CDIM;
        size_t base1 = (size_t)(b * SEQ + r1) * CDIM;
#pragma unroll
        for (int nf = 0; nf < 8; nf++) {
            int col = h * 64 + nf * 8 + 2 * tig;
            AO[base0 + ppf((size_t)col)]     = tf32bits(oacc[nf][0] * inv0);
            AO[base0 + ppf((size_t)col + 1)] = tf32bits(oacc[nf][1] * inv0);
            AO[base1 + ppf((size_t)col)]     = tf32bits(oacc[nf][2] * inv1);
            AO[base1 + ppf((size_t)col + 1)] = tf32bits(oacc[nf][3] * inv1);
        }
    }
}

// ---------------- attention map for query 0 (mean over heads) ---------------
__global__ void attn_map_kernel(const float* __restrict__ Q, const float* __restrict__ K,
                                float* __restrict__ omap)
{
    __shared__ float sc[SEQ];
    __shared__ float acc[SEQ];
    __shared__ float red[256];
    __shared__ float q0[HDIM];
    int b = blockIdx.x, tid = threadIdx.x;
    for (int i = tid; i < SEQ; i += 256) acc[i] = 0.f;
    for (int h = 0; h < NHEAD; h++) {
        const float* Qb = Q + ((size_t)(b*NHEAD + h) * SEQ) * HDIM;
        const float* Kb = K + ((size_t)(b*NHEAD + h) * SEQ) * HDIM;
        __syncthreads();
        if (tid < HDIM) q0[tid] = Qb[tid];
        __syncthreads();
        for (int m = tid; m < SEQ; m += 256) {
            float s = 0.f;
#pragma unroll 16
            for (int j = 0; j < HDIM; j++) s += q0[j] * Kb[(size_t)m*HDIM + j];
            sc[m] = s * 0.125f;
        }
        __syncthreads();
        float mx = -1e30f;
        for (int m = tid; m < SEQ; m += 256) mx = fmaxf(mx, sc[m]);
        red[tid] = mx; __syncthreads();
        for (int s = 128; s > 0; s >>= 1) { if (tid < s) red[tid] = fmaxf(red[tid], red[tid+s]); __syncthreads(); }
        mx = red[0]; __syncthreads();
        float sum = 0.f;
        for (int m = tid; m < SEQ; m += 256) { float p = __expf(sc[m] - mx); sc[m] = p; sum += p; }
        red[tid] = sum; __syncthreads();
        for (int s = 128; s > 0; s >>= 1) { if (tid < s) red[tid] += red[tid+s]; __syncthreads(); }
        float inv = 1.0f / red[0]; __syncthreads();
        for (int m = tid; m < SEQ; m += 256) acc[m] += sc[m] * inv;
    }
    __syncthreads();
    for (int m = tid; m < SEQ; m += 256)
        if (m >= 1) omap[(size_t)b*(SEQ-1) + m - 1] = acc[m] * (1.0f/NHEAD);
}

// ---------------- launch ----------------------------------------------------
extern "C" void kernel_launch(void* const* d_in, const int* in_sizes, int n_in,
                              void* d_out, int out_size)
{
    const float* x_list = (const float*)d_in[0];
    const float* w_     = (const float*)d_in[1];
    const float* qkv_w  = (const float*)d_in[2];
    const float* qkv_b  = (const float*)d_in[3];
    const float* proj_w = (const float*)d_in[4];
    const float* proj_b = (const float*)d_in[5];
    const float* nq_g   = (const float*)d_in[6];
    const float* nq_b   = (const float*)d_in[7];
    const float* nk_g   = (const float*)d_in[8];
    const float* nk_b   = (const float*)d_in[9];
    const float* conv_w = (const float*)d_in[10];
    const float* conv_b = (const float*)d_in[11];
    const float* ca1_w  = (const float*)d_in[12];
    const float* ca1_b  = (const float*)d_in[13];
    const float* ca2_w  = (const float*)d_in[14];
    const float* ca2_b  = (const float*)d_in[15];
    const float* mlp1_w = (const float*)d_in[16];
    const float* mlp1_b = (const float*)d_in[17];
    const float* mlp2_w = (const float*)d_in[18];
    const float* mlp2_b = (const float*)d_in[19];
    float* out = (float*)d_out;

    float *px, *pop0, *ph1p, *pgate, *pmhp, *pop3, *pxc, *pxcp, *pqkv, *pq, *pk, *pv, *paop;
    float *pwpk, *pbpk, *pqkvw, *pprojw, *pmlp2w, *pca2w, *pca1w;
    cudaGetSymbolAddress((void**)&px,    g_x);
    cudaGetSymbolAddress((void**)&pop0,  g_op0);
    cudaGetSymbolAddress((void**)&ph1p,  g_h1p);
    cudaGetSymbolAddress((void**)&pgate, g_gate);
    cudaGetSymbolAddress((void**)&pmhp,  g_mhp);
    cudaGetSymbolAddress((void**)&pop3,  g_op3);
    cudaGetSymbolAddress((void**)&pxc,   g_xc);
    cudaGetSymbolAddress((void**)&pxcp,  g_xcp);
    cudaGetSymbolAddress((void**)&pqkv,  g_qkv);
    cudaGetSymbolAddress((void**)&pq,    g_q);
    cudaGetSymbolAddress((void**)&pk,    g_k);
    cudaGetSymbolAddress((void**)&pv,    g_v);
    cudaGetSymbolAddress((void**)&paop,  g_aop);
    cudaGetSymbolAddress((void**)&pwpk,  g_wpk);
    cudaGetSymbolAddress((void**)&pbpk,  g_bpk);
    cudaGetSymbolAddress((void**)&pqkvw, g_qkvw);
    cudaGetSymbolAddress((void**)&pprojw,g_projw);
    cudaGetSymbolAddress((void**)&pmlp2w,g_mlp2w);
    cudaGetSymbolAddress((void**)&pca2w, g_ca2w);
    cudaGetSymbolAddress((void**)&pca1w, g_ca1w);

    const int NE = TOK * CDIM;

    cudaFuncSetAttribute(gemm_ca<EPI_GELU,1>, cudaFuncAttributeMaxDynamicSharedMemorySize, CASMEM);
    cudaFuncSetAttribute(gemm_ca<EPI_SIGM,0>, cudaFuncAttributeMaxDynamicSharedMemorySize, CASMEM);
    cudaFuncSetAttribute(gemm_ca<EPI_NONE,0>, cudaFuncAttributeMaxDynamicSharedMemorySize, CASMEM);
    cudaFuncSetAttribute(gemm_ca<EPI_RES,0>,  cudaFuncAttributeMaxDynamicSharedMemorySize, CASMEM);
    cudaFuncSetAttribute(attn_mma, cudaFuncAttributeMaxDynamicSharedMemorySize, ATT_SMEM);

    // ---- weight pre-round + pair packs
    pack_pair_round<<<(CDIM*CDIM+255)/256, 256>>>(pwpk, conv_w, CDIM*CDIM);
    pack_pair_round<<<(CHID*CDIM+255)/256, 256>>>(pwpk + CDIM*CDIM, mlp1_w, CHID*CDIM);
    pack_pair_round<<<(3*CDIM*CDIM+255)/256, 256>>>(pqkvw, qkv_w, 3*CDIM*CDIM);
    pack_pair_round<<<(CDIM*CDIM+255)/256, 256>>>(pprojw, proj_w, CDIM*CDIM);
    pack_pair_round<<<(CDIM*CHID+255)/256, 256>>>(pmlp2w, mlp2_w, CDIM*CHID);
    pack_pair_round<<<(CDIM*64+255)/256, 256>>>(pca2w, ca2_w, CDIM*64);
    pack_pair_round<<<(64*CDIM+255)/256, 256>>>(pca1w, ca1_w, 64*CDIM);
    pack_bias<<<(CDIM+CHID+255)/256, 256>>>(pbpk, conv_b, mlp1_b);

    extract_x<<<(NE + 255)/256, 256>>>(x_list, px);

    // packed conv+mlp1: op0 (normal) + mh (paired)
    gemm_ca<EPI_GELU,1><<<dim3((CDIM+CHID)/128, TOK/128), 256, CASMEM>>>(
        px, pwpk, pbpk, nullptr, pop0, pmhp, TOK, CDIM+CHID, CDIM, CDIM);
    // h1 = relu(x @ ca1_w^T + ca1_b), paired+rounded
    gemm_nt_relu<32,64,16,2,4><<<dim3(1, TOK/32), 256>>>(
        px, pca1w, ca1_b, ph1p, TOK, 64, CDIM);
    // gate = sigmoid(h1 @ ca2_w^T + ca2_b)
    gemm_ca<EPI_SIGM,0><<<dim3(CDIM/128, TOK/128), 256, CASMEM>>>(
        ph1p, pca2w, ca2_b, nullptr, pgate, nullptr, TOK, CDIM, 64, 64);
    // op3 = mh @ mlp2_w^T + mlp2_b
    gemm_ca<EPI_NONE,0><<<dim3(CDIM/128, TOK/128), 256, CASMEM>>>(
        pmhp, pmlp2w, mlp2_b, nullptr, pop3, nullptr, TOK, CDIM, CHID, CHID);

    combine<<<(NE + 255)/256, 256>>>(x_list, w_, pop0, pgate, pop3, pxc, pxcp);

    // qkv = xc @ qkv_w^T + qkv_b
    gemm_ca<EPI_NONE,0><<<dim3(3*CDIM/128, TOK/128), 256, CASMEM>>>(
        pxcp, pqkvw, qkv_b, nullptr, pqkv, nullptr, TOK, 3*CDIM, CDIM, CDIM);

    ln_split<<<(TOK*NHEAD*32 + 255)/256, 256>>>(pqkv, nq_g, nq_b, nk_g, nk_b, pq, pk, pv);

    attn_mma<<<dim3(SEQ/128, NB*NHEAD), 256, ATT_SMEM>>>(pq, pk, pv, paop);

    attn_map_kernel<<<NB, 256>>>(pq, pk, out + (size_t)TOK * CDIM);

    // out = ao @ proj_w^T + proj_b + xc
    gemm_ca<EPI_RES,0><<<dim3(CDIM/128, TOK/128), 256, CASMEM>>>(
        paop, pprojw, proj_b, pxc, out, nullptr, TOK, CDIM, CDIM, CDIM);
}

// round 8
// speedup vs baseline: 5.3025x; 1.5645x over previous
#include <cuda_runtime.h>
#include <math.h>
#include <stdint.h>

// Problem constants
#define TOK   4096          // b*l tokens
#define CDIM  1024
#define CHID  4096          // mlp hidden
#define NHEAD 16
#define HDIM  64
#define NB    4
#define SEQ   1024
#define WTHR  1e-7f         // branch-weight negligibility threshold

// ---------------- scratch (device globals; no allocation allowed) ----------
__device__ float g_x   [TOK * CDIM];        // paired+rounded x
__device__ float g_op0 [TOK * CDIM];
__device__ float g_h1p [TOK * 64];
__device__ float g_gate[TOK * CDIM];
__device__ float g_mhp [TOK * CHID];
__device__ float g_op3 [TOK * CDIM];
__device__ float g_xc  [TOK * CDIM];
__device__ float g_xcp [TOK * CDIM];
__device__ float g_qkv [TOK * 3 * CDIM];
__device__ float g_q   [TOK * CDIM];
__device__ float g_k   [TOK * CDIM];
__device__ float g_v   [TOK * CDIM];
__device__ float g_aop [TOK * CDIM];
// pre-rounded + paired weights
__device__ float g_wpk  [(CDIM + CHID) * CDIM];   // [conv_w; mlp1_w]
__device__ float g_bpk  [CDIM + CHID];
__device__ float g_qkvw [3 * CDIM * CDIM];
__device__ float g_projw[CDIM * CDIM];
__device__ float g_mlp2w[CDIM * CHID];
__device__ float g_ca2w [CDIM * 64];
__device__ float g_ca1w [64 * CDIM];

#define EPI_NONE 0
#define EPI_GELU 1
#define EPI_RELU 2
#define EPI_SIGM 3
#define EPI_RES  4

__device__ __forceinline__ float gelu_exact(float v) {
    return 0.5f * v * (1.0f + erff(v * 0.70710678118654752f));
}
__device__ __forceinline__ uint32_t f2tf32(float x) {
    uint32_t u; asm("cvt.rn.tf32.f32 %0, %1;" : "=r"(u) : "f"(x)); return u;
}
__device__ __forceinline__ float tf32bits(float x) { return __uint_as_float(f2tf32(x)); }

// softmax(w_*100) weight of branch idx (0..5)
__device__ __forceinline__ float bw6(const float* __restrict__ w_, int idx) {
    float w[6], mx = -1e30f;
#pragma unroll
    for (int i = 0; i < 6; i++) { w[i] = w_[i] * 100.0f; mx = fmaxf(mx, w[i]); }
    float s = 0.f;
#pragma unroll
    for (int i = 0; i < 6; i++) { w[i] = __expf(w[i] - mx); s += w[i]; }
    return w[idx] / s;
}

// octet-local pair permutation of the K index: k -> 2*(k%4) + (k/4)%2
__device__ __forceinline__ size_t ppf(size_t i) {
    return (i & ~(size_t)7) | (((i & 3) << 1) | ((i >> 2) & 1));
}
__device__ __forceinline__ uint32_t smem_to_u32(const void* p) {
    uint32_t a;
    asm("{ .reg .u64 t; cvta.to.shared.u64 t, %1; cvt.u32.u64 %0, t; }" : "=r"(a) : "l"(p));
    return a;
}
__device__ __forceinline__ void mma16n8k8(float acc[4],
                                          uint32_t a0, uint32_t a1, uint32_t a2, uint32_t a3,
                                          uint32_t b0, uint32_t b1) {
    asm volatile(
        "mma.sync.aligned.m16n8k8.row.col.f32.tf32.tf32.f32 "
        "{%0,%1,%2,%3}, {%4,%5,%6,%7}, {%8,%9}, {%0,%1,%2,%3};\n"
        : "+f"(acc[0]), "+f"(acc[1]), "+f"(acc[2]), "+f"(acc[3])
        : "r"(a0), "r"(a1), "r"(a2), "r"(a3), "r"(b0), "r"(b1));
}

// =========== cp.async tf32 GEMM. A/W pre-rounded tf32 + K-paired. ===========
#define GST 5
#define BKC 16
#define APITCH 20
#define TILEF (128 * APITCH)
#define CASMEM (GST * 2 * TILEF * 4)

template<int EPI, int PACK>
__global__ __launch_bounds__(256, 2)
void gemm_ca(const float* __restrict__ A, const float* __restrict__ W,
             const float* __restrict__ bias, const float* __restrict__ res,
             float* __restrict__ Out, float* __restrict__ Out2,
             int M, int N, int K, int lda,
             const float* __restrict__ gw, int gidx)
{
    const int m0 = blockIdx.y * 128, n0 = blockIdx.x * 128;
    if (gw) {
        int gi = PACK ? (n0 < CDIM ? 2 : 5) : gidx;
        if (bw6(gw, gi) < WTHR) return;
    }

    extern __shared__ float smem[];
    const uint32_t abase = smem_to_u32(smem);
    const uint32_t wbase = abase + GST * TILEF * 4;

    const int tid = threadIdx.x;
    const int lane = tid & 31, wid = tid >> 5;
    const int gid = lane >> 2, tig = lane & 3;
    const int mb = (wid >> 2) * 64, nb = (wid & 3) * 32;

    const int nchunk = K >> 4;

    auto issue = [&](int c) {
        const int st = c % GST;
        const int k0 = c * BKC;
        const uint32_t sA = abase + st * TILEF * 4;
        const uint32_t sW = wbase + st * TILEF * 4;
#pragma unroll
        for (int i = 0; i < 2; i++) {
            int u = tid + i * 256;
            int row = u >> 2, q = u & 3;
            const float* ga = A + (size_t)(m0 + row) * lda + k0 + q * 4;
            asm volatile("cp.async.cg.shared.global [%0], [%1], 16;"
                         :: "r"(sA + (uint32_t)(row * APITCH + q * 4) * 4), "l"(ga));
            const float* gwp = W + (size_t)(n0 + row) * K + k0 + q * 4;
            asm volatile("cp.async.cg.shared.global [%0], [%1], 16;"
                         :: "r"(sW + (uint32_t)(row * APITCH + q * 4) * 4), "l"(gwp));
        }
        asm volatile("cp.async.commit_group;" ::: "memory");
    };

    float acc[4][4][4];
#pragma unroll
    for (int mf = 0; mf < 4; mf++)
#pragma unroll
        for (int nf = 0; nf < 4; nf++)
#pragma unroll
            for (int i = 0; i < 4; i++) acc[mf][nf][i] = 0.f;

    for (int c = 0; c < 4 && c < nchunk; c++) issue(c);
    for (int c = nchunk; c < 4; c++)
        asm volatile("cp.async.commit_group;" ::: "memory");

    for (int c = 0; c < nchunk; c++) {
        asm volatile("cp.async.wait_group 3;" ::: "memory");
        __syncthreads();
        if (c + 4 < nchunk) issue(c + 4);
        else asm volatile("cp.async.commit_group;" ::: "memory");

        const float* Ac = smem + (c % GST) * TILEF;
        const float* Wc = smem + (GST + (c % GST)) * TILEF;
#pragma unroll
        for (int ks = 0; ks < 2; ks++) {
            const int kb = ks * 8 + tig * 2;
            float2 bf[4];
#pragma unroll
            for (int nf = 0; nf < 4; nf++)
                bf[nf] = *(const float2*)&Wc[(nb + nf * 8 + gid) * APITCH + kb];
#pragma unroll
            for (int mf = 0; mf < 4; mf++) {
                float2 alo = *(const float2*)&Ac[(mb + mf * 16 + gid) * APITCH + kb];
                float2 ahi = *(const float2*)&Ac[(mb + mf * 16 + 8 + gid) * APITCH + kb];
#pragma unroll
                for (int nf = 0; nf < 4; nf++)
                    mma16n8k8(acc[mf][nf],
                              __float_as_uint(alo.x), __float_as_uint(ahi.x),
                              __float_as_uint(alo.y), __float_as_uint(ahi.y),
                              __float_as_uint(bf[nf].x), __float_as_uint(bf[nf].y));
            }
        }
    }

#pragma unroll
    for (int mf = 0; mf < 4; mf++) {
        const int row0 = m0 + mb + mf * 16 + gid;
        const int row1 = row0 + 8;
#pragma unroll
        for (int nf = 0; nf < 4; nf++) {
            const int col = n0 + nb + nf * 8 + 2 * tig;
            float2 b2 = *(const float2*)&bias[col];
            float v0 = acc[mf][nf][0] + b2.x;
            float v1 = acc[mf][nf][1] + b2.y;
            float v2 = acc[mf][nf][2] + b2.x;
            float v3 = acc[mf][nf][3] + b2.y;
            if (PACK || EPI == EPI_GELU) {
                v0 = gelu_exact(v0); v1 = gelu_exact(v1);
                v2 = gelu_exact(v2); v3 = gelu_exact(v3);
            } else if (EPI == EPI_SIGM) {
                v0 = 1.f/(1.f+__expf(-v0)); v1 = 1.f/(1.f+__expf(-v1));
                v2 = 1.f/(1.f+__expf(-v2)); v3 = 1.f/(1.f+__expf(-v3));
            } else if (EPI == EPI_RES) {
                float2 r0 = *(const float2*)&res[(size_t)row0 * N + col];
                float2 r1 = *(const float2*)&res[(size_t)row1 * N + col];
                v0 += r0.x; v1 += r0.y; v2 += r1.x; v3 += r1.y;
            }
            if (PACK) {
                if (n0 < CDIM) {
                    float2 o0 = { tf32bits(v0), tf32bits(v1) };
                    float2 o1 = { tf32bits(v2), tf32bits(v3) };
                    *(float2*)&Out[(size_t)row0 * CDIM + col] = o0;
                    *(float2*)&Out[(size_t)row1 * CDIM + col] = o1;
                } else {
                    int cm = col - CDIM;
                    Out2[ppf((size_t)row0 * CHID + cm)]     = tf32bits(v0);
                    Out2[ppf((size_t)row0 * CHID + cm + 1)] = tf32bits(v1);
                    Out2[ppf((size_t)row1 * CHID + cm)]     = tf32bits(v2);
                    Out2[ppf((size_t)row1 * CHID + cm + 1)] = tf32bits(v3);
                }
            } else {
                float2 o0 = {v0, v1}, o1 = {v2, v3};
                *(float2*)&Out[(size_t)row0 * N + col] = o0;
                *(float2*)&Out[(size_t)row1 * N + col] = o1;
            }
        }
    }
}

// ---------------- fp32 GEMM for tiny ca1 (output paired+rounded) ------------
template<int BM, int BN, int BK, int TM, int TN>
__global__ __launch_bounds__((BM/TM)*(BN/TN))
void gemm_nt_relu(const float* __restrict__ A, const float* __restrict__ W,
                  const float* __restrict__ bias, float* __restrict__ Out,
                  int M, int N, int K, const float* __restrict__ gw)
{
    if (gw && bw6(gw, 3) < WTHR) return;
    constexpr int NT = (BM/TM)*(BN/TN);
    __shared__ float As[BK][BM + 4];
    __shared__ float Ws[BK][BN + 4];

    const int tid = threadIdx.x;
    const int m0 = blockIdx.y * BM;
    const int n0 = blockIdx.x * BN;
    const int tx = tid % (BN / TN);
    const int ty = tid / (BN / TN);

    float acc[TM][TN];
#pragma unroll
    for (int i = 0; i < TM; i++)
#pragma unroll
        for (int j = 0; j < TN; j++) acc[i][j] = 0.f;

    for (int k0 = 0; k0 < K; k0 += BK) {
#pragma unroll
        for (int i = tid; i < BM*BK/4; i += NT) {
            int r = i / (BK/4), cg = i % (BK/4);
            float4 v = *(const float4*)&A[(size_t)(m0 + r) * K + k0 + cg*4];
            As[cg*4+0][r] = v.x; As[cg*4+1][r] = v.y;
            As[cg*4+2][r] = v.z; As[cg*4+3][r] = v.w;
        }
#pragma unroll
        for (int i = tid; i < BN*BK/4; i += NT) {
            int r = i / (BK/4), cg = i % (BK/4);
            float4 v = *(const float4*)&W[(size_t)(n0 + r) * K + k0 + cg*4];
            Ws[cg*4+0][r] = v.x; Ws[cg*4+1][r] = v.y;
            Ws[cg*4+2][r] = v.z; Ws[cg*4+3][r] = v.w;
        }
        __syncthreads();
#pragma unroll
        for (int k = 0; k < BK; k++) {
            float a[TM], b[TN];
#pragma unroll
            for (int i = 0; i < TM; i++) a[i] = As[k][ty*TM + i];
#pragma unroll
            for (int j = 0; j < TN; j++) b[j] = Ws[k][tx*TN + j];
#pragma unroll
            for (int i = 0; i < TM; i++)
#pragma unroll
                for (int j = 0; j < TN; j++) acc[i][j] += a[i] * b[j];
        }
        __syncthreads();
    }

#pragma unroll
    for (int i = 0; i < TM; i++) {
        int m = m0 + ty*TM + i;
#pragma unroll
        for (int j = 0; j < TN; j++) {
            int n = n0 + tx*TN + j;
            float v = fmaxf(acc[i][j] + bias[n], 0.f);
            Out[ppf((size_t)m * N + n)] = tf32bits(v);
        }
    }
}

// ---------------- octet-vectorized pack: round + pair-permute ---------------
// out[0..7] = {in0,in4,in1,in5,in2,in6,in3,in7}
__global__ void pack_pair8(float* __restrict__ dst, const float* __restrict__ src,
                           int n_oct, const float* __restrict__ gw, int gidx)
{
    int i = blockIdx.x * blockDim.x + threadIdx.x;
    if (i >= n_oct) return;
    if (gw && bw6(gw, gidx) < WTHR) return;
    const float4* s4 = (const float4*)src;
    float4 a = s4[2*i], b = s4[2*i+1];
    float4 o0 = { tf32bits(a.x), tf32bits(b.x), tf32bits(a.y), tf32bits(b.y) };
    float4 o1 = { tf32bits(a.z), tf32bits(b.z), tf32bits(a.w), tf32bits(b.w) };
    float4* d4 = (float4*)dst;
    d4[2*i] = o0; d4[2*i+1] = o1;
}
__global__ void pack_bias(float* __restrict__ dst, const float* __restrict__ b0,
                          const float* __restrict__ b1)
{
    int i = blockIdx.x * blockDim.x + threadIdx.x;
    if (i < CDIM + CHID) dst[i] = (i < CDIM) ? b0[i] : b1[i - CDIM];
}

// ---------------- extract x = x_list[...,-1] (octet, paired + rounded) ------
__global__ void extract_x8(const float* __restrict__ x_list, float* __restrict__ x,
                           const float* __restrict__ gw)
{
    int i = blockIdx.x * blockDim.x + threadIdx.x;
    if (i >= TOK * CDIM / 8) return;
    if (gw && bw6(gw, 2) < WTHR && bw6(gw, 3) < WTHR && bw6(gw, 5) < WTHR) return;
    const float4* s4 = (const float4*)x_list;
    float4 c0 = s4[4*i], c1 = s4[4*i+1], c2 = s4[4*i+2], c3 = s4[4*i+3];
    // in[k] = x[8i+k] = last-of-pair: {c0.y,c0.w,c1.y,c1.w,c2.y,c2.w,c3.y,c3.w}
    float4 o0 = { tf32bits(c0.y), tf32bits(c2.y), tf32bits(c0.w), tf32bits(c2.w) };
    float4 o1 = { tf32bits(c1.y), tf32bits(c3.y), tf32bits(c1.w), tf32bits(c3.w) };
    float4* d4 = (float4*)x;
    d4[2*i] = o0; d4[2*i+1] = o1;
}

// ---------------- combine: softmax(w_/T) weighted mix (predicated) ----------
__global__ void combine(const float* __restrict__ x_list,
                        const float* __restrict__ w_,
                        const float* __restrict__ op0,
                        const float* __restrict__ gate,
                        const float* __restrict__ op3,
                        float* __restrict__ xc, float* __restrict__ xcp)
{
    float w[6], mx = -1e30f;
#pragma unroll
    for (int i = 0; i < 6; i++) { w[i] = w_[i] * 100.0f; mx = fmaxf(mx, w[i]); }
    float s = 0.f;
#pragma unroll
    for (int i = 0; i < 6; i++) { w[i] = __expf(w[i] - mx); s += w[i]; }
    float inv = 1.0f / s;
#pragma unroll
    for (int i = 0; i < 6; i++) w[i] *= inv;

    int i = blockIdx.x * blockDim.x + threadIdx.x;
    if (i >= TOK * CDIM) return;
    float xl0 = x_list[2*i];
    float xv  = x_list[2*i + 1];
    float v = w[0]*xl0 + (w[1] + w[4])*xv;
    if (w[2] >= WTHR) v += w[2]*op0[i];
    if (w[3] >= WTHR) v += w[3]*(gate[i]*xv);
    if (w[5] >= WTHR) v += w[5]*op3[i];
    v = tf32bits(v);
    xc[i] = v;
    xcp[ppf((size_t)i)] = v;
}

// ---------------- qkv split + per-head LN + head-major transpose ------------
__global__ void ln_split(const float* __restrict__ qkv,
                         const float* __restrict__ nqg, const float* __restrict__ nqb,
                         const float* __restrict__ nkg, const float* __restrict__ nkb,
                         float* __restrict__ Qo, float* __restrict__ Ko, float* __restrict__ Vo)
{
    int gw = (blockIdx.x * blockDim.x + threadIdx.x) >> 5;
    int lane = threadIdx.x & 31;
    if (gw >= TOK * NHEAD) return;
    int t = gw / NHEAD, h = gw % NHEAD;
    int b = t / SEQ, n = t % SEQ;
    size_t src = (size_t)t * (3*CDIM) + h * HDIM;
    size_t dst = ((size_t)(b*NHEAD + h) * SEQ + n) * HDIM;

#pragma unroll
    for (int which = 0; which < 2; which++) {
        size_t so = src + (which ? CDIM : 0);
        float2 xv = *(const float2*)&qkv[so + lane*2];
        float sum = xv.x + xv.y;
        float ssq = xv.x*xv.x + xv.y*xv.y;
#pragma unroll
        for (int o = 16; o > 0; o >>= 1) {
            sum += __shfl_xor_sync(0xffffffff, sum, o);
            ssq += __shfl_xor_sync(0xffffffff, ssq, o);
        }
        float mean = sum * (1.0f/64.0f);
        float var  = ssq * (1.0f/64.0f) - mean*mean;
        float inv  = rsqrtf(var + 1e-5f);
        const float* g = which ? nkg : nqg;
        const float* bb = which ? nkb : nqb;
        float* O = which ? Ko : Qo;
        O[dst + lane*2 + 0] = (xv.x - mean)*inv*g[lane*2+0] + bb[lane*2+0];
        O[dst + lane*2 + 1] = (xv.y - mean)*inv*g[lane*2+1] + bb[lane*2+1];
    }
    *(float2*)&Vo[dst + lane*2] = *(const float2*)&qkv[src + 2*CDIM + lane*2];
}

// ---------------- tf32 MMA flash attention (epilogue: paired+rounded) -------
#define KPAD 68
#define VPAD 72
#define QS_F2   (32*130)
#define KS_F    (64*KPAD)
#define VS_F    (64*VPAD)
#define ATT_SMEM ((QS_F2*2 + KS_F + VS_F + QS_F2*2) * 4)

__global__ __launch_bounds__(256, 2)
void attn_mma(const float* __restrict__ Q, const float* __restrict__ K,
              const float* __restrict__ V, float* __restrict__ AO)
{
    extern __shared__ float sma[];
    float2* Qs2 = (float2*)sma;
    float*  Ks  = sma + QS_F2*2;
    float*  Vs  = Ks + KS_F;
    float2* Ps2 = (float2*)(Vs + VS_F);

    const int tid = threadIdx.x;
    const int lane = tid & 31, wid = tid >> 5;
    const int gid = lane >> 2, tig = lane & 3;
    const int q0 = blockIdx.x * 128;
    const int bh = blockIdx.y;
    const int qb = wid * 16;
    const float* Qb = Q + (size_t)bh * SEQ * HDIM;
    const float* Kb = K + (size_t)bh * SEQ * HDIM;
    const float* Vb = V + (size_t)bh * SEQ * HDIM;

    {
        int r = tid >> 1, hf = tid & 1;
#pragma unroll
        for (int i = 0; i < 8; i++) {
            int k0 = hf * 32 + i * 4;
            float4 v = *(const float4*)&Qb[(size_t)(q0 + r) * HDIM + k0];
            int p0 = (k0 >> 3) * 4;
            int h  = (k0 & 4) >> 2;
            ((float*)&Qs2[(p0 + 0) * 130 + r])[h] = tf32bits(v.x);
            ((float*)&Qs2[(p0 + 1) * 130 + r])[h] = tf32bits(v.y);
            ((float*)&Qs2[(p0 + 2) * 130 + r])[h] = tf32bits(v.z);
            ((float*)&Qs2[(p0 + 3) * 130 + r])[h] = tf32bits(v.w);
        }
    }

    float oacc[8][4];
#pragma unroll
    for (int nf = 0; nf < 8; nf++)
#pragma unroll
        for (int i = 0; i < 4; i++) oacc[nf][i] = 0.f;
    float m0s = -1e30f, m1s = -1e30f, l0s = 0.f, l1s = 0.f;

    for (int kt = 0; kt < 16; kt++) {
        __syncthreads();
        {
            int j = tid >> 2, f = tid & 3;
            int rowg = kt * 64 + j;
#pragma unroll
            for (int i = 0; i < 4; i++) {
                int d0 = f * 16 + i * 4;
                float4 kv = *(const float4*)&Kb[(size_t)rowg * HDIM + d0];
                float4 vv = *(const float4*)&Vb[(size_t)rowg * HDIM + d0];
                float4 kc = { tf32bits(kv.x), tf32bits(kv.y), tf32bits(kv.z), tf32bits(kv.w) };
                float4 vc = { tf32bits(vv.x), tf32bits(vv.y), tf32bits(vv.z), tf32bits(vv.w) };
                *(float4*)&Ks[j * KPAD + d0] = kc;
                *(float4*)&Vs[j * VPAD + d0] = vc;
            }
        }
        __syncthreads();

        float sacc[8][4];
#pragma unroll
        for (int nf = 0; nf < 8; nf++)
#pragma unroll
            for (int i = 0; i < 4; i++) sacc[nf][i] = 0.f;
#pragma unroll
        for (int ks = 0; ks < 8; ks++) {
            int p = ks * 4 + tig;
            uint2 aL = *(const uint2*)&Qs2[p * 130 + qb + gid];
            uint2 aH = *(const uint2*)&Qs2[p * 130 + qb + gid + 8];
#pragma unroll
            for (int nf = 0; nf < 8; nf++) {
                uint32_t b0 = __float_as_uint(Ks[(nf * 8 + gid) * KPAD + ks * 8 + tig]);
                uint32_t b1 = __float_as_uint(Ks[(nf * 8 + gid) * KPAD + ks * 8 + tig + 4]);
                mma16n8k8(sacc[nf], aL.x, aH.x, aL.y, aH.y, b0, b1);
            }
        }

        float mx0 = -1e30f, mx1 = -1e30f;
#pragma unroll
        for (int nf = 0; nf < 8; nf++) {
            sacc[nf][0] *= 0.125f; sacc[nf][1] *= 0.125f;
            sacc[nf][2] *= 0.125f; sacc[nf][3] *= 0.125f;
            mx0 = fmaxf(mx0, fmaxf(sacc[nf][0], sacc[nf][1]));
            mx1 = fmaxf(mx1, fmaxf(sacc[nf][2], sacc[nf][3]));
        }
        mx0 = fmaxf(mx0, __shfl_xor_sync(0xffffffff, mx0, 1));
        mx0 = fmaxf(mx0, __shfl_xor_sync(0xffffffff, mx0, 2));
        mx1 = fmaxf(mx1, __shfl_xor_sync(0xffffffff, mx1, 1));
        mx1 = fmaxf(mx1, __shfl_xor_sync(0xffffffff, mx1, 2));
        float mn0 = fmaxf(m0s, mx0), mn1 = fmaxf(m1s, mx1);
        float sc0 = __expf(m0s - mn0), sc1 = __expf(m1s - mn1);
        float sum0 = 0.f, sum1 = 0.f;
#pragma unroll
        for (int nf = 0; nf < 8; nf++) {
#pragma unroll
            for (int j = 0; j < 2; j++) {
                int cc = 2 * tig + j;
                int pc = nf * 4 + (cc & 3);
                int h  = cc >> 2;
                float p0 = __expf(sacc[nf][j]     - mn0);
                float p1 = __expf(sacc[nf][2 + j] - mn1);
                sum0 += p0; sum1 += p1;
                ((float*)&Ps2[pc * 130 + qb + gid])[h]     = tf32bits(p0);
                ((float*)&Ps2[pc * 130 + qb + gid + 8])[h] = tf32bits(p1);
            }
        }
        sum0 += __shfl_xor_sync(0xffffffff, sum0, 1);
        sum0 += __shfl_xor_sync(0xffffffff, sum0, 2);
        sum1 += __shfl_xor_sync(0xffffffff, sum1, 1);
        sum1 += __shfl_xor_sync(0xffffffff, sum1, 2);
        l0s = l0s * sc0 + sum0;  m0s = mn0;
        l1s = l1s * sc1 + sum1;  m1s = mn1;
#pragma unroll
        for (int nf = 0; nf < 8; nf++) {
            oacc[nf][0] *= sc0; oacc[nf][1] *= sc0;
            oacc[nf][2] *= sc1; oacc[nf][3] *= sc1;
        }
        __syncwarp();

#pragma unroll
        for (int ks = 0; ks < 8; ks++) {
            int p = ks * 4 + tig;
            uint2 aL = *(const uint2*)&Ps2[p * 130 + qb + gid];
            uint2 aH = *(const uint2*)&Ps2[p * 130 + qb + gid + 8];
#pragma unroll
            for (int nf = 0; nf < 8; nf++) {
                uint32_t b0 = __float_as_uint(Vs[(ks * 8 + tig) * VPAD + nf * 8 + gid]);
                uint32_t b1 = __float_as_uint(Vs[(ks * 8 + tig + 4) * VPAD + nf * 8 + gid]);
                mma16n8k8(oacc[nf], aL.x, aH.x, aL.y, aH.y, b0, b1);
            }
        }
    }

    {
        int b = bh >> 4, h = bh & 15;
        int r0 = q0 + qb + gid, r1 = r0 + 8;
        float inv0 = 1.0f / l0s, inv1 = 1.0f / l1s;
        size_t base0 = (size_t)(b * SEQ + r0) * CDIM;
        size_t base1 = (size_t)(b * SEQ + r1) * CDIM;
#pragma unroll
        for (int nf = 0; nf < 8; nf++) {
            int col = h * 64 + nf * 8 + 2 * tig;
            AO[base0 + ppf((size_t)col)]     = tf32bits(oacc[nf][0] * inv0);
            AO[base0 + ppf((size_t)col + 1)] = tf32bits(oacc[nf][1] * inv0);
            AO[base1 + ppf((size_t)col)]     = tf32bits(oacc[nf][2] * inv1);
            AO[base1 + ppf((size_t)col + 1)] = tf32bits(oacc[nf][3] * inv1);
        }
    }
}

// ---------------- attention map for query 0 (mean over heads) ---------------
__global__ void attn_map_kernel(const float* __restrict__ Q, const float* __restrict__ K,
                                float* __restrict__ omap)
{
    __shared__ float sc[SEQ];
    __shared__ float acc[SEQ];
    __shared__ float red[256];
    __shared__ float q0[HDIM];
    int b = blockIdx.x, tid = threadIdx.x;
    for (int i = tid; i < SEQ; i += 256) acc[i] = 0.f;
    for (int h = 0; h < NHEAD; h++) {
        const float* Qb = Q + ((size_t)(b*NHEAD + h) * SEQ) * HDIM;
        const float* Kb = K + ((size_t)(b*NHEAD + h) * SEQ) * HDIM;
        __syncthreads();
        if (tid < HDIM) q0[tid] = Qb[tid];
        __syncthreads();
        for (int m = tid; m < SEQ; m += 256) {
            float s = 0.f;
#pragma unroll 16
            for (int j = 0; j < HDIM; j++) s += q0[j] * Kb[(size_t)m*HDIM + j];
            sc[m] = s * 0.125f;
        }
        __syncthreads();
        float mx = -1e30f;
        for (int m = tid; m < SEQ; m += 256) mx = fmaxf(mx, sc[m]);
        red[tid] = mx; __syncthreads();
        for (int s = 128; s > 0; s >>= 1) { if (tid < s) red[tid] = fmaxf(red[tid], red[tid+s]); __syncthreads(); }
        mx = red[0]; __syncthreads();
        float sum = 0.f;
        for (int m = tid; m < SEQ; m += 256) { float p = __expf(sc[m] - mx); sc[m] = p; sum += p; }
        red[tid] = sum; __syncthreads();
        for (int s = 128; s > 0; s >>= 1) { if (tid < s) red[tid] += red[tid+s]; __syncthreads(); }
        float inv = 1.0f / red[0]; __syncthreads();
        for (int m = tid; m < SEQ; m += 256) acc[m] += sc[m] * inv;
    }
    __syncthreads();
    for (int m = tid; m < SEQ; m += 256)
        if (m >= 1) omap[(size_t)b*(SEQ-1) + m - 1] = acc[m] * (1.0f/NHEAD);
}

// ---------------- launch ----------------------------------------------------
extern "C" void kernel_launch(void* const* d_in, const int* in_sizes, int n_in,
                              void* d_out, int out_size)
{
    const float* x_list = (const float*)d_in[0];
    const float* w_     = (const float*)d_in[1];
    const float* qkv_w  = (const float*)d_in[2];
    const float* qkv_b  = (const float*)d_in[3];
    const float* proj_w = (const float*)d_in[4];
    const float* proj_b = (const float*)d_in[5];
    const float* nq_g   = (const float*)d_in[6];
    const float* nq_b   = (const float*)d_in[7];
    const float* nk_g   = (const float*)d_in[8];
    const float* nk_b   = (const float*)d_in[9];
    const float* conv_w = (const float*)d_in[10];
    const float* conv_b = (const float*)d_in[11];
    const float* ca1_w  = (const float*)d_in[12];
    const float* ca1_b  = (const float*)d_in[13];
    const float* ca2_w  = (const float*)d_in[14];
    const float* ca2_b  = (const float*)d_in[15];
    const float* mlp1_w = (const float*)d_in[16];
    const float* mlp1_b = (const float*)d_in[17];
    const float* mlp2_w = (const float*)d_in[18];
    const float* mlp2_b = (const float*)d_in[19];
    float* out = (float*)d_out;

    float *px, *pop0, *ph1p, *pgate, *pmhp, *pop3, *pxc, *pxcp, *pqkv, *pq, *pk, *pv, *paop;
    float *pwpk, *pbpk, *pqkvw, *pprojw, *pmlp2w, *pca2w, *pca1w;
    cudaGetSymbolAddress((void**)&px,    g_x);
    cudaGetSymbolAddress((void**)&pop0,  g_op0);
    cudaGetSymbolAddress((void**)&ph1p,  g_h1p);
    cudaGetSymbolAddress((void**)&pgate, g_gate);
    cudaGetSymbolAddress((void**)&pmhp,  g_mhp);
    cudaGetSymbolAddress((void**)&pop3,  g_op3);
    cudaGetSymbolAddress((void**)&pxc,   g_xc);
    cudaGetSymbolAddress((void**)&pxcp,  g_xcp);
    cudaGetSymbolAddress((void**)&pqkv,  g_qkv);
    cudaGetSymbolAddress((void**)&pq,    g_q);
    cudaGetSymbolAddress((void**)&pk,    g_k);
    cudaGetSymbolAddress((void**)&pv,    g_v);
    cudaGetSymbolAddress((void**)&paop,  g_aop);
    cudaGetSymbolAddress((void**)&pwpk,  g_wpk);
    cudaGetSymbolAddress((void**)&pbpk,  g_bpk);
    cudaGetSymbolAddress((void**)&pqkvw, g_qkvw);
    cudaGetSymbolAddress((void**)&pprojw,g_projw);
    cudaGetSymbolAddress((void**)&pmlp2w,g_mlp2w);
    cudaGetSymbolAddress((void**)&pca2w, g_ca2w);
    cudaGetSymbolAddress((void**)&pca1w, g_ca1w);

    const int NE = TOK * CDIM;

    cudaFuncSetAttribute(gemm_ca<EPI_GELU,1>, cudaFuncAttributeMaxDynamicSharedMemorySize, CASMEM);
    cudaFuncSetAttribute(gemm_ca<EPI_SIGM,0>, cudaFuncAttributeMaxDynamicSharedMemorySize, CASMEM);
    cudaFuncSetAttribute(gemm_ca<EPI_NONE,0>, cudaFuncAttributeMaxDynamicSharedMemorySize, CASMEM);
    cudaFuncSetAttribute(gemm_ca<EPI_RES,0>,  cudaFuncAttributeMaxDynamicSharedMemorySize, CASMEM);
    cudaFuncSetAttribute(attn_mma, cudaFuncAttributeMaxDynamicSharedMemorySize, ATT_SMEM);

    // ---- weight pre-round + pair packs (branch-gated; octet-vectorized)
    pack_pair8<<<(CDIM*CDIM/8+255)/256, 256>>>(pwpk, conv_w, CDIM*CDIM/8, w_, 2);
    pack_pair8<<<(CHID*CDIM/8+255)/256, 256>>>(pwpk + CDIM*CDIM, mlp1_w, CHID*CDIM/8, w_, 5);
    pack_pair8<<<(3*CDIM*CDIM/8+255)/256, 256>>>(pqkvw, qkv_w, 3*CDIM*CDIM/8, nullptr, 0);
    pack_pair8<<<(CDIM*CDIM/8+255)/256, 256>>>(pprojw, proj_w, CDIM*CDIM/8, nullptr, 0);
    pack_pair8<<<(CDIM*CHID/8+255)/256, 256>>>(pmlp2w, mlp2_w, CDIM*CHID/8, w_, 5);
    pack_pair8<<<(CDIM*64/8+255)/256, 256>>>(pca2w, ca2_w, CDIM*64/8, w_, 3);
    pack_pair8<<<(64*CDIM/8+255)/256, 256>>>(pca1w, ca1_w, 64*CDIM/8, w_, 3);
    pack_bias<<<(CDIM+CHID+255)/256, 256>>>(pbpk, conv_b, mlp1_b);

    extract_x8<<<(NE/8 + 255)/256, 256>>>(x_list, px, w_);

    // packed conv+mlp1 (gated per region: conv=2, mlp1=5)
    gemm_ca<EPI_GELU,1><<<dim3((CDIM+CHID)/128, TOK/128), 256, CASMEM>>>(
        px, pwpk, pbpk, nullptr, pop0, pmhp, TOK, CDIM+CHID, CDIM, CDIM, w_, 0);
    // h1 = relu(x @ ca1_w^T + ca1_b)  (gate 3)
    gemm_nt_relu<32,64,16,2,4><<<dim3(1, TOK/32), 256>>>(
        px, pca1w, ca1_b, ph1p, TOK, 64, CDIM, w_);
    // gate = sigmoid(h1 @ ca2_w^T + ca2_b)  (gate 3)
    gemm_ca<EPI_SIGM,0><<<dim3(CDIM/128, TOK/128), 256, CASMEM>>>(
        ph1p, pca2w, ca2_b, nullptr, pgate, nullptr, TOK, CDIM, 64, 64, w_, 3);
    // op3 = mh @ mlp2_w^T + mlp2_b  (gate 5)
    gemm_ca<EPI_NONE,0><<<dim3(CDIM/128, TOK/128), 256, CASMEM>>>(
        pmhp, pmlp2w, mlp2_b, nullptr, pop3, nullptr, TOK, CDIM, CHID, CHID, w_, 5);

    combine<<<(NE + 255)/256, 256>>>(x_list, w_, pop0, pgate, pop3, pxc, pxcp);

    // qkv = xc @ qkv_w^T + qkv_b  (always)
    gemm_ca<EPI_NONE,0><<<dim3(3*CDIM/128, TOK/128), 256, CASMEM>>>(
        pxcp, pqkvw, qkv_b, nullptr, pqkv, nullptr, TOK, 3*CDIM, CDIM, CDIM, nullptr, 0);

    ln_split<<<(TOK*NHEAD*32 + 255)/256, 256>>>(pqkv, nq_g, nq_b, nk_g, nk_b, pq, pk, pv);

    attn_mma<<<dim3(SEQ/128, NB*NHEAD), 256, ATT_SMEM>>>(pq, pk, pv, paop);

    attn_map_kernel<<<NB, 256>>>(pq, pk, out + (size_t)TOK * CDIM);

    // out = ao @ proj_w^T + proj_b + xc  (always)
    gemm_ca<EPI_RES,0><<<dim3(CDIM/128, TOK/128), 256, CASMEM>>>(
        paop, pprojw, proj_b, pxc, out, nullptr, TOK, CDIM, CDIM, CDIM, nullptr, 0);
}

// round 9
// speedup vs baseline: 5.4799x; 1.0334x over previous
#include <cuda_runtime.h>
#include <math.h>
#include <stdint.h>

// Problem constants
#define TOK   4096          // b*l tokens
#define CDIM  1024
#define CHID  4096          // mlp hidden
#define NHEAD 16
#define HDIM  64
#define NB    4
#define SEQ   1024
#define WTHR  1e-7f         // branch-weight negligibility threshold

// ---------------- scratch (device globals; no allocation allowed) ----------
__device__ float g_x   [TOK * CDIM];        // paired+rounded x
__device__ float g_op0 [TOK * CDIM];
__device__ float g_h1p [TOK * 64];
__device__ float g_gate[TOK * CDIM];
__device__ float g_mhp [TOK * CHID];
__device__ float g_op3 [TOK * CDIM];
__device__ float g_xc  [TOK * CDIM];
__device__ float g_xcp [TOK * CDIM];
__device__ float g_qkv [TOK * 3 * CDIM];
__device__ float g_q   [TOK * CDIM];
__device__ float g_k   [TOK * CDIM];
__device__ float g_v   [TOK * CDIM];
__device__ float g_aop [TOK * CDIM];
// pre-rounded + paired weights
__device__ float g_wpk  [(CDIM + CHID) * CDIM];   // [conv_w; mlp1_w]
__device__ float g_bpk  [CDIM + CHID];
__device__ float g_qkvw [3 * CDIM * CDIM];
__device__ float g_projw[CDIM * CDIM];
__device__ float g_mlp2w[CDIM * CHID];
__device__ float g_ca2w [CDIM * 64];
__device__ float g_ca1w [64 * CDIM];

#define EPI_NONE 0
#define EPI_GELU 1
#define EPI_RELU 2
#define EPI_SIGM 3
#define EPI_RES  4

__device__ __forceinline__ float gelu_exact(float v) {
    return 0.5f * v * (1.0f + erff(v * 0.70710678118654752f));
}
__device__ __forceinline__ uint32_t f2tf32(float x) {
    uint32_t u; asm("cvt.rn.tf32.f32 %0, %1;" : "=r"(u) : "f"(x)); return u;
}
__device__ __forceinline__ float tf32bits(float x) { return __uint_as_float(f2tf32(x)); }

// softmax(w_*100) weights, all 6
__device__ __forceinline__ void bw6all(const float* __restrict__ w_, float* wts) {
    float w[6], mx = -1e30f;
#pragma unroll
    for (int i = 0; i < 6; i++) { w[i] = w_[i] * 100.0f; mx = fmaxf(mx, w[i]); }
    float s = 0.f;
#pragma unroll
    for (int i = 0; i < 6; i++) { w[i] = __expf(w[i] - mx); s += w[i]; }
    float inv = 1.0f / s;
#pragma unroll
    for (int i = 0; i < 6; i++) wts[i] = w[i] * inv;
}
__device__ __forceinline__ float bw6(const float* __restrict__ w_, int idx) {
    float wts[6]; bw6all(w_, wts); return wts[idx];
}

// octet-local pair permutation of the K index: k -> 2*(k%4) + (k/4)%2
__device__ __forceinline__ size_t ppf(size_t i) {
    return (i & ~(size_t)7) | (((i & 3) << 1) | ((i >> 2) & 1));
}
__device__ __forceinline__ uint32_t smem_to_u32(const void* p) {
    uint32_t a;
    asm("{ .reg .u64 t; cvta.to.shared.u64 t, %1; cvt.u32.u64 %0, t; }" : "=r"(a) : "l"(p));
    return a;
}
__device__ __forceinline__ void mma16n8k8(float acc[4],
                                          uint32_t a0, uint32_t a1, uint32_t a2, uint32_t a3,
                                          uint32_t b0, uint32_t b1) {
    asm volatile(
        "mma.sync.aligned.m16n8k8.row.col.f32.tf32.tf32.f32 "
        "{%0,%1,%2,%3}, {%4,%5,%6,%7}, {%8,%9}, {%0,%1,%2,%3};\n"
        : "+f"(acc[0]), "+f"(acc[1]), "+f"(acc[2]), "+f"(acc[3])
        : "r"(a0), "r"(a1), "r"(a2), "r"(a3), "r"(b0), "r"(b1));
}

// =========== cp.async tf32 GEMM. A/W pre-rounded tf32 + K-paired. ===========
// CTA 128x128, BK=32, 3-stage cp.async ring (lookahead 2), 8 warps (2x4).
#define GST 3
#define BKC 32
#define APITCH 36
#define TILEF (128 * APITCH)
#define CASMEM (GST * 2 * TILEF * 4)   // 110592 B

template<int EPI, int PACK>
__global__ __launch_bounds__(256, 2)
void gemm_ca(const float* __restrict__ A, const float* __restrict__ W,
             const float* __restrict__ bias, const float* __restrict__ res,
             float* __restrict__ Out, float* __restrict__ Out2,
             int M, int N, int K, int lda,
             const float* __restrict__ gw, int gidx)
{
    const int m0 = blockIdx.y * 128, n0 = blockIdx.x * 128;
    if (gw) {
        int gi = PACK ? (n0 < CDIM ? 2 : 5) : gidx;
        if (bw6(gw, gi) < WTHR) return;
    }

    extern __shared__ float smem[];
    const uint32_t abase = smem_to_u32(smem);
    const uint32_t wbase = abase + GST * TILEF * 4;

    const int tid = threadIdx.x;
    const int lane = tid & 31, wid = tid >> 5;
    const int gid = lane >> 2, tig = lane & 3;
    const int mb = (wid >> 2) * 64, nb = (wid & 3) * 32;

    const int nchunk = K >> 5;

    auto issue = [&](int c) {
        const int st = c % GST;
        const int k0 = c << 5;
        const uint32_t sA = abase + st * TILEF * 4;
        const uint32_t sW = wbase + st * TILEF * 4;
#pragma unroll
        for (int i = 0; i < 4; i++) {
            int u = tid + i * 256;          // 0..1023
            int row = u >> 3, q = u & 7;
            const float* ga = A + (size_t)(m0 + row) * lda + k0 + q * 4;
            asm volatile("cp.async.cg.shared.global [%0], [%1], 16;"
                         :: "r"(sA + (uint32_t)(row * APITCH + q * 4) * 4), "l"(ga));
            const float* gwp = W + (size_t)(n0 + row) * K + k0 + q * 4;
            asm volatile("cp.async.cg.shared.global [%0], [%1], 16;"
                         :: "r"(sW + (uint32_t)(row * APITCH + q * 4) * 4), "l"(gwp));
        }
        asm volatile("cp.async.commit_group;" ::: "memory");
    };

    float acc[4][4][4];
#pragma unroll
    for (int mf = 0; mf < 4; mf++)
#pragma unroll
        for (int nf = 0; nf < 4; nf++)
#pragma unroll
            for (int i = 0; i < 4; i++) acc[mf][nf][i] = 0.f;

    issue(0);
    if (nchunk > 1) issue(1);
    else asm volatile("cp.async.commit_group;" ::: "memory");

    for (int c = 0; c < nchunk; c++) {
        asm volatile("cp.async.wait_group 1;" ::: "memory");
        __syncthreads();
        if (c + 2 < nchunk) issue(c + 2);
        else asm volatile("cp.async.commit_group;" ::: "memory");

        const float* Ac = smem + (c % GST) * TILEF;
        const float* Wc = smem + (GST + (c % GST)) * TILEF;
#pragma unroll
        for (int ks = 0; ks < 4; ks++) {
            const int kb = ks * 8 + tig * 2;
            float2 bf[4];
#pragma unroll
            for (int nf = 0; nf < 4; nf++)
                bf[nf] = *(const float2*)&Wc[(nb + nf * 8 + gid) * APITCH + kb];
#pragma unroll
            for (int mf = 0; mf < 4; mf++) {
                float2 alo = *(const float2*)&Ac[(mb + mf * 16 + gid) * APITCH + kb];
                float2 ahi = *(const float2*)&Ac[(mb + mf * 16 + 8 + gid) * APITCH + kb];
#pragma unroll
                for (int nf = 0; nf < 4; nf++)
                    mma16n8k8(acc[mf][nf],
                              __float_as_uint(alo.x), __float_as_uint(ahi.x),
                              __float_as_uint(alo.y), __float_as_uint(ahi.y),
                              __float_as_uint(bf[nf].x), __float_as_uint(bf[nf].y));
            }
        }
    }

#pragma unroll
    for (int mf = 0; mf < 4; mf++) {
        const int row0 = m0 + mb + mf * 16 + gid;
        const int row1 = row0 + 8;
#pragma unroll
        for (int nf = 0; nf < 4; nf++) {
            const int col = n0 + nb + nf * 8 + 2 * tig;
            float2 b2 = *(const float2*)&bias[col];
            float v0 = acc[mf][nf][0] + b2.x;
            float v1 = acc[mf][nf][1] + b2.y;
            float v2 = acc[mf][nf][2] + b2.x;
            float v3 = acc[mf][nf][3] + b2.y;
            if (PACK || EPI == EPI_GELU) {
                v0 = gelu_exact(v0); v1 = gelu_exact(v1);
                v2 = gelu_exact(v2); v3 = gelu_exact(v3);
            } else if (EPI == EPI_SIGM) {
                v0 = 1.f/(1.f+__expf(-v0)); v1 = 1.f/(1.f+__expf(-v1));
                v2 = 1.f/(1.f+__expf(-v2)); v3 = 1.f/(1.f+__expf(-v3));
            } else if (EPI == EPI_RES) {
                float2 r0 = *(const float2*)&res[(size_t)row0 * N + col];
                float2 r1 = *(const float2*)&res[(size_t)row1 * N + col];
                v0 += r0.x; v1 += r0.y; v2 += r1.x; v3 += r1.y;
            }
            if (PACK) {
                if (n0 < CDIM) {
                    float2 o0 = { tf32bits(v0), tf32bits(v1) };
                    float2 o1 = { tf32bits(v2), tf32bits(v3) };
                    *(float2*)&Out[(size_t)row0 * CDIM + col] = o0;
                    *(float2*)&Out[(size_t)row1 * CDIM + col] = o1;
                } else {
                    int cm = col - CDIM;
                    Out2[ppf((size_t)row0 * CHID + cm)]     = tf32bits(v0);
                    Out2[ppf((size_t)row0 * CHID + cm + 1)] = tf32bits(v1);
                    Out2[ppf((size_t)row1 * CHID + cm)]     = tf32bits(v2);
                    Out2[ppf((size_t)row1 * CHID + cm + 1)] = tf32bits(v3);
                }
            } else {
                float2 o0 = {v0, v1}, o1 = {v2, v3};
                *(float2*)&Out[(size_t)row0 * N + col] = o0;
                *(float2*)&Out[(size_t)row1 * N + col] = o1;
            }
        }
    }
}

// ---------------- fp32 GEMM for tiny ca1 (output paired+rounded) ------------
template<int BM, int BN, int BK, int TM, int TN>
__global__ __launch_bounds__((BM/TM)*(BN/TN))
void gemm_nt_relu(const float* __restrict__ A, const float* __restrict__ W,
                  const float* __restrict__ bias, float* __restrict__ Out,
                  int M, int N, int K, const float* __restrict__ gw)
{
    if (gw && bw6(gw, 3) < WTHR) return;
    constexpr int NT = (BM/TM)*(BN/TN);
    __shared__ float As[BK][BM + 4];
    __shared__ float Ws[BK][BN + 4];

    const int tid = threadIdx.x;
    const int m0 = blockIdx.y * BM;
    const int n0 = blockIdx.x * BN;
    const int tx = tid % (BN / TN);
    const int ty = tid / (BN / TN);

    float acc[TM][TN];
#pragma unroll
    for (int i = 0; i < TM; i++)
#pragma unroll
        for (int j = 0; j < TN; j++) acc[i][j] = 0.f;

    for (int k0 = 0; k0 < K; k0 += BK) {
#pragma unroll
        for (int i = tid; i < BM*BK/4; i += NT) {
            int r = i / (BK/4), cg = i % (BK/4);
            float4 v = *(const float4*)&A[(size_t)(m0 + r) * K + k0 + cg*4];
            As[cg*4+0][r] = v.x; As[cg*4+1][r] = v.y;
            As[cg*4+2][r] = v.z; As[cg*4+3][r] = v.w;
        }
#pragma unroll
        for (int i = tid; i < BN*BK/4; i += NT) {
            int r = i / (BK/4), cg = i % (BK/4);
            float4 v = *(const float4*)&W[(size_t)(n0 + r) * K + k0 + cg*4];
            Ws[cg*4+0][r] = v.x; Ws[cg*4+1][r] = v.y;
            Ws[cg*4+2][r] = v.z; Ws[cg*4+3][r] = v.w;
        }
        __syncthreads();
#pragma unroll
        for (int k = 0; k < BK; k++) {
            float a[TM], b[TN];
#pragma unroll
            for (int i = 0; i < TM; i++) a[i] = As[k][ty*TM + i];
#pragma unroll
            for (int j = 0; j < TN; j++) b[j] = Ws[k][tx*TN + j];
#pragma unroll
            for (int i = 0; i < TM; i++)
#pragma unroll
                for (int j = 0; j < TN; j++) acc[i][j] += a[i] * b[j];
        }
        __syncthreads();
    }

#pragma unroll
    for (int i = 0; i < TM; i++) {
        int m = m0 + ty*TM + i;
#pragma unroll
        for (int j = 0; j < TN; j++) {
            int n = n0 + tx*TN + j;
            float v = fmaxf(acc[i][j] + bias[n], 0.f);
            Out[ppf((size_t)m * N + n)] = tf32bits(v);
        }
    }
}

// ---------------- unified pack kernel (all weights+biases, one launch) ------
// Each thread handles 32 floats (8 LDG.128 / 8 STG.128).
__device__ __forceinline__ void pack32(float* __restrict__ dst,
                                       const float* __restrict__ src, int g) {
    const float4* s4 = (const float4*)src + (size_t)g * 8;
    float4* d4 = (float4*)dst + (size_t)g * 8;
    float4 a[4], b[4];
#pragma unroll
    for (int j = 0; j < 4; j++) { a[j] = s4[2*j]; b[j] = s4[2*j+1]; }
#pragma unroll
    for (int j = 0; j < 4; j++) {
        float4 o0 = { tf32bits(a[j].x), tf32bits(b[j].x), tf32bits(a[j].y), tf32bits(b[j].y) };
        float4 o1 = { tf32bits(a[j].z), tf32bits(b[j].z), tf32bits(a[j].w), tf32bits(b[j].w) };
        d4[2*j] = o0; d4[2*j+1] = o1;
    }
}
__device__ __forceinline__ void copy32(float* __restrict__ dst,
                                       const float* __restrict__ src, int g) {
    const float4* s4 = (const float4*)src + (size_t)g * 8;
    float4* d4 = (float4*)dst + (size_t)g * 8;
    float4 t[8];
#pragma unroll
    for (int j = 0; j < 8; j++) t[j] = s4[j];
#pragma unroll
    for (int j = 0; j < 8; j++) d4[j] = t[j];
}

// region sizes in 32-float groups (compile-time)
#define PK_CONV  32768
#define PK_MLP1  131072
#define PK_QKV   98304
#define PK_PROJ  32768
#define PK_MLP2  131072
#define PK_CA2   2048
#define PK_CA1   2048
#define PK_BC    32
#define PK_BM    128
#define PKP0 0
#define PKP1 (PKP0+PK_CONV)      // 32768
#define PKP2 (PKP1+PK_MLP1)      // 163840
#define PKP3 (PKP2+PK_QKV)       // 262144
#define PKP4 (PKP3+PK_PROJ)      // 294912
#define PKP5 (PKP4+PK_MLP2)      // 425984
#define PKP6 (PKP5+PK_CA2)       // 428032
#define PKP7 (PKP6+PK_CA1)       // 430080
#define PKP8 (PKP7+PK_BC)        // 430112
#define PKEND (PKP8+PK_BM)       // 430240

__global__ void pack_all(const float* __restrict__ w_,
                         const float* __restrict__ conv_w, const float* __restrict__ mlp1_w,
                         const float* __restrict__ qkv_w,  const float* __restrict__ proj_w,
                         const float* __restrict__ mlp2_w, const float* __restrict__ ca2_w,
                         const float* __restrict__ ca1_w,
                         const float* __restrict__ conv_b, const float* __restrict__ mlp1_b,
                         float* __restrict__ wpk, float* __restrict__ qkvw,
                         float* __restrict__ projw, float* __restrict__ mlp2w,
                         float* __restrict__ ca2w, float* __restrict__ ca1w,
                         float* __restrict__ bpk)
{
    int t = blockIdx.x * blockDim.x + threadIdx.x;
    if (t >= PKEND) return;
    float wts[6]; bw6all(w_, wts);
    if (t < PKP1)      { if (wts[2] >= WTHR) pack32(wpk, conv_w, t - PKP0); }
    else if (t < PKP2) { if (wts[5] >= WTHR) pack32(wpk + (size_t)CDIM*CDIM, mlp1_w, t - PKP1); }
    else if (t < PKP3) { pack32(qkvw, qkv_w, t - PKP2); }
    else if (t < PKP4) { pack32(projw, proj_w, t - PKP3); }
    else if (t < PKP5) { if (wts[5] >= WTHR) pack32(mlp2w, mlp2_w, t - PKP4); }
    else if (t < PKP6) { if (wts[3] >= WTHR) pack32(ca2w, ca2_w, t - PKP5); }
    else if (t < PKP7) { if (wts[3] >= WTHR) pack32(ca1w, ca1_w, t - PKP6); }
    else if (t < PKP8) { if (wts[2] >= WTHR) copy32(bpk, conv_b, t - PKP7); }
    else               { if (wts[5] >= WTHR) copy32(bpk + CDIM, mlp1_b, t - PKP8); }
}

// ---------------- extract x = x_list[...,-1] (32 floats/thread) -------------
__global__ void extract_x32(const float* __restrict__ x_list, float* __restrict__ x,
                            const float* __restrict__ gw)
{
    int t = blockIdx.x * blockDim.x + threadIdx.x;
    if (t >= TOK * CDIM / 32) return;
    float wts[6]; bw6all(gw, wts);
    if (wts[2] < WTHR && wts[3] < WTHR && wts[5] < WTHR) return;
    const float4* s4 = (const float4*)x_list;
    float4* d4 = (float4*)x;
#pragma unroll
    for (int o = 0; o < 4; o++) {
        int i = t * 4 + o;       // octet index
        float4 c0 = s4[4*i], c1 = s4[4*i+1], c2 = s4[4*i+2], c3 = s4[4*i+3];
        float4 o0 = { tf32bits(c0.y), tf32bits(c2.y), tf32bits(c0.w), tf32bits(c2.w) };
        float4 o1 = { tf32bits(c1.y), tf32bits(c3.y), tf32bits(c1.w), tf32bits(c3.w) };
        d4[2*i] = o0; d4[2*i+1] = o1;
    }
}

// ---------------- combine: 8 elements/thread, predicated --------------------
__global__ void combine8(const float* __restrict__ x_list,
                         const float* __restrict__ w_,
                         const float* __restrict__ op0,
                         const float* __restrict__ gate,
                         const float* __restrict__ op3,
                         float* __restrict__ xc, float* __restrict__ xcp)
{
    float w[6]; bw6all(w_, w);
    int i = blockIdx.x * blockDim.x + threadIdx.x;   // octet index
    if (i >= TOK * CDIM / 8) return;
    const float4* s4 = (const float4*)x_list;
    float4 c0 = s4[4*i], c1 = s4[4*i+1], c2 = s4[4*i+2], c3 = s4[4*i+3];
    float xl0[8] = { c0.x, c0.z, c1.x, c1.z, c2.x, c2.z, c3.x, c3.z };
    float xv [8] = { c0.y, c0.w, c1.y, c1.w, c2.y, c2.w, c3.y, c3.w };
    float v[8];
    float w14 = w[1] + w[4];
#pragma unroll
    for (int k = 0; k < 8; k++) v[k] = w[0]*xl0[k] + w14*xv[k];
    if (w[2] >= WTHR) {
        float4 a = ((const float4*)op0)[2*i], b = ((const float4*)op0)[2*i+1];
        v[0] += w[2]*a.x; v[1] += w[2]*a.y; v[2] += w[2]*a.z; v[3] += w[2]*a.w;
        v[4] += w[2]*b.x; v[5] += w[2]*b.y; v[6] += w[2]*b.z; v[7] += w[2]*b.w;
    }
    if (w[3] >= WTHR) {
        float4 a = ((const float4*)gate)[2*i], b = ((const float4*)gate)[2*i+1];
        v[0] += w[3]*a.x*xv[0]; v[1] += w[3]*a.y*xv[1]; v[2] += w[3]*a.z*xv[2]; v[3] += w[3]*a.w*xv[3];
        v[4] += w[3]*b.x*xv[4]; v[5] += w[3]*b.y*xv[5]; v[6] += w[3]*b.z*xv[6]; v[7] += w[3]*b.w*xv[7];
    }
    if (w[5] >= WTHR) {
        float4 a = ((const float4*)op3)[2*i], b = ((const float4*)op3)[2*i+1];
        v[0] += w[5]*a.x; v[1] += w[5]*a.y; v[2] += w[5]*a.z; v[3] += w[5]*a.w;
        v[4] += w[5]*b.x; v[5] += w[5]*b.y; v[6] += w[5]*b.z; v[7] += w[5]*b.w;
    }
#pragma unroll
    for (int k = 0; k < 8; k++) v[k] = tf32bits(v[k]);
    float4* dc = (float4*)xc;
    float4 u0 = { v[0], v[1], v[2], v[3] }, u1 = { v[4], v[5], v[6], v[7] };
    dc[2*i] = u0; dc[2*i+1] = u1;
    float4* dp = (float4*)xcp;
    float4 p0 = { v[0], v[4], v[1], v[5] }, p1 = { v[2], v[6], v[3], v[7] };
    dp[2*i] = p0; dp[2*i+1] = p1;
}

// ---------------- qkv split + per-head LN + head-major transpose ------------
__global__ void ln_split(const float* __restrict__ qkv,
                         const float* __restrict__ nqg, const float* __restrict__ nqb,
                         const float* __restrict__ nkg, const float* __restrict__ nkb,
                         float* __restrict__ Qo, float* __restrict__ Ko, float* __restrict__ Vo)
{
    int gw = (blockIdx.x * blockDim.x + threadIdx.x) >> 5;
    int lane = threadIdx.x & 31;
    if (gw >= TOK * NHEAD) return;
    int t = gw / NHEAD, h = gw % NHEAD;
    int b = t / SEQ, n = t % SEQ;
    size_t src = (size_t)t * (3*CDIM) + h * HDIM;
    size_t dst = ((size_t)(b*NHEAD + h) * SEQ + n) * HDIM;

#pragma unroll
    for (int which = 0; which < 2; which++) {
        size_t so = src + (which ? CDIM : 0);
        float2 xv = *(const float2*)&qkv[so + lane*2];
        float sum = xv.x + xv.y;
        float ssq = xv.x*xv.x + xv.y*xv.y;
#pragma unroll
        for (int o = 16; o > 0; o >>= 1) {
            sum += __shfl_xor_sync(0xffffffff, sum, o);
            ssq += __shfl_xor_sync(0xffffffff, ssq, o);
        }
        float mean = sum * (1.0f/64.0f);
        float var  = ssq * (1.0f/64.0f) - mean*mean;
        float inv  = rsqrtf(var + 1e-5f);
        const float* g = which ? nkg : nqg;
        const float* bb = which ? nkb : nqb;
        float* O = which ? Ko : Qo;
        O[dst + lane*2 + 0] = (xv.x - mean)*inv*g[lane*2+0] + bb[lane*2+0];
        O[dst + lane*2 + 1] = (xv.y - mean)*inv*g[lane*2+1] + bb[lane*2+1];
    }
    *(float2*)&Vo[dst + lane*2] = *(const float2*)&qkv[src + 2*CDIM + lane*2];
}

// ---------------- tf32 MMA flash attention (epilogue: paired+rounded) -------
#define KPAD 68
#define VPAD 72
#define QS_F2   (32*130)
#define KS_F    (64*KPAD)
#define VS_F    (64*VPAD)
#define ATT_SMEM ((QS_F2*2 + KS_F + VS_F + QS_F2*2) * 4)

__global__ __launch_bounds__(256, 2)
void attn_mma(const float* __restrict__ Q, const float* __restrict__ K,
              const float* __restrict__ V, float* __restrict__ AO)
{
    extern __shared__ float sma[];
    float2* Qs2 = (float2*)sma;
    float*  Ks  = sma + QS_F2*2;
    float*  Vs  = Ks + KS_F;
    float2* Ps2 = (float2*)(Vs + VS_F);

    const int tid = threadIdx.x;
    const int lane = tid & 31, wid = tid >> 5;
    const int gid = lane >> 2, tig = lane & 3;
    const int q0 = blockIdx.x * 128;
    const int bh = blockIdx.y;
    const int qb = wid * 16;
    const float* Qb = Q + (size_t)bh * SEQ * HDIM;
    const float* Kb = K + (size_t)bh * SEQ * HDIM;
    const float* Vb = V + (size_t)bh * SEQ * HDIM;

    {
        int r = tid >> 1, hf = tid & 1;
#pragma unroll
        for (int i = 0; i < 8; i++) {
            int k0 = hf * 32 + i * 4;
            float4 v = *(const float4*)&Qb[(size_t)(q0 + r) * HDIM + k0];
            int p0 = (k0 >> 3) * 4;
            int h  = (k0 & 4) >> 2;
            ((float*)&Qs2[(p0 + 0) * 130 + r])[h] = tf32bits(v.x);
            ((float*)&Qs2[(p0 + 1) * 130 + r])[h] = tf32bits(v.y);
            ((float*)&Qs2[(p0 + 2) * 130 + r])[h] = tf32bits(v.z);
            ((float*)&Qs2[(p0 + 3) * 130 + r])[h] = tf32bits(v.w);
        }
    }

    float oacc[8][4];
#pragma unroll
    for (int nf = 0; nf < 8; nf++)
#pragma unroll
        for (int i = 0; i < 4; i++) oacc[nf][i] = 0.f;
    float m0s = -1e30f, m1s = -1e30f, l0s = 0.f, l1s = 0.f;

    for (int kt = 0; kt < 16; kt++) {
        __syncthreads();
        {
            int j = tid >> 2, f = tid & 3;
            int rowg = kt * 64 + j;
#pragma unroll
            for (int i = 0; i < 4; i++) {
                int d0 = f * 16 + i * 4;
                float4 kv = *(const float4*)&Kb[(size_t)rowg * HDIM + d0];
                float4 vv = *(const float4*)&Vb[(size_t)rowg * HDIM + d0];
                float4 kc = { tf32bits(kv.x), tf32bits(kv.y), tf32bits(kv.z), tf32bits(kv.w) };
                float4 vc = { tf32bits(vv.x), tf32bits(vv.y), tf32bits(vv.z), tf32bits(vv.w) };
                *(float4*)&Ks[j * KPAD + d0] = kc;
                *(float4*)&Vs[j * VPAD + d0] = vc;
            }
        }
        __syncthreads();

        float sacc[8][4];
#pragma unroll
        for (int nf = 0; nf < 8; nf++)
#pragma unroll
            for (int i = 0; i < 4; i++) sacc[nf][i] = 0.f;
#pragma unroll
        for (int ks = 0; ks < 8; ks++) {
            int p = ks * 4 + tig;
            uint2 aL = *(const uint2*)&Qs2[p * 130 + qb + gid];
            uint2 aH = *(const uint2*)&Qs2[p * 130 + qb + gid + 8];
#pragma unroll
            for (int nf = 0; nf < 8; nf++) {
                uint32_t b0 = __float_as_uint(Ks[(nf * 8 + gid) * KPAD + ks * 8 + tig]);
                uint32_t b1 = __float_as_uint(Ks[(nf * 8 + gid) * KPAD + ks * 8 + tig + 4]);
                mma16n8k8(sacc[nf], aL.x, aH.x, aL.y, aH.y, b0, b1);
            }
        }

        float mx0 = -1e30f, mx1 = -1e30f;
#pragma unroll
        for (int nf = 0; nf < 8; nf++) {
            sacc[nf][0] *= 0.125f; sacc[nf][1] *= 0.125f;
            sacc[nf][2] *= 0.125f; sacc[nf][3] *= 0.125f;
            mx0 = fmaxf(mx0, fmaxf(sacc[nf][0], sacc[nf][1]));
            mx1 = fmaxf(mx1, fmaxf(sacc[nf][2], sacc[nf][3]));
        }
        mx0 = fmaxf(mx0, __shfl_xor_sync(0xffffffff, mx0, 1));
        mx0 = fmaxf(mx0, __shfl_xor_sync(0xffffffff, mx0, 2));
        mx1 = fmaxf(mx1, __shfl_xor_sync(0xffffffff, mx1, 1));
        mx1 = fmaxf(mx1, __shfl_xor_sync(0xffffffff, mx1, 2));
        float mn0 = fmaxf(m0s, mx0), mn1 = fmaxf(m1s, mx1);
        float sc0 = __expf(m0s - mn0), sc1 = __expf(m1s - mn1);
        float sum0 = 0.f, sum1 = 0.f;
#pragma unroll
        for (int nf = 0; nf < 8; nf++) {
#pragma unroll
            for (int j = 0; j < 2; j++) {
                int cc = 2 * tig + j;
                int pc = nf * 4 + (cc & 3);
                int h  = cc >> 2;
                float p0 = __expf(sacc[nf][j]     - mn0);
                float p1 = __expf(sacc[nf][2 + j] - mn1);
                sum0 += p0; sum1 += p1;
                ((float*)&Ps2[pc * 130 + qb + gid])[h]     = tf32bits(p0);
                ((float*)&Ps2[pc * 130 + qb + gid + 8])[h] = tf32bits(p1);
            }
        }
        sum0 += __shfl_xor_sync(0xffffffff, sum0, 1);
        sum0 += __shfl_xor_sync(0xffffffff, sum0, 2);
        sum1 += __shfl_xor_sync(0xffffffff, sum1, 1);
        sum1 += __shfl_xor_sync(0xffffffff, sum1, 2);
        l0s = l0s * sc0 + sum0;  m0s = mn0;
        l1s = l1s * sc1 + sum1;  m1s = mn1;
#pragma unroll
        for (int nf = 0; nf < 8; nf++) {
            oacc[nf][0] *= sc0; oacc[nf][1] *= sc0;
            oacc[nf][2] *= sc1; oacc[nf][3] *= sc1;
        }
        __syncwarp();

#pragma unroll
        for (int ks = 0; ks < 8; ks++) {
            int p = ks * 4 + tig;
            uint2 aL = *(const uint2*)&Ps2[p * 130 + qb + gid];
            uint2 aH = *(const uint2*)&Ps2[p * 130 + qb + gid + 8];
#pragma unroll
            for (int nf = 0; nf < 8; nf++) {
                uint32_t b0 = __float_as_uint(Vs[(ks * 8 + tig) * VPAD + nf * 8 + gid]);
                uint32_t b1 = __float_as_uint(Vs[(ks * 8 + tig + 4) * VPAD + nf * 8 + gid]);
                mma16n8k8(oacc[nf], aL.x, aH.x, aL.y, aH.y, b0, b1);
            }
        }
    }

    {
        int b = bh >> 4, h = bh & 15;
        int r0 = q0 + qb + gid, r1 = r0 + 8;
        float inv0 = 1.0f / l0s, inv1 = 1.0f / l1s;
        size_t base0 = (size_t)(b * SEQ + r0) * CDIM;
        size_t base1 = (size_t)(b * SEQ + r1) * CDIM;
#pragma unroll
        for (int nf = 0; nf < 8; nf++) {
            int col = h * 64 + nf * 8 + 2 * tig;
            AO[base0 + ppf((size_t)col)]     = tf32bits(oacc[nf][0] * inv0);
            AO[base0 + ppf((size_t)col + 1)] = tf32bits(oacc[nf][1] * inv0);
            AO[base1 + ppf((size_t)col)]     = tf32bits(oacc[nf][2] * inv1);
            AO[base1 + ppf((size_t)col + 1)] = tf32bits(oacc[nf][3] * inv1);
        }
    }
}

// ---------------- attention map for query 0 (mean over heads) ---------------
__global__ void attn_map_kernel(const float* __restrict__ Q, const float* __restrict__ K,
                                float* __restrict__ omap)
{
    __shared__ float sc[SEQ];
    __shared__ float acc[SEQ];
    __shared__ float red[256];
    __shared__ float q0[HDIM];
    int b = blockIdx.x, tid = threadIdx.x;
    for (int i = tid; i < SEQ; i += 256) acc[i] = 0.f;
    for (int h = 0; h < NHEAD; h++) {
        const float* Qb = Q + ((size_t)(b*NHEAD + h) * SEQ) * HDIM;
        const float* Kb = K + ((size_t)(b*NHEAD + h) * SEQ) * HDIM;
        __syncthreads();
        if (tid < HDIM) q0[tid] = Qb[tid];
        __syncthreads();
        for (int m = tid; m < SEQ; m += 256) {
            float s = 0.f;
#pragma unroll 16
            for (int j = 0; j < HDIM; j++) s += q0[j] * Kb[(size_t)m*HDIM + j];
            sc[m] = s * 0.125f;
        }
        __syncthreads();
        float mx = -1e30f;
        for (int m = tid; m < SEQ; m += 256) mx = fmaxf(mx, sc[m]);
        red[tid] = mx; __syncthreads();
        for (int s = 128; s > 0; s >>= 1) { if (tid < s) red[tid] = fmaxf(red[tid], red[tid+s]); __syncthreads(); }
        mx = red[0]; __syncthreads();
        float sum = 0.f;
        for (int m = tid; m < SEQ; m += 256) { float p = __expf(sc[m] - mx); sc[m] = p; sum += p; }
        red[tid] = sum; __syncthreads();
        for (int s = 128; s > 0; s >>= 1) { if (tid < s) red[tid] += red[tid+s]; __syncthreads(); }
        float inv = 1.0f / red[0]; __syncthreads();
        for (int m = tid; m < SEQ; m += 256) acc[m] += sc[m] * inv;
    }
    __syncthreads();
    for (int m = tid; m < SEQ; m += 256)
        if (m >= 1) omap[(size_t)b*(SEQ-1) + m - 1] = acc[m] * (1.0f/NHEAD);
}

// ---------------- launch ----------------------------------------------------
extern "C" void kernel_launch(void* const* d_in, const int* in_sizes, int n_in,
                              void* d_out, int out_size)
{
    const float* x_list = (const float*)d_in[0];
    const float* w_     = (const float*)d_in[1];
    const float* qkv_w  = (const float*)d_in[2];
    const float* qkv_b  = (const float*)d_in[3];
    const float* proj_w = (const float*)d_in[4];
    const float* proj_b = (const float*)d_in[5];
    const float* nq_g   = (const float*)d_in[6];
    const float* nq_b   = (const float*)d_in[7];
    const float* nk_g   = (const float*)d_in[8];
    const float* nk_b   = (const float*)d_in[9];
    const float* conv_w = (const float*)d_in[10];
    const float* conv_b = (const float*)d_in[11];
    const float* ca1_w  = (const float*)d_in[12];
    const float* ca1_b  = (const float*)d_in[13];
    const float* ca2_w  = (const float*)d_in[14];
    const float* ca2_b  = (const float*)d_in[15];
    const float* mlp1_w = (const float*)d_in[16];
    const float* mlp1_b = (const float*)d_in[17];
    const float* mlp2_w = (const float*)d_in[18];
    const float* mlp2_b = (const float*)d_in[19];
    float* out = (float*)d_out;

    float *px, *pop0, *ph1p, *pgate, *pmhp, *pop3, *pxc, *pxcp, *pqkv, *pq, *pk, *pv, *paop;
    float *pwpk, *pbpk, *pqkvw, *pprojw, *pmlp2w, *pca2w, *pca1w;
    cudaGetSymbolAddress((void**)&px,    g_x);
    cudaGetSymbolAddress((void**)&pop0,  g_op0);
    cudaGetSymbolAddress((void**)&ph1p,  g_h1p);
    cudaGetSymbolAddress((void**)&pgate, g_gate);
    cudaGetSymbolAddress((void**)&pmhp,  g_mhp);
    cudaGetSymbolAddress((void**)&pop3,  g_op3);
    cudaGetSymbolAddress((void**)&pxc,   g_xc);
    cudaGetSymbolAddress((void**)&pxcp,  g_xcp);
    cudaGetSymbolAddress((void**)&pqkv,  g_qkv);
    cudaGetSymbolAddress((void**)&pq,    g_q);
    cudaGetSymbolAddress((void**)&pk,    g_k);
    cudaGetSymbolAddress((void**)&pv,    g_v);
    cudaGetSymbolAddress((void**)&paop,  g_aop);
    cudaGetSymbolAddress((void**)&pwpk,  g_wpk);
    cudaGetSymbolAddress((void**)&pbpk,  g_bpk);
    cudaGetSymbolAddress((void**)&pqkvw, g_qkvw);
    cudaGetSymbolAddress((void**)&pprojw,g_projw);
    cudaGetSymbolAddress((void**)&pmlp2w,g_mlp2w);
    cudaGetSymbolAddress((void**)&pca2w, g_ca2w);
    cudaGetSymbolAddress((void**)&pca1w, g_ca1w);

    const int NE = TOK * CDIM;

    cudaFuncSetAttribute(gemm_ca<EPI_GELU,1>, cudaFuncAttributeMaxDynamicSharedMemorySize, CASMEM);
    cudaFuncSetAttribute(gemm_ca<EPI_SIGM,0>, cudaFuncAttributeMaxDynamicSharedMemorySize, CASMEM);
    cudaFuncSetAttribute(gemm_ca<EPI_NONE,0>, cudaFuncAttributeMaxDynamicSharedMemorySize, CASMEM);
    cudaFuncSetAttribute(gemm_ca<EPI_RES,0>,  cudaFuncAttributeMaxDynamicSharedMemorySize, CASMEM);
    cudaFuncSetAttribute(attn_mma, cudaFuncAttributeMaxDynamicSharedMemorySize, ATT_SMEM);

    // ---- one merged pack launch (gated per region inside)
    pack_all<<<(PKEND + 255)/256, 256>>>(w_,
        conv_w, mlp1_w, qkv_w, proj_w, mlp2_w, ca2_w, ca1_w, conv_b, mlp1_b,
        pwpk, pqkvw, pprojw, pmlp2w, pca2w, pca1w, pbpk);

    extract_x32<<<(NE/32 + 255)/256, 256>>>(x_list, px, w_);

    // packed conv+mlp1 (gated per region: conv=2, mlp1=5)
    gemm_ca<EPI_GELU,1><<<dim3((CDIM+CHID)/128, TOK/128), 256, CASMEM>>>(
        px, pwpk, pbpk, nullptr, pop0, pmhp, TOK, CDIM+CHID, CDIM, CDIM, w_, 0);
    // h1 = relu(x @ ca1_w^T + ca1_b)  (gate 3)
    gemm_nt_relu<32,64,16,2,4><<<dim3(1, TOK/32), 256>>>(
        px, pca1w, ca1_b, ph1p, TOK, 64, CDIM, w_);
    // gate = sigmoid(h1 @ ca2_w^T + ca2_b)  (gate 3)
    gemm_ca<EPI_SIGM,0><<<dim3(CDIM/128, TOK/128), 256, CASMEM>>>(
        ph1p, pca2w, ca2_b, nullptr, pgate, nullptr, TOK, CDIM, 64, 64, w_, 3);
    // op3 = mh @ mlp2_w^T + mlp2_b  (gate 5)
    gemm_ca<EPI_NONE,0><<<dim3(CDIM/128, TOK/128), 256, CASMEM>>>(
        pmhp, pmlp2w, mlp2_b, nullptr, pop3, nullptr, TOK, CDIM, CHID, CHID, w_, 5);

    combine8<<<(NE/8 + 255)/256, 256>>>(x_list, w_, pop0, pgate, pop3, pxc, pxcp);

    // qkv = xc @ qkv_w^T + qkv_b  (always)
    gemm_ca<EPI_NONE,0><<<dim3(3*CDIM/128, TOK/128), 256, CASMEM>>>(
        pxcp, pqkvw, qkv_b, nullptr, pqkv, nullptr, TOK, 3*CDIM, CDIM, CDIM, nullptr, 0);

    ln_split<<<(TOK*NHEAD*32 + 255)/256, 256>>>(pqkv, nq_g, nq_b, nk_g, nk_b, pq, pk, pv);

    attn_mma<<<dim3(SEQ/128, NB*NHEAD), 256, ATT_SMEM>>>(pq, pk, pv, paop);

    attn_map_kernel<<<NB, 256>>>(pq, pk, out + (size_t)TOK * CDIM);

    // out = ao @ proj_w^T + proj_b + xc  (always)
    gemm_ca<EPI_RES,0><<<dim3(CDIM/128, TOK/128), 256, CASMEM>>>(
        paop, pprojw, proj_b, pxc, out, nullptr, TOK, CDIM, CDIM, CDIM, nullptr, 0);
}

// round 10
// speedup vs baseline: 11.1320x; 2.0314x over previous
#include <cuda_runtime.h>
#include <math.h>
#include <stdint.h>

// Problem constants
#define TOK   4096          // b*l tokens
#define CDIM  1024
#define CHID  4096          // mlp hidden
#define NHEAD 16
#define HDIM  64
#define NB    4
#define SEQ   1024
#define WTHR  1e-7f         // branch-weight negligibility threshold

// ---------------- scratch (device globals; no allocation allowed) ----------
__device__ float g_x   [TOK * CDIM];        // paired+rounded x
__device__ float g_op0 [TOK * CDIM];
__device__ float g_h1p [TOK * 64];
__device__ float g_gate[TOK * CDIM];
__device__ float g_mhp [TOK * CHID];
__device__ float g_op3 [TOK * CDIM];
__device__ float g_xc  [TOK * CDIM];
__device__ float g_xcp [TOK * CDIM];
__device__ float g_qkv [TOK * 3 * CDIM];
__device__ float g_q   [TOK * CDIM];
__device__ float g_k   [TOK * CDIM];
__device__ float g_v   [TOK * CDIM];
__device__ float g_aop [TOK * CDIM];
__device__ float g_amap[NB * NHEAD * SEQ];  // per-head q0 attention probs
// pre-rounded + paired weights
__device__ float g_wpk  [(CDIM + CHID) * CDIM];   // [conv_w; mlp1_w]
__device__ float g_bpk  [CDIM + CHID];
__device__ float g_qkvw [3 * CDIM * CDIM];
__device__ float g_projw[CDIM * CDIM];
__device__ float g_mlp2w[CDIM * CHID];
__device__ float g_ca2w [CDIM * 64];
__device__ float g_ca1w [64 * CDIM];

#define EPI_NONE 0
#define EPI_GELU 1
#define EPI_RELU 2
#define EPI_SIGM 3
#define EPI_RES  4

__device__ __forceinline__ float gelu_exact(float v) {
    return 0.5f * v * (1.0f + erff(v * 0.70710678118654752f));
}
__device__ __forceinline__ uint32_t f2tf32(float x) {
    uint32_t u; asm("cvt.rn.tf32.f32 %0, %1;" : "=r"(u) : "f"(x)); return u;
}
__device__ __forceinline__ float tf32bits(float x) { return __uint_as_float(f2tf32(x)); }

// softmax(w_*100) weights, all 6
__device__ __forceinline__ void bw6all(const float* __restrict__ w_, float* wts) {
    float w[6], mx = -1e30f;
#pragma unroll
    for (int i = 0; i < 6; i++) { w[i] = w_[i] * 100.0f; mx = fmaxf(mx, w[i]); }
    float s = 0.f;
#pragma unroll
    for (int i = 0; i < 6; i++) { w[i] = __expf(w[i] - mx); s += w[i]; }
    float inv = 1.0f / s;
#pragma unroll
    for (int i = 0; i < 6; i++) wts[i] = w[i] * inv;
}
__device__ __forceinline__ float bw6(const float* __restrict__ w_, int idx) {
    float wts[6]; bw6all(w_, wts); return wts[idx];
}

// octet-local pair permutation of the K index: k -> 2*(k%4) + (k/4)%2
__device__ __forceinline__ size_t ppf(size_t i) {
    return (i & ~(size_t)7) | (((i & 3) << 1) | ((i >> 2) & 1));
}
__device__ __forceinline__ uint32_t smem_to_u32(const void* p) {
    uint32_t a;
    asm("{ .reg .u64 t; cvta.to.shared.u64 t, %1; cvt.u32.u64 %0, t; }" : "=r"(a) : "l"(p));
    return a;
}
__device__ __forceinline__ void mma16n8k8(float acc[4],
                                          uint32_t a0, uint32_t a1, uint32_t a2, uint32_t a3,
                                          uint32_t b0, uint32_t b1) {
    asm volatile(
        "mma.sync.aligned.m16n8k8.row.col.f32.tf32.tf32.f32 "
        "{%0,%1,%2,%3}, {%4,%5,%6,%7}, {%8,%9}, {%0,%1,%2,%3};\n"
        : "+f"(acc[0]), "+f"(acc[1]), "+f"(acc[2]), "+f"(acc[3])
        : "r"(a0), "r"(a1), "r"(a2), "r"(a3), "r"(b0), "r"(b1));
}

// =========== cp.async tf32 GEMM. A/W pre-rounded tf32 + K-paired. ===========
// CTA 128x128, BK=32, 2-stage double buffer, 8 warps (2x4).
// APITCH=40 (== 8 mod 32): conflict-free LDS.64 fragment loads per half-warp.
#define GST 2
#define BKC 32
#define APITCH 40
#define TILEF (128 * APITCH)
#define CASMEM (GST * 2 * TILEF * 4)   // 81920 B

template<int EPI, int PACK>
__global__ __launch_bounds__(256, 2)
void gemm_ca(const float* __restrict__ A, const float* __restrict__ W,
             const float* __restrict__ bias, const float* __restrict__ res,
             float* __restrict__ Out, float* __restrict__ Out2,
             int M, int N, int K, int lda,
             const float* __restrict__ gw, int gidx)
{
    const int m0 = blockIdx.y * 128, n0 = blockIdx.x * 128;
    if (gw) {
        int gi = PACK ? (n0 < CDIM ? 2 : 5) : gidx;
        if (bw6(gw, gi) < WTHR) return;
    }

    extern __shared__ float smem[];
    const uint32_t abase = smem_to_u32(smem);
    const uint32_t wbase = abase + GST * TILEF * 4;

    const int tid = threadIdx.x;
    const int lane = tid & 31, wid = tid >> 5;
    const int gid = lane >> 2, tig = lane & 3;
    const int mb = (wid >> 2) * 64, nb = (wid & 3) * 32;

    const int nchunk = K >> 5;

    auto issue = [&](int c) {
        const int st = c & 1;
        const int k0 = c << 5;
        const uint32_t sA = abase + st * TILEF * 4;
        const uint32_t sW = wbase + st * TILEF * 4;
#pragma unroll
        for (int i = 0; i < 4; i++) {
            int u = tid + i * 256;          // 0..1023
            int row = u >> 3, q = u & 7;
            const float* ga = A + (size_t)(m0 + row) * lda + k0 + q * 4;
            asm volatile("cp.async.cg.shared.global [%0], [%1], 16;"
                         :: "r"(sA + (uint32_t)(row * APITCH + q * 4) * 4), "l"(ga));
            const float* gwp = W + (size_t)(n0 + row) * K + k0 + q * 4;
            asm volatile("cp.async.cg.shared.global [%0], [%1], 16;"
                         :: "r"(sW + (uint32_t)(row * APITCH + q * 4) * 4), "l"(gwp));
        }
        asm volatile("cp.async.commit_group;" ::: "memory");
    };

    float acc[4][4][4];
#pragma unroll
    for (int mf = 0; mf < 4; mf++)
#pragma unroll
        for (int nf = 0; nf < 4; nf++)
#pragma unroll
            for (int i = 0; i < 4; i++) acc[mf][nf][i] = 0.f;

    issue(0);

    for (int c = 0; c < nchunk; c++) {
        asm volatile("cp.async.wait_group 0;" ::: "memory");
        __syncthreads();
        if (c + 1 < nchunk) issue(c + 1);

        const float* Ac = smem + (c & 1) * TILEF;
        const float* Wc = smem + (GST + (c & 1)) * TILEF;
#pragma unroll
        for (int ks = 0; ks < 4; ks++) {
            const int kb = ks * 8 + tig * 2;
            float2 bf[4];
#pragma unroll
            for (int nf = 0; nf < 4; nf++)
                bf[nf] = *(const float2*)&Wc[(nb + nf * 8 + gid) * APITCH + kb];
#pragma unroll
            for (int mf = 0; mf < 4; mf++) {
                float2 alo = *(const float2*)&Ac[(mb + mf * 16 + gid) * APITCH + kb];
                float2 ahi = *(const float2*)&Ac[(mb + mf * 16 + 8 + gid) * APITCH + kb];
#pragma unroll
                for (int nf = 0; nf < 4; nf++)
                    mma16n8k8(acc[mf][nf],
                              __float_as_uint(alo.x), __float_as_uint(ahi.x),
                              __float_as_uint(alo.y), __float_as_uint(ahi.y),
                              __float_as_uint(bf[nf].x), __float_as_uint(bf[nf].y));
            }
        }
    }

#pragma unroll
    for (int mf = 0; mf < 4; mf++) {
        const int row0 = m0 + mb + mf * 16 + gid;
        const int row1 = row0 + 8;
#pragma unroll
        for (int nf = 0; nf < 4; nf++) {
            const int col = n0 + nb + nf * 8 + 2 * tig;
            float2 b2 = *(const float2*)&bias[col];
            float v0 = acc[mf][nf][0] + b2.x;
            float v1 = acc[mf][nf][1] + b2.y;
            float v2 = acc[mf][nf][2] + b2.x;
            float v3 = acc[mf][nf][3] + b2.y;
            if (PACK || EPI == EPI_GELU) {
                v0 = gelu_exact(v0); v1 = gelu_exact(v1);
                v2 = gelu_exact(v2); v3 = gelu_exact(v3);
            } else if (EPI == EPI_SIGM) {
                v0 = 1.f/(1.f+__expf(-v0)); v1 = 1.f/(1.f+__expf(-v1));
                v2 = 1.f/(1.f+__expf(-v2)); v3 = 1.f/(1.f+__expf(-v3));
            } else if (EPI == EPI_RES) {
                float2 r0 = *(const float2*)&res[(size_t)row0 * N + col];
                float2 r1 = *(const float2*)&res[(size_t)row1 * N + col];
                v0 += r0.x; v1 += r0.y; v2 += r1.x; v3 += r1.y;
            }
            if (PACK) {
                if (n0 < CDIM) {
                    float2 o0 = { tf32bits(v0), tf32bits(v1) };
                    float2 o1 = { tf32bits(v2), tf32bits(v3) };
                    *(float2*)&Out[(size_t)row0 * CDIM + col] = o0;
                    *(float2*)&Out[(size_t)row1 * CDIM + col] = o1;
                } else {
                    int cm = col - CDIM;
                    Out2[ppf((size_t)row0 * CHID + cm)]     = tf32bits(v0);
                    Out2[ppf((size_t)row0 * CHID + cm + 1)] = tf32bits(v1);
                    Out2[ppf((size_t)row1 * CHID + cm)]     = tf32bits(v2);
                    Out2[ppf((size_t)row1 * CHID + cm + 1)] = tf32bits(v3);
                }
            } else {
                float2 o0 = {v0, v1}, o1 = {v2, v3};
                *(float2*)&Out[(size_t)row0 * N + col] = o0;
                *(float2*)&Out[(size_t)row1 * N + col] = o1;
            }
        }
    }
}

// ---------------- fp32 GEMM for tiny ca1 (output paired+rounded) ------------
template<int BM, int BN, int BK, int TM, int TN>
__global__ __launch_bounds__((BM/TM)*(BN/TN))
void gemm_nt_relu(const float* __restrict__ A, const float* __restrict__ W,
                  const float* __restrict__ bias, float* __restrict__ Out,
                  int M, int N, int K, const float* __restrict__ gw)
{
    if (gw && bw6(gw, 3) < WTHR) return;
    constexpr int NT = (BM/TM)*(BN/TN);
    __shared__ float As[BK][BM + 4];
    __shared__ float Ws[BK][BN + 4];

    const int tid = threadIdx.x;
    const int m0 = blockIdx.y * BM;
    const int n0 = blockIdx.x * BN;
    const int tx = tid % (BN / TN);
    const int ty = tid / (BN / TN);

    float acc[TM][TN];
#pragma unroll
    for (int i = 0; i < TM; i++)
#pragma unroll
        for (int j = 0; j < TN; j++) acc[i][j] = 0.f;

    for (int k0 = 0; k0 < K; k0 += BK) {
#pragma unroll
        for (int i = tid; i < BM*BK/4; i += NT) {
            int r = i / (BK/4), cg = i % (BK/4);
            float4 v = *(const float4*)&A[(size_t)(m0 + r) * K + k0 + cg*4];
            As[cg*4+0][r] = v.x; As[cg*4+1][r] = v.y;
            As[cg*4+2][r] = v.z; As[cg*4+3][r] = v.w;
        }
#pragma unroll
        for (int i = tid; i < BN*BK/4; i += NT) {
            int r = i / (BK/4), cg = i % (BK/4);
            float4 v = *(const float4*)&W[(size_t)(n0 + r) * K + k0 + cg*4];
            Ws[cg*4+0][r] = v.x; Ws[cg*4+1][r] = v.y;
            Ws[cg*4+2][r] = v.z; Ws[cg*4+3][r] = v.w;
        }
        __syncthreads();
#pragma unroll
        for (int k = 0; k < BK; k++) {
            float a[TM], b[TN];
#pragma unroll
            for (int i = 0; i < TM; i++) a[i] = As[k][ty*TM + i];
#pragma unroll
            for (int j = 0; j < TN; j++) b[j] = Ws[k][tx*TN + j];
#pragma unroll
            for (int i = 0; i < TM; i++)
#pragma unroll
                for (int j = 0; j < TN; j++) acc[i][j] += a[i] * b[j];
        }
        __syncthreads();
    }

#pragma unroll
    for (int i = 0; i < TM; i++) {
        int m = m0 + ty*TM + i;
#pragma unroll
        for (int j = 0; j < TN; j++) {
            int n = n0 + tx*TN + j;
            float v = fmaxf(acc[i][j] + bias[n], 0.f);
            Out[ppf((size_t)m * N + n)] = tf32bits(v);
        }
    }
}

// ---------------- unified pack kernel (all weights+biases, one launch) ------
__device__ __forceinline__ void pack32(float* __restrict__ dst,
                                       const float* __restrict__ src, int g) {
    const float4* s4 = (const float4*)src + (size_t)g * 8;
    float4* d4 = (float4*)dst + (size_t)g * 8;
    float4 a[4], b[4];
#pragma unroll
    for (int j = 0; j < 4; j++) { a[j] = s4[2*j]; b[j] = s4[2*j+1]; }
#pragma unroll
    for (int j = 0; j < 4; j++) {
        float4 o0 = { tf32bits(a[j].x), tf32bits(b[j].x), tf32bits(a[j].y), tf32bits(b[j].y) };
        float4 o1 = { tf32bits(a[j].z), tf32bits(b[j].z), tf32bits(a[j].w), tf32bits(b[j].w) };
        d4[2*j] = o0; d4[2*j+1] = o1;
    }
}
__device__ __forceinline__ void copy32(float* __restrict__ dst,
                                       const float* __restrict__ src, int g) {
    const float4* s4 = (const float4*)src + (size_t)g * 8;
    float4* d4 = (float4*)dst + (size_t)g * 8;
    float4 t[8];
#pragma unroll
    for (int j = 0; j < 8; j++) t[j] = s4[j];
#pragma unroll
    for (int j = 0; j < 8; j++) d4[j] = t[j];
}

#define PK_CONV  32768
#define PK_MLP1  131072
#define PK_QKV   98304
#define PK_PROJ  32768
#define PK_MLP2  131072
#define PK_CA2   2048
#define PK_CA1   2048
#define PK_BC    32
#define PK_BM    128
#define PKP0 0
#define PKP1 (PKP0+PK_CONV)
#define PKP2 (PKP1+PK_MLP1)
#define PKP3 (PKP2+PK_QKV)
#define PKP4 (PKP3+PK_PROJ)
#define PKP5 (PKP4+PK_MLP2)
#define PKP6 (PKP5+PK_CA2)
#define PKP7 (PKP6+PK_CA1)
#define PKP8 (PKP7+PK_BC)
#define PKEND (PKP8+PK_BM)

__global__ void pack_all(const float* __restrict__ w_,
                         const float* __restrict__ conv_w, const float* __restrict__ mlp1_w,
                         const float* __restrict__ qkv_w,  const float* __restrict__ proj_w,
                         const float* __restrict__ mlp2_w, const float* __restrict__ ca2_w,
                         const float* __restrict__ ca1_w,
                         const float* __restrict__ conv_b, const float* __restrict__ mlp1_b,
                         float* __restrict__ wpk, float* __restrict__ qkvw,
                         float* __restrict__ projw, float* __restrict__ mlp2w,
                         float* __restrict__ ca2w, float* __restrict__ ca1w,
                         float* __restrict__ bpk)
{
    int t = blockIdx.x * blockDim.x + threadIdx.x;
    if (t >= PKEND) return;
    float wts[6]; bw6all(w_, wts);
    if (t < PKP1)      { if (wts[2] >= WTHR) pack32(wpk, conv_w, t - PKP0); }
    else if (t < PKP2) { if (wts[5] >= WTHR) pack32(wpk + (size_t)CDIM*CDIM, mlp1_w, t - PKP1); }
    else if (t < PKP3) { pack32(qkvw, qkv_w, t - PKP2); }
    else if (t < PKP4) { pack32(projw, proj_w, t - PKP3); }
    else if (t < PKP5) { if (wts[5] >= WTHR) pack32(mlp2w, mlp2_w, t - PKP4); }
    else if (t < PKP6) { if (wts[3] >= WTHR) pack32(ca2w, ca2_w, t - PKP5); }
    else if (t < PKP7) { if (wts[3] >= WTHR) pack32(ca1w, ca1_w, t - PKP6); }
    else if (t < PKP8) { if (wts[2] >= WTHR) copy32(bpk, conv_b, t - PKP7); }
    else               { if (wts[5] >= WTHR) copy32(bpk + CDIM, mlp1_b, t - PKP8); }
}

// ---------------- extract x = x_list[...,-1] (32 floats/thread) -------------
__global__ void extract_x32(const float* __restrict__ x_list, float* __restrict__ x,
                            const float* __restrict__ gw)
{
    int t = blockIdx.x * blockDim.x + threadIdx.x;
    if (t >= TOK * CDIM / 32) return;
    float wts[6]; bw6all(gw, wts);
    if (wts[2] < WTHR && wts[3] < WTHR && wts[5] < WTHR) return;
    const float4* s4 = (const float4*)x_list;
    float4* d4 = (float4*)x;
#pragma unroll
    for (int o = 0; o < 4; o++) {
        int i = t * 4 + o;       // octet index
        float4 c0 = s4[4*i], c1 = s4[4*i+1], c2 = s4[4*i+2], c3 = s4[4*i+3];
        float4 o0 = { tf32bits(c0.y), tf32bits(c2.y), tf32bits(c0.w), tf32bits(c2.w) };
        float4 o1 = { tf32bits(c1.y), tf32bits(c3.y), tf32bits(c1.w), tf32bits(c3.w) };
        d4[2*i] = o0; d4[2*i+1] = o1;
    }
}

// ---------------- combine: 8 elements/thread, predicated --------------------
__global__ void combine8(const float* __restrict__ x_list,
                         const float* __restrict__ w_,
                         const float* __restrict__ op0,
                         const float* __restrict__ gate,
                         const float* __restrict__ op3,
                         float* __restrict__ xc, float* __restrict__ xcp)
{
    float w[6]; bw6all(w_, w);
    int i = blockIdx.x * blockDim.x + threadIdx.x;   // octet index
    if (i >= TOK * CDIM / 8) return;
    const float4* s4 = (const float4*)x_list;
    float4 c0 = s4[4*i], c1 = s4[4*i+1], c2 = s4[4*i+2], c3 = s4[4*i+3];
    float xl0[8] = { c0.x, c0.z, c1.x, c1.z, c2.x, c2.z, c3.x, c3.z };
    float xv [8] = { c0.y, c0.w, c1.y, c1.w, c2.y, c2.w, c3.y, c3.w };
    float v[8];
    float w14 = w[1] + w[4];
#pragma unroll
    for (int k = 0; k < 8; k++) v[k] = w[0]*xl0[k] + w14*xv[k];
    if (w[2] >= WTHR) {
        float4 a = ((const float4*)op0)[2*i], b = ((const float4*)op0)[2*i+1];
        v[0] += w[2]*a.x; v[1] += w[2]*a.y; v[2] += w[2]*a.z; v[3] += w[2]*a.w;
        v[4] += w[2]*b.x; v[5] += w[2]*b.y; v[6] += w[2]*b.z; v[7] += w[2]*b.w;
    }
    if (w[3] >= WTHR) {
        float4 a = ((const float4*)gate)[2*i], b = ((const float4*)gate)[2*i+1];
        v[0] += w[3]*a.x*xv[0]; v[1] += w[3]*a.y*xv[1]; v[2] += w[3]*a.z*xv[2]; v[3] += w[3]*a.w*xv[3];
        v[4] += w[3]*b.x*xv[4]; v[5] += w[3]*b.y*xv[5]; v[6] += w[3]*b.z*xv[6]; v[7] += w[3]*b.w*xv[7];
    }
    if (w[5] >= WTHR) {
        float4 a = ((const float4*)op3)[2*i], b = ((const float4*)op3)[2*i+1];
        v[0] += w[5]*a.x; v[1] += w[5]*a.y; v[2] += w[5]*a.z; v[3] += w[5]*a.w;
        v[4] += w[5]*b.x; v[5] += w[5]*b.y; v[6] += w[5]*b.z; v[7] += w[5]*b.w;
    }
#pragma unroll
    for (int k = 0; k < 8; k++) v[k] = tf32bits(v[k]);
    float4* dc = (float4*)xc;
    float4 u0 = { v[0], v[1], v[2], v[3] }, u1 = { v[4], v[5], v[6], v[7] };
    dc[2*i] = u0; dc[2*i+1] = u1;
    float4* dp = (float4*)xcp;
    float4 p0 = { v[0], v[4], v[1], v[5] }, p1 = { v[2], v[6], v[3], v[7] };
    dp[2*i] = p0; dp[2*i+1] = p1;
}

// ---------------- qkv split + per-head LN + head-major transpose ------------
__global__ void ln_split(const float* __restrict__ qkv,
                         const float* __restrict__ nqg, const float* __restrict__ nqb,
                         const float* __restrict__ nkg, const float* __restrict__ nkb,
                         float* __restrict__ Qo, float* __restrict__ Ko, float* __restrict__ Vo)
{
    int gw = (blockIdx.x * blockDim.x + threadIdx.x) >> 5;
    int lane = threadIdx.x & 31;
    if (gw >= TOK * NHEAD) return;
    int t = gw / NHEAD, h = gw % NHEAD;
    int b = t / SEQ, n = t % SEQ;
    size_t src = (size_t)t * (3*CDIM) + h * HDIM;
    size_t dst = ((size_t)(b*NHEAD + h) * SEQ + n) * HDIM;

#pragma unroll
    for (int which = 0; which < 2; which++) {
        size_t so = src + (which ? CDIM : 0);
        float2 xv = *(const float2*)&qkv[so + lane*2];
        float sum = xv.x + xv.y;
        float ssq = xv.x*xv.x + xv.y*xv.y;
#pragma unroll
        for (int o = 16; o > 0; o >>= 1) {
            sum += __shfl_xor_sync(0xffffffff, sum, o);
            ssq += __shfl_xor_sync(0xffffffff, ssq, o);
        }
        float mean = sum * (1.0f/64.0f);
        float var  = ssq * (1.0f/64.0f) - mean*mean;
        float inv  = rsqrtf(var + 1e-5f);
        const float* g = which ? nkg : nqg;
        const float* bb = which ? nkb : nqb;
        float* O = which ? Ko : Qo;
        O[dst + lane*2 + 0] = (xv.x - mean)*inv*g[lane*2+0] + bb[lane*2+0];
        O[dst + lane*2 + 1] = (xv.y - mean)*inv*g[lane*2+1] + bb[lane*2+1];
    }
    *(float2*)&Vo[dst + lane*2] = *(const float2*)&qkv[src + 2*CDIM + lane*2];
}

// ---------------- tf32 MMA flash attention (epilogue: paired+rounded) -------
// Qs2/Ps2 pitch 132 (264 words == 8 mod 32): conflict-free A-frag LDS.64.
#define QPITCH 132
#define KPAD 68
#define VPAD 72
#define QS_F2   (32*QPITCH)
#define KS_F    (64*KPAD)
#define VS_F    (64*VPAD)
#define ATT_SMEM ((QS_F2*2 + KS_F + VS_F + QS_F2*2) * 4)

__global__ __launch_bounds__(256, 2)
void attn_mma(const float* __restrict__ Q, const float* __restrict__ K,
              const float* __restrict__ V, float* __restrict__ AO)
{
    extern __shared__ float sma[];
    float2* Qs2 = (float2*)sma;
    float*  Ks  = sma + QS_F2*2;
    float*  Vs  = Ks + KS_F;
    float2* Ps2 = (float2*)(Vs + VS_F);

    const int tid = threadIdx.x;
    const int lane = tid & 31, wid = tid >> 5;
    const int gid = lane >> 2, tig = lane & 3;
    const int q0 = blockIdx.x * 128;
    const int bh = blockIdx.y;
    const int qb = wid * 16;
    const float* Qb = Q + (size_t)bh * SEQ * HDIM;
    const float* Kb = K + (size_t)bh * SEQ * HDIM;
    const float* Vb = V + (size_t)bh * SEQ * HDIM;

    {
        int r = tid >> 1, hf = tid & 1;
#pragma unroll
        for (int i = 0; i < 8; i++) {
            int k0 = hf * 32 + i * 4;
            float4 v = *(const float4*)&Qb[(size_t)(q0 + r) * HDIM + k0];
            int p0 = (k0 >> 3) * 4;
            int h  = (k0 & 4) >> 2;
            ((float*)&Qs2[(p0 + 0) * QPITCH + r])[h] = tf32bits(v.x);
            ((float*)&Qs2[(p0 + 1) * QPITCH + r])[h] = tf32bits(v.y);
            ((float*)&Qs2[(p0 + 2) * QPITCH + r])[h] = tf32bits(v.z);
            ((float*)&Qs2[(p0 + 3) * QPITCH + r])[h] = tf32bits(v.w);
        }
    }

    float oacc[8][4];
#pragma unroll
    for (int nf = 0; nf < 8; nf++)
#pragma unroll
        for (int i = 0; i < 4; i++) oacc[nf][i] = 0.f;
    float m0s = -1e30f, m1s = -1e30f, l0s = 0.f, l1s = 0.f;

    for (int kt = 0; kt < 16; kt++) {
        __syncthreads();
        {
            int j = tid >> 2, f = tid & 3;
            int rowg = kt * 64 + j;
#pragma unroll
            for (int i = 0; i < 4; i++) {
                int d0 = f * 16 + i * 4;
                float4 kv = *(const float4*)&Kb[(size_t)rowg * HDIM + d0];
                float4 vv = *(const float4*)&Vb[(size_t)rowg * HDIM + d0];
                float4 kc = { tf32bits(kv.x), tf32bits(kv.y), tf32bits(kv.z), tf32bits(kv.w) };
                float4 vc = { tf32bits(vv.x), tf32bits(vv.y), tf32bits(vv.z), tf32bits(vv.w) };
                *(float4*)&Ks[j * KPAD + d0] = kc;
                *(float4*)&Vs[j * VPAD + d0] = vc;
            }
        }
        __syncthreads();

        float sacc[8][4];
#pragma unroll
        for (int nf = 0; nf < 8; nf++)
#pragma unroll
            for (int i = 0; i < 4; i++) sacc[nf][i] = 0.f;
#pragma unroll
        for (int ks = 0; ks < 8; ks++) {
            int p = ks * 4 + tig;
            uint2 aL = *(const uint2*)&Qs2[p * QPITCH + qb + gid];
            uint2 aH = *(const uint2*)&Qs2[p * QPITCH + qb + gid + 8];
#pragma unroll
            for (int nf = 0; nf < 8; nf++) {
                uint32_t b0 = __float_as_uint(Ks[(nf * 8 + gid) * KPAD + ks * 8 + tig]);
                uint32_t b1 = __float_as_uint(Ks[(nf * 8 + gid) * KPAD + ks * 8 + tig + 4]);
                mma16n8k8(sacc[nf], aL.x, aH.x, aL.y, aH.y, b0, b1);
            }
        }

        float mx0 = -1e30f, mx1 = -1e30f;
#pragma unroll
        for (int nf = 0; nf < 8; nf++) {
            sacc[nf][0] *= 0.125f; sacc[nf][1] *= 0.125f;
            sacc[nf][2] *= 0.125f; sacc[nf][3] *= 0.125f;
            mx0 = fmaxf(mx0, fmaxf(sacc[nf][0], sacc[nf][1]));
            mx1 = fmaxf(mx1, fmaxf(sacc[nf][2], sacc[nf][3]));
        }
        mx0 = fmaxf(mx0, __shfl_xor_sync(0xffffffff, mx0, 1));
        mx0 = fmaxf(mx0, __shfl_xor_sync(0xffffffff, mx0, 2));
        mx1 = fmaxf(mx1, __shfl_xor_sync(0xffffffff, mx1, 1));
        mx1 = fmaxf(mx1, __shfl_xor_sync(0xffffffff, mx1, 2));
        float mn0 = fmaxf(m0s, mx0), mn1 = fmaxf(m1s, mx1);
        float sc0 = __expf(m0s - mn0), sc1 = __expf(m1s - mn1);
        float sum0 = 0.f, sum1 = 0.f;
#pragma unroll
        for (int nf = 0; nf < 8; nf++) {
#pragma unroll
            for (int j = 0; j < 2; j++) {
                int cc = 2 * tig + j;
                int pc = nf * 4 + (cc & 3);
                int h  = cc >> 2;
                float p0 = __expf(sacc[nf][j]     - mn0);
                float p1 = __expf(sacc[nf][2 + j] - mn1);
                sum0 += p0; sum1 += p1;
                ((float*)&Ps2[pc * QPITCH + qb + gid])[h]     = tf32bits(p0);
                ((float*)&Ps2[pc * QPITCH + qb + gid + 8])[h] = tf32bits(p1);
            }
        }
        sum0 += __shfl_xor_sync(0xffffffff, sum0, 1);
        sum0 += __shfl_xor_sync(0xffffffff, sum0, 2);
        sum1 += __shfl_xor_sync(0xffffffff, sum1, 1);
        sum1 += __shfl_xor_sync(0xffffffff, sum1, 2);
        l0s = l0s * sc0 + sum0;  m0s = mn0;
        l1s = l1s * sc1 + sum1;  m1s = mn1;
#pragma unroll
        for (int nf = 0; nf < 8; nf++) {
            oacc[nf][0] *= sc0; oacc[nf][1] *= sc0;
            oacc[nf][2] *= sc1; oacc[nf][3] *= sc1;
        }
        __syncwarp();

#pragma unroll
        for (int ks = 0; ks < 8; ks++) {
            int p = ks * 4 + tig;
            uint2 aL = *(const uint2*)&Ps2[p * QPITCH + qb + gid];
            uint2 aH = *(const uint2*)&Ps2[p * QPITCH + qb + gid + 8];
#pragma unroll
            for (int nf = 0; nf < 8; nf++) {
                uint32_t b0 = __float_as_uint(Vs[(ks * 8 + tig) * VPAD + nf * 8 + gid]);
                uint32_t b1 = __float_as_uint(Vs[(ks * 8 + tig + 4) * VPAD + nf * 8 + gid]);
                mma16n8k8(oacc[nf], aL.x, aH.x, aL.y, aH.y, b0, b1);
            }
        }
    }

    {
        int b = bh >> 4, h = bh & 15;
        int r0 = q0 + qb + gid, r1 = r0 + 8;
        float inv0 = 1.0f / l0s, inv1 = 1.0f / l1s;
        size_t base0 = (size_t)(b * SEQ + r0) * CDIM;
        size_t base1 = (size_t)(b * SEQ + r1) * CDIM;
#pragma unroll
        for (int nf = 0; nf < 8; nf++) {
            int col = h * 64 + nf * 8 + 2 * tig;
            AO[base0 + ppf((size_t)col)]     = tf32bits(oacc[nf][0] * inv0);
            AO[base0 + ppf((size_t)col + 1)] = tf32bits(oacc[nf][1] * inv0);
            AO[base1 + ppf((size_t)col)]     = tf32bits(oacc[nf][2] * inv1);
            AO[base1 + ppf((size_t)col + 1)] = tf32bits(oacc[nf][3] * inv1);
        }
    }
}

// ---------------- attention map: per-(b,h) partial + deterministic reduce ---
__global__ void attn_map_part(const float* __restrict__ Q, const float* __restrict__ K,
                              float* __restrict__ amap)
{
    __shared__ float sc[SEQ];
    __shared__ float red[256];
    __shared__ float q0[HDIM];
    int bh = blockIdx.x, tid = threadIdx.x;
    const float* Qb = Q + (size_t)bh * SEQ * HDIM;
    const float* Kb = K + (size_t)bh * SEQ * HDIM;
    if (tid < HDIM) q0[tid] = Qb[tid];
    __syncthreads();
    for (int m = tid; m < SEQ; m += 256) {
        float s = 0.f;
#pragma unroll 16
        for (int j = 0; j < HDIM; j++) s += q0[j] * Kb[(size_t)m*HDIM + j];
        sc[m] = s * 0.125f;
    }
    __syncthreads();
    float mx = -1e30f;
    for (int m = tid; m < SEQ; m += 256) mx = fmaxf(mx, sc[m]);
    red[tid] = mx; __syncthreads();
    for (int s = 128; s > 0; s >>= 1) { if (tid < s) red[tid] = fmaxf(red[tid], red[tid+s]); __syncthreads(); }
    mx = red[0]; __syncthreads();
    float sum = 0.f;
    for (int m = tid; m < SEQ; m += 256) { float p = __expf(sc[m] - mx); sc[m] = p; sum += p; }
    red[tid] = sum; __syncthreads();
    for (int s = 128; s > 0; s >>= 1) { if (tid < s) red[tid] += red[tid+s]; __syncthreads(); }
    float inv = 1.0f / red[0]; __syncthreads();
    for (int m = tid; m < SEQ; m += 256)
        amap[(size_t)bh * SEQ + m] = sc[m] * inv;
}

__global__ void attn_map_reduce(const float* __restrict__ amap, float* __restrict__ omap)
{
    int i = blockIdx.x * blockDim.x + threadIdx.x;
    if (i >= NB * SEQ) return;
    int b = i / SEQ, m = i % SEQ;
    float acc = 0.f;
#pragma unroll
    for (int h = 0; h < NHEAD; h++)
        acc += amap[((size_t)(b * NHEAD + h)) * SEQ + m];
    if (m >= 1) omap[(size_t)b * (SEQ-1) + m - 1] = acc * (1.0f/NHEAD);
}

// ---------------- launch ----------------------------------------------------
extern "C" void kernel_launch(void* const* d_in, const int* in_sizes, int n_in,
                              void* d_out, int out_size)
{
    const float* x_list = (const float*)d_in[0];
    const float* w_     = (const float*)d_in[1];
    const float* qkv_w  = (const float*)d_in[2];
    const float* qkv_b  = (const float*)d_in[3];
    const float* proj_w = (const float*)d_in[4];
    const float* proj_b = (const float*)d_in[5];
    const float* nq_g   = (const float*)d_in[6];
    const float* nq_b   = (const float*)d_in[7];
    const float* nk_g   = (const float*)d_in[8];
    const float* nk_b   = (const float*)d_in[9];
    const float* conv_w = (const float*)d_in[10];
    const float* conv_b = (const float*)d_in[11];
    const float* ca1_w  = (const float*)d_in[12];
    const float* ca1_b  = (const float*)d_in[13];
    const float* ca2_w  = (const float*)d_in[14];
    const float* ca2_b  = (const float*)d_in[15];
    const float* mlp1_w = (const float*)d_in[16];
    const float* mlp1_b = (const float*)d_in[17];
    const float* mlp2_w = (const float*)d_in[18];
    const float* mlp2_b = (const float*)d_in[19];
    float* out = (float*)d_out;

    float *px, *pop0, *ph1p, *pgate, *pmhp, *pop3, *pxc, *pxcp, *pqkv, *pq, *pk, *pv, *paop, *pamap;
    float *pwpk, *pbpk, *pqkvw, *pprojw, *pmlp2w, *pca2w, *pca1w;
    cudaGetSymbolAddress((void**)&px,    g_x);
    cudaGetSymbolAddress((void**)&pop0,  g_op0);
    cudaGetSymbolAddress((void**)&ph1p,  g_h1p);
    cudaGetSymbolAddress((void**)&pgate, g_gate);
    cudaGetSymbolAddress((void**)&pmhp,  g_mhp);
    cudaGetSymbolAddress((void**)&pop3,  g_op3);
    cudaGetSymbolAddress((void**)&pxc,   g_xc);
    cudaGetSymbolAddress((void**)&pxcp,  g_xcp);
    cudaGetSymbolAddress((void**)&pqkv,  g_qkv);
    cudaGetSymbolAddress((void**)&pq,    g_q);
    cudaGetSymbolAddress((void**)&pk,    g_k);
    cudaGetSymbolAddress((void**)&pv,    g_v);
    cudaGetSymbolAddress((void**)&paop,  g_aop);
    cudaGetSymbolAddress((void**)&pamap, g_amap);
    cudaGetSymbolAddress((void**)&pwpk,  g_wpk);
    cudaGetSymbolAddress((void**)&pbpk,  g_bpk);
    cudaGetSymbolAddress((void**)&pqkvw, g_qkvw);
    cudaGetSymbolAddress((void**)&pprojw,g_projw);
    cudaGetSymbolAddress((void**)&pmlp2w,g_mlp2w);
    cudaGetSymbolAddress((void**)&pca2w, g_ca2w);
    cudaGetSymbolAddress((void**)&pca1w, g_ca1w);

    const int NE = TOK * CDIM;

    cudaFuncSetAttribute(gemm_ca<EPI_GELU,1>, cudaFuncAttributeMaxDynamicSharedMemorySize, CASMEM);
    cudaFuncSetAttribute(gemm_ca<EPI_SIGM,0>, cudaFuncAttributeMaxDynamicSharedMemorySize, CASMEM);
    cudaFuncSetAttribute(gemm_ca<EPI_NONE,0>, cudaFuncAttributeMaxDynamicSharedMemorySize, CASMEM);
    cudaFuncSetAttribute(gemm_ca<EPI_RES,0>,  cudaFuncAttributeMaxDynamicSharedMemorySize, CASMEM);
    cudaFuncSetAttribute(attn_mma, cudaFuncAttributeMaxDynamicSharedMemorySize, ATT_SMEM);

    // ---- one merged pack launch (gated per region inside)
    pack_all<<<(PKEND + 255)/256, 256>>>(w_,
        conv_w, mlp1_w, qkv_w, proj_w, mlp2_w, ca2_w, ca1_w, conv_b, mlp1_b,
        pwpk, pqkvw, pprojw, pmlp2w, pca2w, pca1w, pbpk);

    extract_x32<<<(NE/32 + 255)/256, 256>>>(x_list, px, w_);

    // packed conv+mlp1 (gated per region: conv=2, mlp1=5)
    gemm_ca<EPI_GELU,1><<<dim3((CDIM+CHID)/128, TOK/128), 256, CASMEM>>>(
        px, pwpk, pbpk, nullptr, pop0, pmhp, TOK, CDIM+CHID, CDIM, CDIM, w_, 0);
    // h1 = relu(x @ ca1_w^T + ca1_b)  (gate 3)
    gemm_nt_relu<32,64,16,2,4><<<dim3(1, TOK/32), 256>>>(
        px, pca1w, ca1_b, ph1p, TOK, 64, CDIM, w_);
    // gate = sigmoid(h1 @ ca2_w^T + ca2_b)  (gate 3)
    gemm_ca<EPI_SIGM,0><<<dim3(CDIM/128, TOK/128), 256, CASMEM>>>(
        ph1p, pca2w, ca2_b, nullptr, pgate, nullptr, TOK, CDIM, 64, 64, w_, 3);
    // op3 = mh @ mlp2_w^T + mlp2_b  (gate 5)
    gemm_ca<EPI_NONE,0><<<dim3(CDIM/128, TOK/128), 256, CASMEM>>>(
        pmhp, pmlp2w, mlp2_b, nullptr, pop3, nullptr, TOK, CDIM, CHID, CHID, w_, 5);

    combine8<<<(NE/8 + 255)/256, 256>>>(x_list, w_, pop0, pgate, pop3, pxc, pxcp);

    // qkv = xc @ qkv_w^T + qkv_b  (always)
    gemm_ca<EPI_NONE,0><<<dim3(3*CDIM/128, TOK/128), 256, CASMEM>>>(
        pxcp, pqkvw, qkv_b, nullptr, pqkv, nullptr, TOK, 3*CDIM, CDIM, CDIM, nullptr, 0);

    ln_split<<<(TOK*NHEAD*32 + 255)/256, 256>>>(pqkv, nq_g, nq_b, nk_g, nk_b, pq, pk, pv);

    attn_mma<<<dim3(SEQ/128, NB*NHEAD), 256, ATT_SMEM>>>(pq, pk, pv, paop);

    attn_map_part<<<NB*NHEAD, 256>>>(pq, pk, pamap);
    attn_map_reduce<<<(NB*SEQ + 255)/256, 256>>>(pamap, out + (size_t)TOK * CDIM);

    // out = ao @ proj_w^T + proj_b + xc  (always)
    gemm_ca<EPI_RES,0><<<dim3(CDIM/128, TOK/128), 256, CASMEM>>>(
        paop, pprojw, proj_b, pxc, out, nullptr, TOK, CDIM, CDIM, CDIM, nullptr, 0);
}

// round 11
// speedup vs baseline: 11.5323x; 1.0360x over previous
#include <cuda_runtime.h>
#include <math.h>
#include <stdint.h>

// Problem constants
#define TOK   4096          // b*l tokens
#define CDIM  1024
#define CHID  4096          // mlp hidden
#define NHEAD 16
#define HDIM  64
#define NB    4
#define SEQ   1024
#define WTHR  1e-7f         // branch-weight negligibility threshold

// ---------------- scratch (device globals; no allocation allowed) ----------
__device__ float g_x   [TOK * CDIM];        // paired+rounded x
__device__ float g_op0 [TOK * CDIM];
__device__ float g_h1p [TOK * 64];
__device__ float g_gate[TOK * CDIM];
__device__ float g_mhp [TOK * CHID];
__device__ float g_op3 [TOK * CDIM];
__device__ float g_xc  [TOK * CDIM];
__device__ float g_xcp [TOK * CDIM];
__device__ float g_qkv [TOK * 3 * CDIM];
__device__ float g_aop [TOK * CDIM];
__device__ float g_amap[NB * NHEAD * SEQ];  // per-head q0 attention probs
// pre-rounded + paired weights
__device__ float g_wpk  [(CDIM + CHID) * CDIM];   // [conv_w; mlp1_w]
__device__ float g_bpk  [CDIM + CHID];
__device__ float g_qkvw [3 * CDIM * CDIM];
__device__ float g_projw[CDIM * CDIM];
__device__ float g_mlp2w[CDIM * CHID];
__device__ float g_ca2w [CDIM * 64];
__device__ float g_ca1w [64 * CDIM];

#define EPI_NONE 0
#define EPI_GELU 1
#define EPI_RELU 2
#define EPI_SIGM 3
#define EPI_RES  4

__device__ __forceinline__ float gelu_exact(float v) {
    return 0.5f * v * (1.0f + erff(v * 0.70710678118654752f));
}
__device__ __forceinline__ uint32_t f2tf32(float x) {
    uint32_t u; asm("cvt.rn.tf32.f32 %0, %1;" : "=r"(u) : "f"(x)); return u;
}
__device__ __forceinline__ float tf32bits(float x) { return __uint_as_float(f2tf32(x)); }

// softmax(w_*100) weights, all 6
__device__ __forceinline__ void bw6all(const float* __restrict__ w_, float* wts) {
    float w[6], mx = -1e30f;
#pragma unroll
    for (int i = 0; i < 6; i++) { w[i] = w_[i] * 100.0f; mx = fmaxf(mx, w[i]); }
    float s = 0.f;
#pragma unroll
    for (int i = 0; i < 6; i++) { w[i] = __expf(w[i] - mx); s += w[i]; }
    float inv = 1.0f / s;
#pragma unroll
    for (int i = 0; i < 6; i++) wts[i] = w[i] * inv;
}
__device__ __forceinline__ float bw6(const float* __restrict__ w_, int idx) {
    float wts[6]; bw6all(w_, wts); return wts[idx];
}

// octet-local pair permutation of the K index: k -> 2*(k%4) + (k/4)%2
__device__ __forceinline__ size_t ppf(size_t i) {
    return (i & ~(size_t)7) | (((i & 3) << 1) | ((i >> 2) & 1));
}
__device__ __forceinline__ uint32_t smem_to_u32(const void* p) {
    uint32_t a;
    asm("{ .reg .u64 t; cvta.to.shared.u64 t, %1; cvt.u32.u64 %0, t; }" : "=r"(a) : "l"(p));
    return a;
}
__device__ __forceinline__ void mma16n8k8(float acc[4],
                                          uint32_t a0, uint32_t a1, uint32_t a2, uint32_t a3,
                                          uint32_t b0, uint32_t b1) {
    asm volatile(
        "mma.sync.aligned.m16n8k8.row.col.f32.tf32.tf32.f32 "
        "{%0,%1,%2,%3}, {%4,%5,%6,%7}, {%8,%9}, {%0,%1,%2,%3};\n"
        : "+f"(acc[0]), "+f"(acc[1]), "+f"(acc[2]), "+f"(acc[3])
        : "r"(a0), "r"(a1), "r"(a2), "r"(a3), "r"(b0), "r"(b1));
}

// =========== cp.async tf32 GEMM. A/W pre-rounded tf32 + K-paired. ===========
// CTA 128x128, BK=32, 2-stage double buffer, 8 warps (2x4).
// APITCH=40 (== 8 mod 32): conflict-free LDS.64 fragment loads per half-warp.
#define GST 2
#define BKC 32
#define APITCH 40
#define TILEF (128 * APITCH)
#define CASMEM (GST * 2 * TILEF * 4)   // 81920 B

template<int EPI, int PACK>
__global__ __launch_bounds__(256, 2)
void gemm_ca(const float* __restrict__ A, const float* __restrict__ W,
             const float* __restrict__ bias, const float* __restrict__ res,
             float* __restrict__ Out, float* __restrict__ Out2,
             int M, int N, int K, int lda,
             const float* __restrict__ gw, int gidx)
{
    const int m0 = blockIdx.y * 128, n0 = blockIdx.x * 128;
    if (gw) {
        int gi = PACK ? (n0 < CDIM ? 2 : 5) : gidx;
        if (bw6(gw, gi) < WTHR) return;
    }

    extern __shared__ float smem[];
    const uint32_t abase = smem_to_u32(smem);
    const uint32_t wbase = abase + GST * TILEF * 4;

    const int tid = threadIdx.x;
    const int lane = tid & 31, wid = tid >> 5;
    const int gid = lane >> 2, tig = lane & 3;
    const int mb = (wid >> 2) * 64, nb = (wid & 3) * 32;

    const int nchunk = K >> 5;

    auto issue = [&](int c) {
        const int st = c & 1;
        const int k0 = c << 5;
        const uint32_t sA = abase + st * TILEF * 4;
        const uint32_t sW = wbase + st * TILEF * 4;
#pragma unroll
        for (int i = 0; i < 4; i++) {
            int u = tid + i * 256;          // 0..1023
            int row = u >> 3, q = u & 7;
            const float* ga = A + (size_t)(m0 + row) * lda + k0 + q * 4;
            asm volatile("cp.async.cg.shared.global [%0], [%1], 16;"
                         :: "r"(sA + (uint32_t)(row * APITCH + q * 4) * 4), "l"(ga));
            const float* gwp = W + (size_t)(n0 + row) * K + k0 + q * 4;
            asm volatile("cp.async.cg.shared.global [%0], [%1], 16;"
                         :: "r"(sW + (uint32_t)(row * APITCH + q * 4) * 4), "l"(gwp));
        }
        asm volatile("cp.async.commit_group;" ::: "memory");
    };

    float acc[4][4][4];
#pragma unroll
    for (int mf = 0; mf < 4; mf++)
#pragma unroll
        for (int nf = 0; nf < 4; nf++)
#pragma unroll
            for (int i = 0; i < 4; i++) acc[mf][nf][i] = 0.f;

    issue(0);

    for (int c = 0; c < nchunk; c++) {
        asm volatile("cp.async.wait_group 0;" ::: "memory");
        __syncthreads();
        if (c + 1 < nchunk) issue(c + 1);

        const float* Ac = smem + (c & 1) * TILEF;
        const float* Wc = smem + (GST + (c & 1)) * TILEF;
#pragma unroll
        for (int ks = 0; ks < 4; ks++) {
            const int kb = ks * 8 + tig * 2;
            float2 bf[4];
#pragma unroll
            for (int nf = 0; nf < 4; nf++)
                bf[nf] = *(const float2*)&Wc[(nb + nf * 8 + gid) * APITCH + kb];
#pragma unroll
            for (int mf = 0; mf < 4; mf++) {
                float2 alo = *(const float2*)&Ac[(mb + mf * 16 + gid) * APITCH + kb];
                float2 ahi = *(const float2*)&Ac[(mb + mf * 16 + 8 + gid) * APITCH + kb];
#pragma unroll
                for (int nf = 0; nf < 4; nf++)
                    mma16n8k8(acc[mf][nf],
                              __float_as_uint(alo.x), __float_as_uint(ahi.x),
                              __float_as_uint(alo.y), __float_as_uint(ahi.y),
                              __float_as_uint(bf[nf].x), __float_as_uint(bf[nf].y));
            }
        }
    }

#pragma unroll
    for (int mf = 0; mf < 4; mf++) {
        const int row0 = m0 + mb + mf * 16 + gid;
        const int row1 = row0 + 8;
#pragma unroll
        for (int nf = 0; nf < 4; nf++) {
            const int col = n0 + nb + nf * 8 + 2 * tig;
            float2 b2 = *(const float2*)&bias[col];
            float v0 = acc[mf][nf][0] + b2.x;
            float v1 = acc[mf][nf][1] + b2.y;
            float v2 = acc[mf][nf][2] + b2.x;
            float v3 = acc[mf][nf][3] + b2.y;
            if (PACK || EPI == EPI_GELU) {
                v0 = gelu_exact(v0); v1 = gelu_exact(v1);
                v2 = gelu_exact(v2); v3 = gelu_exact(v3);
            } else if (EPI == EPI_SIGM) {
                v0 = 1.f/(1.f+__expf(-v0)); v1 = 1.f/(1.f+__expf(-v1));
                v2 = 1.f/(1.f+__expf(-v2)); v3 = 1.f/(1.f+__expf(-v3));
            } else if (EPI == EPI_RES) {
                float2 r0 = *(const float2*)&res[(size_t)row0 * N + col];
                float2 r1 = *(const float2*)&res[(size_t)row1 * N + col];
                v0 += r0.x; v1 += r0.y; v2 += r1.x; v3 += r1.y;
            }
            if (PACK) {
                if (n0 < CDIM) {
                    float2 o0 = { tf32bits(v0), tf32bits(v1) };
                    float2 o1 = { tf32bits(v2), tf32bits(v3) };
                    *(float2*)&Out[(size_t)row0 * CDIM + col] = o0;
                    *(float2*)&Out[(size_t)row1 * CDIM + col] = o1;
                } else {
                    int cm = col - CDIM;
                    Out2[ppf((size_t)row0 * CHID + cm)]     = tf32bits(v0);
                    Out2[ppf((size_t)row0 * CHID + cm + 1)] = tf32bits(v1);
                    Out2[ppf((size_t)row1 * CHID + cm)]     = tf32bits(v2);
                    Out2[ppf((size_t)row1 * CHID + cm + 1)] = tf32bits(v3);
                }
            } else {
                float2 o0 = {v0, v1}, o1 = {v2, v3};
                *(float2*)&Out[(size_t)row0 * N + col] = o0;
                *(float2*)&Out[(size_t)row1 * N + col] = o1;
            }
        }
    }
}

// ---------------- fp32 GEMM for tiny ca1 (output paired+rounded) ------------
template<int BM, int BN, int BK, int TM, int TN>
__global__ __launch_bounds__((BM/TM)*(BN/TN))
void gemm_nt_relu(const float* __restrict__ A, const float* __restrict__ W,
                  const float* __restrict__ bias, float* __restrict__ Out,
                  int M, int N, int K, const float* __restrict__ gw)
{
    if (gw && bw6(gw, 3) < WTHR) return;
    constexpr int NT = (BM/TM)*(BN/TN);
    __shared__ float As[BK][BM + 4];
    __shared__ float Ws[BK][BN + 4];

    const int tid = threadIdx.x;
    const int m0 = blockIdx.y * BM;
    const int n0 = blockIdx.x * BN;
    const int tx = tid % (BN / TN);
    const int ty = tid / (BN / TN);

    float acc[TM][TN];
#pragma unroll
    for (int i = 0; i < TM; i++)
#pragma unroll
        for (int j = 0; j < TN; j++) acc[i][j] = 0.f;

    for (int k0 = 0; k0 < K; k0 += BK) {
#pragma unroll
        for (int i = tid; i < BM*BK/4; i += NT) {
            int r = i / (BK/4), cg = i % (BK/4);
            float4 v = *(const float4*)&A[(size_t)(m0 + r) * K + k0 + cg*4];
            As[cg*4+0][r] = v.x; As[cg*4+1][r] = v.y;
            As[cg*4+2][r] = v.z; As[cg*4+3][r] = v.w;
        }
#pragma unroll
        for (int i = tid; i < BN*BK/4; i += NT) {
            int r = i / (BK/4), cg = i % (BK/4);
            float4 v = *(const float4*)&W[(size_t)(n0 + r) * K + k0 + cg*4];
            Ws[cg*4+0][r] = v.x; Ws[cg*4+1][r] = v.y;
            Ws[cg*4+2][r] = v.z; Ws[cg*4+3][r] = v.w;
        }
        __syncthreads();
#pragma unroll
        for (int k = 0; k < BK; k++) {
            float a[TM], b[TN];
#pragma unroll
            for (int i = 0; i < TM; i++) a[i] = As[k][ty*TM + i];
#pragma unroll
            for (int j = 0; j < TN; j++) b[j] = Ws[k][tx*TN + j];
#pragma unroll
            for (int i = 0; i < TM; i++)
#pragma unroll
                for (int j = 0; j < TN; j++) acc[i][j] += a[i] * b[j];
        }
        __syncthreads();
    }

#pragma unroll
    for (int i = 0; i < TM; i++) {
        int m = m0 + ty*TM + i;
#pragma unroll
        for (int j = 0; j < TN; j++) {
            int n = n0 + tx*TN + j;
            float v = fmaxf(acc[i][j] + bias[n], 0.f);
            Out[ppf((size_t)m * N + n)] = tf32bits(v);
        }
    }
}

// ---------------- unified pack kernel (all weights+biases, one launch) ------
__device__ __forceinline__ void pack32(float* __restrict__ dst,
                                       const float* __restrict__ src, int g) {
    const float4* s4 = (const float4*)src + (size_t)g * 8;
    float4* d4 = (float4*)dst + (size_t)g * 8;
    float4 a[4], b[4];
#pragma unroll
    for (int j = 0; j < 4; j++) { a[j] = s4[2*j]; b[j] = s4[2*j+1]; }
#pragma unroll
    for (int j = 0; j < 4; j++) {
        float4 o0 = { tf32bits(a[j].x), tf32bits(b[j].x), tf32bits(a[j].y), tf32bits(b[j].y) };
        float4 o1 = { tf32bits(a[j].z), tf32bits(b[j].z), tf32bits(a[j].w), tf32bits(b[j].w) };
        d4[2*j] = o0; d4[2*j+1] = o1;
    }
}
__device__ __forceinline__ void copy32(float* __restrict__ dst,
                                       const float* __restrict__ src, int g) {
    const float4* s4 = (const float4*)src + (size_t)g * 8;
    float4* d4 = (float4*)dst + (size_t)g * 8;
    float4 t[8];
#pragma unroll
    for (int j = 0; j < 8; j++) t[j] = s4[j];
#pragma unroll
    for (int j = 0; j < 8; j++) d4[j] = t[j];
}

#define PK_CONV  32768
#define PK_MLP1  131072
#define PK_QKV   98304
#define PK_PROJ  32768
#define PK_MLP2  131072
#define PK_CA2   2048
#define PK_CA1   2048
#define PK_BC    32
#define PK_BM    128
#define PKP0 0
#define PKP1 (PKP0+PK_CONV)
#define PKP2 (PKP1+PK_MLP1)
#define PKP3 (PKP2+PK_QKV)
#define PKP4 (PKP3+PK_PROJ)
#define PKP5 (PKP4+PK_MLP2)
#define PKP6 (PKP5+PK_CA2)
#define PKP7 (PKP6+PK_CA1)
#define PKP8 (PKP7+PK_BC)
#define PKEND (PKP8+PK_BM)

__global__ void pack_all(const float* __restrict__ w_,
                         const float* __restrict__ conv_w, const float* __restrict__ mlp1_w,
                         const float* __restrict__ qkv_w,  const float* __restrict__ proj_w,
                         const float* __restrict__ mlp2_w, const float* __restrict__ ca2_w,
                         const float* __restrict__ ca1_w,
                         const float* __restrict__ conv_b, const float* __restrict__ mlp1_b,
                         float* __restrict__ wpk, float* __restrict__ qkvw,
                         float* __restrict__ projw, float* __restrict__ mlp2w,
                         float* __restrict__ ca2w, float* __restrict__ ca1w,
                         float* __restrict__ bpk)
{
    int t = blockIdx.x * blockDim.x + threadIdx.x;
    if (t >= PKEND) return;
    float wts[6]; bw6all(w_, wts);
    if (t < PKP1)      { if (wts[2] >= WTHR) pack32(wpk, conv_w, t - PKP0); }
    else if (t < PKP2) { if (wts[5] >= WTHR) pack32(wpk + (size_t)CDIM*CDIM, mlp1_w, t - PKP1); }
    else if (t < PKP3) { pack32(qkvw, qkv_w, t - PKP2); }
    else if (t < PKP4) { pack32(projw, proj_w, t - PKP3); }
    else if (t < PKP5) { if (wts[5] >= WTHR) pack32(mlp2w, mlp2_w, t - PKP4); }
    else if (t < PKP6) { if (wts[3] >= WTHR) pack32(ca2w, ca2_w, t - PKP5); }
    else if (t < PKP7) { if (wts[3] >= WTHR) pack32(ca1w, ca1_w, t - PKP6); }
    else if (t < PKP8) { if (wts[2] >= WTHR) copy32(bpk, conv_b, t - PKP7); }
    else               { if (wts[5] >= WTHR) copy32(bpk + CDIM, mlp1_b, t - PKP8); }
}

// ---------------- extract x = x_list[...,-1] (32 floats/thread) -------------
__global__ void extract_x32(const float* __restrict__ x_list, float* __restrict__ x,
                            const float* __restrict__ gw)
{
    int t = blockIdx.x * blockDim.x + threadIdx.x;
    if (t >= TOK * CDIM / 32) return;
    float wts[6]; bw6all(gw, wts);
    if (wts[2] < WTHR && wts[3] < WTHR && wts[5] < WTHR) return;
    const float4* s4 = (const float4*)x_list;
    float4* d4 = (float4*)x;
#pragma unroll
    for (int o = 0; o < 4; o++) {
        int i = t * 4 + o;       // octet index
        float4 c0 = s4[4*i], c1 = s4[4*i+1], c2 = s4[4*i+2], c3 = s4[4*i+3];
        float4 o0 = { tf32bits(c0.y), tf32bits(c2.y), tf32bits(c0.w), tf32bits(c2.w) };
        float4 o1 = { tf32bits(c1.y), tf32bits(c3.y), tf32bits(c1.w), tf32bits(c3.w) };
        d4[2*i] = o0; d4[2*i+1] = o1;
    }
}

// ---------------- combine: 8 elements/thread, predicated --------------------
__global__ void combine8(const float* __restrict__ x_list,
                         const float* __restrict__ w_,
                         const float* __restrict__ op0,
                         const float* __restrict__ gate,
                         const float* __restrict__ op3,
                         float* __restrict__ xc, float* __restrict__ xcp)
{
    float w[6]; bw6all(w_, w);
    int i = blockIdx.x * blockDim.x + threadIdx.x;   // octet index
    if (i >= TOK * CDIM / 8) return;
    const float4* s4 = (const float4*)x_list;
    float4 c0 = s4[4*i], c1 = s4[4*i+1], c2 = s4[4*i+2], c3 = s4[4*i+3];
    float xl0[8] = { c0.x, c0.z, c1.x, c1.z, c2.x, c2.z, c3.x, c3.z };
    float xv [8] = { c0.y, c0.w, c1.y, c1.w, c2.y, c2.w, c3.y, c3.w };
    float v[8];
    float w14 = w[1] + w[4];
#pragma unroll
    for (int k = 0; k < 8; k++) v[k] = w[0]*xl0[k] + w14*xv[k];
    if (w[2] >= WTHR) {
        float4 a = ((const float4*)op0)[2*i], b = ((const float4*)op0)[2*i+1];
        v[0] += w[2]*a.x; v[1] += w[2]*a.y; v[2] += w[2]*a.z; v[3] += w[2]*a.w;
        v[4] += w[2]*b.x; v[5] += w[2]*b.y; v[6] += w[2]*b.z; v[7] += w[2]*b.w;
    }
    if (w[3] >= WTHR) {
        float4 a = ((const float4*)gate)[2*i], b = ((const float4*)gate)[2*i+1];
        v[0] += w[3]*a.x*xv[0]; v[1] += w[3]*a.y*xv[1]; v[2] += w[3]*a.z*xv[2]; v[3] += w[3]*a.w*xv[3];
        v[4] += w[3]*b.x*xv[4]; v[5] += w[3]*b.y*xv[5]; v[6] += w[3]*b.z*xv[6]; v[7] += w[3]*b.w*xv[7];
    }
    if (w[5] >= WTHR) {
        float4 a = ((const float4*)op3)[2*i], b = ((const float4*)op3)[2*i+1];
        v[0] += w[5]*a.x; v[1] += w[5]*a.y; v[2] += w[5]*a.z; v[3] += w[5]*a.w;
        v[4] += w[5]*b.x; v[5] += w[5]*b.y; v[6] += w[5]*b.z; v[7] += w[5]*b.w;
    }
#pragma unroll
    for (int k = 0; k < 8; k++) v[k] = tf32bits(v[k]);
    float4* dc = (float4*)xc;
    float4 u0 = { v[0], v[1], v[2], v[3] }, u1 = { v[4], v[5], v[6], v[7] };
    dc[2*i] = u0; dc[2*i+1] = u1;
    float4* dp = (float4*)xcp;
    float4 p0 = { v[0], v[4], v[1], v[5] }, p1 = { v[2], v[6], v[3], v[7] };
    dp[2*i] = p0; dp[2*i+1] = p1;
}

// ---------------- tf32 MMA flash attention with fused per-head LayerNorm ----
// Reads Q/K/V directly from the qkv buffer (token stride 3*CDIM); applies LN
// to Q and K during the smem tile loads. Qs2/Ps2 pitch 132: conflict-free.
#define QPITCH 132
#define KPAD 68
#define VPAD 72
#define QS_F2   (32*QPITCH)
#define KS_F    (64*KPAD)
#define VS_F    (64*VPAD)
#define ATT_SMEM ((QS_F2*2 + KS_F + VS_F + QS_F2*2) * 4)

__global__ __launch_bounds__(256, 2)
void attn_mma(const float* __restrict__ QKV,
              const float* __restrict__ nqg, const float* __restrict__ nqb,
              const float* __restrict__ nkg, const float* __restrict__ nkb,
              float* __restrict__ AO)
{
    extern __shared__ float sma[];
    float2* Qs2 = (float2*)sma;
    float*  Ks  = sma + QS_F2*2;
    float*  Vs  = Ks + KS_F;
    float2* Ps2 = (float2*)(Vs + VS_F);
    __shared__ float gq[HDIM], bq[HDIM], gk[HDIM], bk[HDIM];

    const int tid = threadIdx.x;
    const int lane = tid & 31, wid = tid >> 5;
    const int gid = lane >> 2, tig = lane & 3;
    const int q0 = blockIdx.x * 128;
    const int bh = blockIdx.y;
    const int b = bh >> 4, h = bh & 15;
    const int qb = wid * 16;
    const float* Qb = QKV + (size_t)(b * SEQ) * (3*CDIM) + h * HDIM;
    const float* Kb = Qb + CDIM;
    const float* Vb = Qb + 2*CDIM;

    if (tid < HDIM) {
        gq[tid] = nqg[tid]; bq[tid] = nqb[tid];
        gk[tid] = nkg[tid]; bk[tid] = nkb[tid];
    }
    __syncthreads();

    // ---- load Q tile with fused LN (2 threads per row, shfl-xor-1 stats)
    {
        int r = tid >> 1, hf = tid & 1;
        const float* qrow = Qb + (size_t)(q0 + r) * (3*CDIM) + hf * 32;
        float vals[32];
        float sum = 0.f, ssq = 0.f;
#pragma unroll
        for (int i = 0; i < 8; i++) {
            float4 v = *(const float4*)&qrow[i * 4];
            vals[i*4+0] = v.x; vals[i*4+1] = v.y; vals[i*4+2] = v.z; vals[i*4+3] = v.w;
            sum += v.x + v.y + v.z + v.w;
            ssq += v.x*v.x + v.y*v.y + v.z*v.z + v.w*v.w;
        }
        sum += __shfl_xor_sync(0xffffffff, sum, 1);
        ssq += __shfl_xor_sync(0xffffffff, ssq, 1);
        float mean = sum * (1.0f/64.0f);
        float inv  = rsqrtf(ssq * (1.0f/64.0f) - mean*mean + 1e-5f);
#pragma unroll
        for (int i = 0; i < 8; i++) {
            int k0 = hf * 32 + i * 4;
            int p0 = (k0 >> 3) * 4;
            int hh = (k0 & 4) >> 2;
#pragma unroll
            for (int c = 0; c < 4; c++) {
                float qn = (vals[i*4+c] - mean) * inv * gq[k0+c] + bq[k0+c];
                ((float*)&Qs2[(p0 + c) * QPITCH + r])[hh] = tf32bits(qn);
            }
        }
    }

    float oacc[8][4];
#pragma unroll
    for (int nf = 0; nf < 8; nf++)
#pragma unroll
        for (int i = 0; i < 4; i++) oacc[nf][i] = 0.f;
    float m0s = -1e30f, m1s = -1e30f, l0s = 0.f, l1s = 0.f;

    for (int kt = 0; kt < 16; kt++) {
        __syncthreads();
        // ---- K tile with fused LN (4 threads/row, shfl-xor-1,2), V copy
        {
            int j = tid >> 2, f = tid & 3;
            size_t roff = (size_t)(kt * 64 + j) * (3*CDIM);
            const float* krow = Kb + roff + f * 16;
            const float* vrow = Vb + roff + f * 16;
            float kvv[16];
            float sum = 0.f, ssq = 0.f;
#pragma unroll
            for (int i = 0; i < 4; i++) {
                float4 v = *(const float4*)&krow[i * 4];
                kvv[i*4+0] = v.x; kvv[i*4+1] = v.y; kvv[i*4+2] = v.z; kvv[i*4+3] = v.w;
                sum += v.x + v.y + v.z + v.w;
                ssq += v.x*v.x + v.y*v.y + v.z*v.z + v.w*v.w;
                float4 vv = *(const float4*)&vrow[i * 4];
                float4 vc = { tf32bits(vv.x), tf32bits(vv.y), tf32bits(vv.z), tf32bits(vv.w) };
                *(float4*)&Vs[j * VPAD + f * 16 + i * 4] = vc;
            }
            sum += __shfl_xor_sync(0xffffffff, sum, 1);
            ssq += __shfl_xor_sync(0xffffffff, ssq, 1);
            sum += __shfl_xor_sync(0xffffffff, sum, 2);
            ssq += __shfl_xor_sync(0xffffffff, ssq, 2);
            float mean = sum * (1.0f/64.0f);
            float inv  = rsqrtf(ssq * (1.0f/64.0f) - mean*mean + 1e-5f);
#pragma unroll
            for (int i = 0; i < 4; i++) {
                float4 kc;
                int c0 = f * 16 + i * 4;
                kc.x = tf32bits((kvv[i*4+0] - mean) * inv * gk[c0+0] + bk[c0+0]);
                kc.y = tf32bits((kvv[i*4+1] - mean) * inv * gk[c0+1] + bk[c0+1]);
                kc.z = tf32bits((kvv[i*4+2] - mean) * inv * gk[c0+2] + bk[c0+2]);
                kc.w = tf32bits((kvv[i*4+3] - mean) * inv * gk[c0+3] + bk[c0+3]);
                *(float4*)&Ks[j * KPAD + c0] = kc;
            }
        }
        __syncthreads();

        float sacc[8][4];
#pragma unroll
        for (int nf = 0; nf < 8; nf++)
#pragma unroll
            for (int i = 0; i < 4; i++) sacc[nf][i] = 0.f;
#pragma unroll
        for (int ks = 0; ks < 8; ks++) {
            int p = ks * 4 + tig;
            uint2 aL = *(const uint2*)&Qs2[p * QPITCH + qb + gid];
            uint2 aH = *(const uint2*)&Qs2[p * QPITCH + qb + gid + 8];
#pragma unroll
            for (int nf = 0; nf < 8; nf++) {
                uint32_t b0 = __float_as_uint(Ks[(nf * 8 + gid) * KPAD + ks * 8 + tig]);
                uint32_t b1 = __float_as_uint(Ks[(nf * 8 + gid) * KPAD + ks * 8 + tig + 4]);
                mma16n8k8(sacc[nf], aL.x, aH.x, aL.y, aH.y, b0, b1);
            }
        }

        float mx0 = -1e30f, mx1 = -1e30f;
#pragma unroll
        for (int nf = 0; nf < 8; nf++) {
            sacc[nf][0] *= 0.125f; sacc[nf][1] *= 0.125f;
            sacc[nf][2] *= 0.125f; sacc[nf][3] *= 0.125f;
            mx0 = fmaxf(mx0, fmaxf(sacc[nf][0], sacc[nf][1]));
            mx1 = fmaxf(mx1, fmaxf(sacc[nf][2], sacc[nf][3]));
        }
        mx0 = fmaxf(mx0, __shfl_xor_sync(0xffffffff, mx0, 1));
        mx0 = fmaxf(mx0, __shfl_xor_sync(0xffffffff, mx0, 2));
        mx1 = fmaxf(mx1, __shfl_xor_sync(0xffffffff, mx1, 1));
        mx1 = fmaxf(mx1, __shfl_xor_sync(0xffffffff, mx1, 2));
        float mn0 = fmaxf(m0s, mx0), mn1 = fmaxf(m1s, mx1);
        float sc0 = __expf(m0s - mn0), sc1 = __expf(m1s - mn1);
        float sum0 = 0.f, sum1 = 0.f;
#pragma unroll
        for (int nf = 0; nf < 8; nf++) {
#pragma unroll
            for (int j = 0; j < 2; j++) {
                int cc = 2 * tig + j;
                int pc = nf * 4 + (cc & 3);
                int hh = cc >> 2;
                float p0 = __expf(sacc[nf][j]     - mn0);
                float p1 = __expf(sacc[nf][2 + j] - mn1);
                sum0 += p0; sum1 += p1;
                ((float*)&Ps2[pc * QPITCH + qb + gid])[hh]     = tf32bits(p0);
                ((float*)&Ps2[pc * QPITCH + qb + gid + 8])[hh] = tf32bits(p1);
            }
        }
        sum0 += __shfl_xor_sync(0xffffffff, sum0, 1);
        sum0 += __shfl_xor_sync(0xffffffff, sum0, 2);
        sum1 += __shfl_xor_sync(0xffffffff, sum1, 1);
        sum1 += __shfl_xor_sync(0xffffffff, sum1, 2);
        l0s = l0s * sc0 + sum0;  m0s = mn0;
        l1s = l1s * sc1 + sum1;  m1s = mn1;
#pragma unroll
        for (int nf = 0; nf < 8; nf++) {
            oacc[nf][0] *= sc0; oacc[nf][1] *= sc0;
            oacc[nf][2] *= sc1; oacc[nf][3] *= sc1;
        }
        __syncwarp();

#pragma unroll
        for (int ks = 0; ks < 8; ks++) {
            int p = ks * 4 + tig;
            uint2 aL = *(const uint2*)&Ps2[p * QPITCH + qb + gid];
            uint2 aH = *(const uint2*)&Ps2[p * QPITCH + qb + gid + 8];
#pragma unroll
            for (int nf = 0; nf < 8; nf++) {
                uint32_t b0 = __float_as_uint(Vs[(ks * 8 + tig) * VPAD + nf * 8 + gid]);
                uint32_t b1 = __float_as_uint(Vs[(ks * 8 + tig + 4) * VPAD + nf * 8 + gid]);
                mma16n8k8(oacc[nf], aL.x, aH.x, aL.y, aH.y, b0, b1);
            }
        }
    }

    {
        int r0 = q0 + qb + gid, r1 = r0 + 8;
        float inv0 = 1.0f / l0s, inv1 = 1.0f / l1s;
        size_t base0 = (size_t)(b * SEQ + r0) * CDIM;
        size_t base1 = (size_t)(b * SEQ + r1) * CDIM;
#pragma unroll
        for (int nf = 0; nf < 8; nf++) {
            int col = h * 64 + nf * 8 + 2 * tig;
            AO[base0 + ppf((size_t)col)]     = tf32bits(oacc[nf][0] * inv0);
            AO[base0 + ppf((size_t)col + 1)] = tf32bits(oacc[nf][1] * inv0);
            AO[base1 + ppf((size_t)col)]     = tf32bits(oacc[nf][2] * inv1);
            AO[base1 + ppf((size_t)col + 1)] = tf32bits(oacc[nf][3] * inv1);
        }
    }
}

// ---------------- attention map with fused LN -------------------------------
__global__ void attn_map_part(const float* __restrict__ QKV,
                              const float* __restrict__ nqg, const float* __restrict__ nqb,
                              const float* __restrict__ nkg, const float* __restrict__ nkb,
                              float* __restrict__ amap)
{
    __shared__ float sc[SEQ];
    __shared__ float red[256];
    __shared__ float q0n[HDIM];
    __shared__ float gkn[HDIM], bkn[HDIM];
    __shared__ float qstats[2];
    int bh = blockIdx.x, tid = threadIdx.x;
    int b = bh >> 4, h = bh & 15;
    const float* Qb = QKV + (size_t)(b * SEQ) * (3*CDIM) + h * HDIM;
    const float* Kb = Qb + CDIM;

    if (tid < HDIM) { gkn[tid] = nkg[tid]; bkn[tid] = nkb[tid]; }
    if (tid < 32) {
        float a = Qb[tid], c = Qb[tid + 32];
        float sum = a + c, ssq = a*a + c*c;
#pragma unroll
        for (int o = 16; o > 0; o >>= 1) {
            sum += __shfl_xor_sync(0xffffffff, sum, o);
            ssq += __shfl_xor_sync(0xffffffff, ssq, o);
        }
        if (tid == 0) {
            float mean = sum * (1.0f/64.0f);
            qstats[0] = mean;
            qstats[1] = rsqrtf(ssq * (1.0f/64.0f) - mean*mean + 1e-5f);
        }
    }
    __syncthreads();
    if (tid < HDIM)
        q0n[tid] = (Qb[tid] - qstats[0]) * qstats[1] * nqg[tid] + nqb[tid];
    __syncthreads();

    for (int m = tid; m < SEQ; m += 256) {
        const float* kr = Kb + (size_t)m * (3*CDIM);
        float kv[64];
        float sum = 0.f, ssq = 0.f;
#pragma unroll
        for (int j = 0; j < 16; j++) {
            float4 v = *(const float4*)&kr[j * 4];
            kv[j*4+0] = v.x; kv[j*4+1] = v.y; kv[j*4+2] = v.z; kv[j*4+3] = v.w;
            sum += v.x + v.y + v.z + v.w;
            ssq += v.x*v.x + v.y*v.y + v.z*v.z + v.w*v.w;
        }
        float mean = sum * (1.0f/64.0f);
        float inv  = rsqrtf(ssq * (1.0f/64.0f) - mean*mean + 1e-5f);
        float s = 0.f;
#pragma unroll
        for (int j = 0; j < 64; j++)
            s += q0n[j] * ((kv[j] - mean) * inv * gkn[j] + bkn[j]);
        sc[m] = s * 0.125f;
    }
    __syncthreads();
    float mx = -1e30f;
    for (int m = tid; m < SEQ; m += 256) mx = fmaxf(mx, sc[m]);
    red[tid] = mx; __syncthreads();
    for (int s = 128; s > 0; s >>= 1) { if (tid < s) red[tid] = fmaxf(red[tid], red[tid+s]); __syncthreads(); }
    mx = red[0]; __syncthreads();
    float sum = 0.f;
    for (int m = tid; m < SEQ; m += 256) { float p = __expf(sc[m] - mx); sc[m] = p; sum += p; }
    red[tid] = sum; __syncthreads();
    for (int s = 128; s > 0; s >>= 1) { if (tid < s) red[tid] += red[tid+s]; __syncthreads(); }
    float inv = 1.0f / red[0]; __syncthreads();
    for (int m = tid; m < SEQ; m += 256)
        amap[(size_t)bh * SEQ + m] = sc[m] * inv;
}

__global__ void attn_map_reduce(const float* __restrict__ amap, float* __restrict__ omap)
{
    int i = blockIdx.x * blockDim.x + threadIdx.x;
    if (i >= NB * SEQ) return;
    int b = i / SEQ, m = i % SEQ;
    float acc = 0.f;
#pragma unroll
    for (int h = 0; h < NHEAD; h++)
        acc += amap[((size_t)(b * NHEAD + h)) * SEQ + m];
    if (m >= 1) omap[(size_t)b * (SEQ-1) + m - 1] = acc * (1.0f/NHEAD);
}

// ---------------- launch ----------------------------------------------------
extern "C" void kernel_launch(void* const* d_in, const int* in_sizes, int n_in,
                              void* d_out, int out_size)
{
    const float* x_list = (const float*)d_in[0];
    const float* w_     = (const float*)d_in[1];
    const float* qkv_w  = (const float*)d_in[2];
    const float* qkv_b  = (const float*)d_in[3];
    const float* proj_w = (const float*)d_in[4];
    const float* proj_b = (const float*)d_in[5];
    const float* nq_g   = (const float*)d_in[6];
    const float* nq_b   = (const float*)d_in[7];
    const float* nk_g   = (const float*)d_in[8];
    const float* nk_b   = (const float*)d_in[9];
    const float* conv_w = (const float*)d_in[10];
    const float* conv_b = (const float*)d_in[11];
    const float* ca1_w  = (const float*)d_in[12];
    const float* ca1_b  = (const float*)d_in[13];
    const float* ca2_w  = (const float*)d_in[14];
    const float* ca2_b  = (const float*)d_in[15];
    const float* mlp1_w = (const float*)d_in[16];
    const float* mlp1_b = (const float*)d_in[17];
    const float* mlp2_w = (const float*)d_in[18];
    const float* mlp2_b = (const float*)d_in[19];
    float* out = (float*)d_out;

    float *px, *pop0, *ph1p, *pgate, *pmhp, *pop3, *pxc, *pxcp, *pqkv, *paop, *pamap;
    float *pwpk, *pbpk, *pqkvw, *pprojw, *pmlp2w, *pca2w, *pca1w;
    cudaGetSymbolAddress((void**)&px,    g_x);
    cudaGetSymbolAddress((void**)&pop0,  g_op0);
    cudaGetSymbolAddress((void**)&ph1p,  g_h1p);
    cudaGetSymbolAddress((void**)&pgate, g_gate);
    cudaGetSymbolAddress((void**)&pmhp,  g_mhp);
    cudaGetSymbolAddress((void**)&pop3,  g_op3);
    cudaGetSymbolAddress((void**)&pxc,   g_xc);
    cudaGetSymbolAddress((void**)&pxcp,  g_xcp);
    cudaGetSymbolAddress((void**)&pqkv,  g_qkv);
    cudaGetSymbolAddress((void**)&paop,  g_aop);
    cudaGetSymbolAddress((void**)&pamap, g_amap);
    cudaGetSymbolAddress((void**)&pwpk,  g_wpk);
    cudaGetSymbolAddress((void**)&pbpk,  g_bpk);
    cudaGetSymbolAddress((void**)&pqkvw, g_qkvw);
    cudaGetSymbolAddress((void**)&pprojw,g_projw);
    cudaGetSymbolAddress((void**)&pmlp2w,g_mlp2w);
    cudaGetSymbolAddress((void**)&pca2w, g_ca2w);
    cudaGetSymbolAddress((void**)&pca1w, g_ca1w);

    const int NE = TOK * CDIM;

    cudaFuncSetAttribute(gemm_ca<EPI_GELU,1>, cudaFuncAttributeMaxDynamicSharedMemorySize, CASMEM);
    cudaFuncSetAttribute(gemm_ca<EPI_SIGM,0>, cudaFuncAttributeMaxDynamicSharedMemorySize, CASMEM);
    cudaFuncSetAttribute(gemm_ca<EPI_NONE,0>, cudaFuncAttributeMaxDynamicSharedMemorySize, CASMEM);
    cudaFuncSetAttribute(gemm_ca<EPI_RES,0>,  cudaFuncAttributeMaxDynamicSharedMemorySize, CASMEM);
    cudaFuncSetAttribute(attn_mma, cudaFuncAttributeMaxDynamicSharedMemorySize, ATT_SMEM);

    // ---- one merged pack launch (gated per region inside)
    pack_all<<<(PKEND + 255)/256, 256>>>(w_,
        conv_w, mlp1_w, qkv_w, proj_w, mlp2_w, ca2_w, ca1_w, conv_b, mlp1_b,
        pwpk, pqkvw, pprojw, pmlp2w, pca2w, pca1w, pbpk);

    extract_x32<<<(NE/32 + 255)/256, 256>>>(x_list, px, w_);

    // packed conv+mlp1 (gated per region: conv=2, mlp1=5)
    gemm_ca<EPI_GELU,1><<<dim3((CDIM+CHID)/128, TOK/128), 256, CASMEM>>>(
        px, pwpk, pbpk, nullptr, pop0, pmhp, TOK, CDIM+CHID, CDIM, CDIM, w_, 0);
    // h1 = relu(x @ ca1_w^T + ca1_b)  (gate 3)
    gemm_nt_relu<32,64,16,2,4><<<dim3(1, TOK/32), 256>>>(
        px, pca1w, ca1_b, ph1p, TOK, 64, CDIM, w_);
    // gate = sigmoid(h1 @ ca2_w^T + ca2_b)  (gate 3)
    gemm_ca<EPI_SIGM,0><<<dim3(CDIM/128, TOK/128), 256, CASMEM>>>(
        ph1p, pca2w, ca2_b, nullptr, pgate, nullptr, TOK, CDIM, 64, 64, w_, 3);
    // op3 = mh @ mlp2_w^T + mlp2_b  (gate 5)
    gemm_ca<EPI_NONE,0><<<dim3(CDIM/128, TOK/128), 256, CASMEM>>>(
        pmhp, pmlp2w, mlp2_b, nullptr, pop3, nullptr, TOK, CDIM, CHID, CHID, w_, 5);

    combine8<<<(NE/8 + 255)/256, 256>>>(x_list, w_, pop0, pgate, pop3, pxc, pxcp);

    // qkv = xc @ qkv_w^T + qkv_b  (always)
    gemm_ca<EPI_NONE,0><<<dim3(3*CDIM/128, TOK/128), 256, CASMEM>>>(
        pxcp, pqkvw, qkv_b, nullptr, pqkv, nullptr, TOK, 3*CDIM, CDIM, CDIM, nullptr, 0);

    // attention with fused per-head LN (reads g_qkv directly)
    attn_mma<<<dim3(SEQ/128, NB*NHEAD), 256, ATT_SMEM>>>(
        pqkv, nq_g, nq_b, nk_g, nk_b, paop);

    attn_map_part<<<NB*NHEAD, 256>>>(pqkv, nq_g, nq_b, nk_g, nk_b, pamap);
    attn_map_reduce<<<(NB*SEQ + 255)/256, 256>>>(pamap, out + (size_t)TOK * CDIM);

    // out = ao @ proj_w^T + proj_b + xc  (always)
    gemm_ca<EPI_RES,0><<<dim3(CDIM/128, TOK/128), 256, CASMEM>>>(
        paop, pprojw, proj_b, pxc, out, nullptr, TOK, CDIM, CDIM, CDIM, nullptr, 0);
}